// round 12
// baseline (speedup 1.0000x reference)
#include <cuda_runtime.h>
#include <math.h>

#define NN 50000
#define NE 800000
#define L  64
#define NB32 ((NN + 31) / 32)
#define NB64 ((NN + 63) / 64)
#define NBG  ((NN + 55) / 56)

// ------------- device scratch (statics zero-initialized; k_fin re-zeroes) -------------
__device__ float  g_H [NN*L];
__device__ float  g_H0[NN*L];
__device__ float  g_Pt[NN*L];
__device__ float  g_Qt[NN*L];
__device__ float  g_Pf[NN*L];
__device__ float  g_Qf[NN*L];
__device__ float  g_mt[NN*L];
__device__ float  g_mf[NN*L];
__device__ float  g_U [NN];
__device__ int    g_rowptr[NN+1];
__device__ int    g_colptr[NN+1];
__device__ int    g_cntr[NN];
__device__ int    g_cntc[NN];
__device__ int    g_nd[NN];
__device__ int    g_dr[NN];
__device__ int    g_ndcount;
__device__ int    g_drcount;
__device__ float4 g_rowE4[NE];
__device__ float4 g_colE4[NE];
__device__ float  g_rowA[NE];
__device__ int    g_rowJ[NE];
__device__ double g_loss;

__device__ __forceinline__ float sigf(float v){ return 1.f/(1.f+__expf(-v)); }

// ---------------- CSR build ----------------
__global__ void k_hist(const int* __restrict__ ei){
    int e = blockIdx.x*blockDim.x + threadIdx.x;
    if(e < NE){
        atomicAdd(&g_cntr[ei[e]], 1);
        atomicAdd(&g_cntc[ei[NE+e]], 1);
    }
}

__device__ void scan_one(int* cnt, int* ptr, int* part){
    const int C = (NN + 1023)/1024;
    int t = threadIdx.x;
    int s = 0;
    for(int k=0;k<C;k++){ int id=t*C+k; if(id<NN) s += cnt[id]; }
    part[t] = s; __syncthreads();
    for(int off=1; off<1024; off<<=1){
        int v = (t>=off)? part[t-off] : 0;
        __syncthreads();
        part[t] += v;
        __syncthreads();
    }
    int run = (t==0)? 0 : part[t-1];
    for(int k=0;k<C;k++){
        int id = t*C+k;
        if(id<NN){ int v=cnt[id]; ptr[id]=run; run+=v; cnt[id]=0; }
    }
    if(t==0) ptr[NN] = part[1023];
    __syncthreads();
}

__global__ void k_scan(const int* __restrict__ tags){
    __shared__ int part[1024];
    scan_one(g_cntr, g_rowptr, part);
    scan_one(g_cntc, g_colptr, part);
    const int C = (NN + 1023)/1024;
    int t = threadIdx.x;
    int cN = 0;
    for(int k=0;k<C;k++){ int id=t*C+k; if(id<NN && tags[id]!=1) cN++; }
    part[t] = cN; __syncthreads();
    for(int off=1; off<1024; off<<=1){
        int v = (t>=off)? part[t-off] : 0;
        __syncthreads();
        part[t] += v;
        __syncthreads();
    }
    int ndBase = (t==0)? 0 : part[t-1];
    int idsBefore = t*C; if(idsBefore > NN) idsBefore = NN;
    int drBase = idsBefore - ndBase;
    for(int k=0;k<C;k++){
        int id = t*C+k;
        if(id<NN){
            if(tags[id]!=1) g_nd[ndBase++] = id;
            else            g_dr[drBase++] = id;
        }
    }
    if(t==1023){ g_ndcount = part[1023]; g_drcount = NN - part[1023]; }
}

__global__ void k_scatter(const int* __restrict__ ei, const float* __restrict__ ea,
                          const float* __restrict__ aij){
    int e = blockIdx.x*blockDim.x + threadIdx.x;
    if(e >= NE) return;
    int r = ei[e], c = ei[NE+e];
    float a0 = ea[3*e], a1 = ea[3*e+1], a2 = ea[3*e+2];
    int pr = atomicAdd(&g_cntr[r], 1);
    int p  = g_rowptr[r] + pr;
    g_rowE4[p] = make_float4(a0,a1,a2,__int_as_float(c));
    g_rowA[p]  = aij[e];
    g_rowJ[p]  = c;
    int pc = atomicAdd(&g_cntc[c], 1);
    int q  = g_colptr[c] + pc;
    g_colE4[q] = make_float4(a0,a1,a2,__int_as_float(r));
}

// ---------------- encoder: x -> H0, H ----------------
__global__ __launch_bounds__(256) void k_enc0(const float* __restrict__ x,
        const float* __restrict__ eW1, const float* __restrict__ eb1,
        const float* __restrict__ eW2, const float* __restrict__ eb2){
    __shared__ float sW[L*L];
    __shared__ float sh[8][4][L];
    int tid = threadIdx.x;
    for(int i=tid;i<L*L/4;i+=256) ((float4*)sW)[i] = ((const float4*)eW2)[i];
    __syncthreads();
    int lane = tid&31, w = tid>>5, c0 = 2*lane;
    int nb = blockIdx.x*32 + w*4;
    float w1a=eW1[c0], w1b=eW1[c0+1], b1a=eb1[c0], b1b=eb1[c0+1];
    float b2a=eb2[c0], b2b=eb2[c0+1];
    bool val[4];
    #pragma unroll
    for(int v=0;v<4;v++){
        int n = nb+v; val[v] = (n<NN);
        float xv = val[v]? x[n] : 0.f;
        sh[w][v][c0]   = fmaxf(fmaf(xv,w1a,b1a),0.f);
        sh[w][v][c0+1] = fmaxf(fmaf(xv,w1b,b1b),0.f);
    }
    __syncwarp();
    float a0[4]={b2a,b2a,b2a,b2a}, a1[4]={b2b,b2b,b2b,b2b};
    for(int k=0;k<L;k++){
        float2 wv = *(const float2*)&sW[k*L+c0];
        #pragma unroll
        for(int v=0;v<4;v++){ float s=sh[w][v][k]; a0[v]=fmaf(s,wv.x,a0[v]); a1[v]=fmaf(s,wv.y,a1[v]); }
    }
    #pragma unroll
    for(int v=0;v<4;v++) if(val[v]){
        int n = nb+v;
        g_H0[n*L+c0]=a0[v]; g_H0[n*L+c0+1]=a1[v];
        g_H [n*L+c0]=a0[v]; g_H [n*L+c0+1]=a1[v];
    }
}

// ---------------- P/Q precompute (both phis), 8 nodes/warp, optional nd-perm ----------------
#define PREP_SMEM ((4*L*L + 64*L)*4)
__global__ __launch_bounds__(256) void k_prep(
        const float* __restrict__ ptW1, const float* __restrict__ ptb1,
        const float* __restrict__ pfW1, const float* __restrict__ pfb1,
        int use_perm){
    if(use_perm && blockIdx.x*64 >= g_ndcount) return;
    extern __shared__ float sm[];
    float* Wat = sm;
    float* Wbt = sm + L*L;
    float* Waf = sm + 2*L*L;
    float* Wbf = sm + 3*L*L;
    float* stg = sm + 4*L*L;
    int tid = threadIdx.x;
    for(int i=tid;i<L*L/4;i+=256){
        ((float4*)Wat)[i] = ((const float4*)ptW1)[i];
        ((float4*)Wbt)[i] = ((const float4*)(ptW1+L*L))[i];
        ((float4*)Waf)[i] = ((const float4*)pfW1)[i];
        ((float4*)Wbf)[i] = ((const float4*)(pfW1+L*L))[i];
    }
    int lane = tid&31, w = tid>>5, c0 = 2*lane;
    int i0 = w*8, sb = blockIdx.x*64 + i0;
    int nid[8]; bool val[8];
    #pragma unroll
    for(int v=0;v<8;v++){
        int slot = sb+v;
        if(use_perm){ val[v] = (slot < g_ndcount); nid[v] = val[v]? g_nd[slot] : 0; }
        else        { val[v] = (slot < NN);        nid[v] = slot; }
        float2 h = val[v]? *(const float2*)&g_H[nid[v]*L+c0] : make_float2(0.f,0.f);
        *(float2*)&stg[(i0+v)*L+c0] = h;
    }
    __syncthreads();
    float pt0[8],pt1[8],qt0[8],qt1[8],pf0[8],pf1[8],qf0[8],qf1[8];
    float bt0=ptb1[c0], bt1=ptb1[c0+1], bf0=pfb1[c0], bf1=pfb1[c0+1];
    #pragma unroll
    for(int v=0;v<8;v++){ pt0[v]=bt0; pt1[v]=bt1; pf0[v]=bf0; pf1[v]=bf1;
                          qt0[v]=0.f; qt1[v]=0.f; qf0[v]=0.f; qf1[v]=0.f; }
    for(int k=0;k<L;k++){
        float2 wat = *(const float2*)&Wat[k*L+c0];
        float2 wbt = *(const float2*)&Wbt[k*L+c0];
        float2 waf = *(const float2*)&Waf[k*L+c0];
        float2 wbf = *(const float2*)&Wbf[k*L+c0];
        #pragma unroll
        for(int v=0;v<8;v++){
            float h = stg[(i0+v)*L + k];
            pt0[v]=fmaf(h,wat.x,pt0[v]); pt1[v]=fmaf(h,wat.y,pt1[v]);
            qt0[v]=fmaf(h,wbt.x,qt0[v]); qt1[v]=fmaf(h,wbt.y,qt1[v]);
            pf0[v]=fmaf(h,waf.x,pf0[v]); pf1[v]=fmaf(h,waf.y,pf1[v]);
            qf0[v]=fmaf(h,wbf.x,qf0[v]); qf1[v]=fmaf(h,wbf.y,qf1[v]);
        }
    }
    #pragma unroll
    for(int v=0;v<8;v++) if(val[v]){
        int n = nid[v];
        g_Pt[n*L+c0]=pt0[v]; g_Pt[n*L+c0+1]=pt1[v];
        g_Qt[n*L+c0]=qt0[v]; g_Qt[n*L+c0+1]=qt1[v];
        g_Pf[n*L+c0]=pf0[v]; g_Pf[n*L+c0+1]=pf1[v];
        g_Qf[n*L+c0]=qf0[v]; g_Qf[n*L+c0+1]=qf1[v];
    }
}

// ---------------- edge aggregation + W2 fold (R9 champion version) ----------------
__global__ __launch_bounds__(256) void k_aggr(
        const int* __restrict__ colptr, const float4* __restrict__ colE4,
        const int* __restrict__ rowptr, const float4* __restrict__ rowE4,
        const float* __restrict__ Pt, const float* __restrict__ Qt,
        const float* __restrict__ Pf, const float* __restrict__ Qf,
        const float* __restrict__ ptW1, const float* __restrict__ ptb2, const float* __restrict__ ptW2,
        const float* __restrict__ pfW1, const float* __restrict__ pfb2, const float* __restrict__ pfW2,
        float* __restrict__ mt, float* __restrict__ mf){
    bool toDir = (blockIdx.x < NB32);
    int bb = toDir ? blockIdx.x : blockIdx.x - NB32;
    if(bb*32 >= g_ndcount) return;
    __shared__ float sW2[L*L];
    __shared__ float sWe[3*L];
    __shared__ float sS[8][4][L];
    const int*    ptr = toDir ? colptr : rowptr;
    const float4* e4  = toDir ? colE4  : rowE4;
    const float*  P   = toDir ? Pt     : Pf;
    const float*  Q   = toDir ? Qt     : Qf;
    const float*  W1  = toDir ? ptW1   : pfW1;
    const float*  b2  = toDir ? ptb2   : pfb2;
    const float*  W2  = toDir ? ptW2   : pfW2;
    float*        out = toDir ? mt     : mf;
    int tid = threadIdx.x;
    for(int i=tid;i<L*L/4;i+=256) ((float4*)sW2)[i] = ((const float4*)W2)[i];
    for(int i=tid;i<3*L;i+=256) sWe[i] = W1[2*L*L + i];
    __syncthreads();
    int lane = tid&31, w = tid>>5, c0 = 2*lane;
    int sb = bb*32 + w*4;
    float we0a=sWe[c0],     we0b=sWe[c0+1];
    float we1a=sWe[L+c0],   we1b=sWe[L+c0+1];
    float we2a=sWe[2*L+c0], we2b=sWe[2*L+c0+1];
    float degv[4]; bool val[4]; int nid[4];
    #pragma unroll
    for(int v=0;v<4;v++){
        int slot = sb+v;
        val[v] = (slot < g_ndcount);
        int n = val[v]? g_nd[slot] : 0;
        nid[v] = n;
        float acc0=0.f, acc1=0.f; int cnt=0;
        if(val[v]){
            float base0 = P[n*L+c0], base1 = P[n*L+c0+1];
            int s = ptr[n], e = ptr[n+1];
            for(int p=s; p<e; p++){
                float4 E = e4[p];
                int j = __float_as_int(E.w);
                if(j == n) continue;
                cnt++;
                float2 qv = *(const float2*)&Q[j*L+c0];
                float pre0 = base0 + qv.x + E.x*we0a + E.y*we1a + E.z*we2a;
                float pre1 = base1 + qv.y + E.x*we0b + E.y*we1b + E.z*we2b;
                acc0 += fmaxf(pre0, 0.f);
                acc1 += fmaxf(pre1, 0.f);
            }
        }
        sS[w][v][c0]=acc0; sS[w][v][c0+1]=acc1; degv[v]=(float)cnt;
    }
    __syncwarp();
    float b2a=b2[c0], b2b=b2[c0+1];
    float o0[4],o1[4];
    #pragma unroll
    for(int v=0;v<4;v++){ o0[v]=degv[v]*b2a; o1[v]=degv[v]*b2b; }
    for(int k=0;k<L;k++){
        float2 wv = *(const float2*)&sW2[k*L+c0];
        #pragma unroll
        for(int v=0;v<4;v++){ float s=sS[w][v][k]; o0[v]=fmaf(s,wv.x,o0[v]); o1[v]=fmaf(s,wv.y,o1[v]); }
    }
    #pragma unroll
    for(int v=0;v<4;v++) if(val[v]){
        int n = nid[v];
        out[n*L+c0]=o0[v]; out[n*L+c0+1]=o1[v];
    }
}

// ---------------- gates: 56 nodes/block, cW in smem, z/r weights via LDG -> 2 blocks/SM ----------------
#define GATE_SMEM ((194*L + 56*194 + 56*L)*4)
__global__ __launch_bounds__(256) void k_gate(
        const float* __restrict__ prb,
        const float* __restrict__ zkW, const float* __restrict__ zkb,
        const float* __restrict__ rkW, const float* __restrict__ rkb,
        const float* __restrict__ cW,  const float* __restrict__ cb){
    if(blockIdx.x*56 >= g_ndcount) return;
    extern __shared__ float sm[];
    float* scw  = sm;                 // 194*64
    float* stgA = scw + 194*L;        // [56][194]
    float* stgB = stgA + 56*194;      // [56][64]
    __shared__ float szb[L], srb[L], scb[L];
    int tid = threadIdx.x;
    for(int i=tid;i<194*L/4;i+=256)
        ((float4*)scw)[i] = ((const float4*)cW)[i];
    if(tid<L){ szb[tid]=zkb[tid]; srb[tid]=rkb[tid]; scb[tid]=cb[tid]; }
    int lane = tid&31, w = tid>>5, c0 = 2*lane;
    int i0 = w*7, sb = blockIdx.x*56 + i0;
    int nid[7]; bool val[7];
    #pragma unroll
    for(int v=0;v<7;v++){
        int slot = sb+v; val[v] = (slot < g_ndcount);
        int n = val[v]? g_nd[slot] : 0; nid[v] = n;
        float* A = stgA + (i0+v)*194;
        if(val[v]){
            *(float2*)&A[c0]     = *(const float2*)&g_H [n*L+c0];
            *(float2*)&A[64+c0]  = *(const float2*)&g_mt[n*L+c0];
            *(float2*)&A[128+c0] = *(const float2*)&g_mf[n*L+c0];
            if(lane==0){ A[192]=prb[2*n]; A[193]=prb[2*n+1]; }
        } else {
            *(float2*)&A[c0]     = make_float2(0.f,0.f);
            *(float2*)&A[64+c0]  = make_float2(0.f,0.f);
            *(float2*)&A[128+c0] = make_float2(0.f,0.f);
            if(lane==0){ A[192]=0.f; A[193]=0.f; }
        }
    }
    __syncthreads();
    float az0[7],az1[7],ar0[7],ar1[7],ac0[7],ac1[7];
    #pragma unroll
    for(int v=0;v<7;v++){ az0[v]=0.f; az1[v]=0.f; ar0[v]=0.f; ar1[v]=0.f; ac0[v]=0.f; ac1[v]=0.f; }
    #pragma unroll 4
    for(int k=0;k<64;k++){
        float2 wz = __ldg((const float2*)&zkW[k*L+c0]);
        float2 wr = __ldg((const float2*)&rkW[k*L+c0]);
        #pragma unroll
        for(int v=0;v<7;v++){
            float cv = stgA[(i0+v)*194 + k];
            az0[v]=fmaf(cv,wz.x,az0[v]); az1[v]=fmaf(cv,wz.y,az1[v]);
            ar0[v]=fmaf(cv,wr.x,ar0[v]); ar1[v]=fmaf(cv,wr.y,ar1[v]);
        }
    }
    #pragma unroll 2
    for(int k=64;k<194;k++){
        float2 wz = __ldg((const float2*)&zkW[k*L+c0]);
        float2 wr = __ldg((const float2*)&rkW[k*L+c0]);
        float2 wc = *(const float2*)&scw[k*L+c0];
        #pragma unroll
        for(int v=0;v<7;v++){
            float cv = stgA[(i0+v)*194 + k];
            az0[v]=fmaf(cv,wz.x,az0[v]); az1[v]=fmaf(cv,wz.y,az1[v]);
            ar0[v]=fmaf(cv,wr.x,ar0[v]); ar1[v]=fmaf(cv,wr.y,ar1[v]);
            ac0[v]=fmaf(cv,wc.x,ac0[v]); ac1[v]=fmaf(cv,wc.y,ac1[v]);
        }
    }
    float z0[7],z1[7];
    #pragma unroll
    for(int v=0;v<7;v++){
        z0[v]=sigf(az0[v]+szb[c0]); z1[v]=sigf(az1[v]+szb[c0+1]);
        float rr0=sigf(ar0[v]+srb[c0]), rr1=sigf(ar1[v]+srb[c0+1]);
        stgB[(i0+v)*L+c0]=rr0; stgB[(i0+v)*L+c0+1]=rr1;
    }
    __syncwarp();
    for(int k=0;k<64;k++){
        float2 wc = *(const float2*)&scw[k*L+c0];
        #pragma unroll
        for(int v=0;v<7;v++){
            float rh = stgB[(i0+v)*L+k] * stgA[(i0+v)*194+k];
            ac0[v]=fmaf(rh,wc.x,ac0[v]); ac1[v]=fmaf(rh,wc.y,ac1[v]);
        }
    }
    #pragma unroll
    for(int v=0;v<7;v++) if(val[v]){
        int n = nid[v];
        float* A = stgA + (i0+v)*194;
        float co0 = tanhf(ac0[v]+scb[c0]);
        float co1 = tanhf(ac1[v]+scb[c0+1]);
        float hn0 = A[c0]   + z0[v]*co0;
        float hn1 = A[c0+1] + z1[v]*co1;
        g_H[n*L+c0]   = hn0;
        g_H[n*L+c0+1] = hn1;
    }
}

// ---------------- decode + enc/autoenc losses over a node list ----------------
#define DEC_SMEM (3*64*L*4)
__global__ __launch_bounds__(256) void k_decode(
        int mode, float lossW,
        const float* __restrict__ dW1, const float* __restrict__ db1,
        const float* __restrict__ dW2, const float* __restrict__ db2,
        const float* __restrict__ eW1, const float* __restrict__ eb1,
        const float* __restrict__ eW2, const float* __restrict__ eb2){
    int cnt = mode ? g_ndcount : g_drcount;
    if(blockIdx.x*64 >= cnt) return;
    const int* list = mode ? g_nd : g_dr;
    extern __shared__ float sm[];
    float* sHn = sm;
    float* sB  = sm + 64*L;
    float* sE  = sm + 2*64*L;
    __shared__ float sdW2[L], sdb1[L], sE1[L], sEb1[L], sEb2[L];
    __shared__ double red[8];
    int tid = threadIdx.x;
    if(tid<L){ sdW2[tid]=dW2[tid]; sdb1[tid]=db1[tid]; sE1[tid]=eW1[tid];
               sEb1[tid]=eb1[tid]; sEb2[tid]=eb2[tid]; }
    __syncthreads();
    int lane = tid&31, w = tid>>5, c0 = 2*lane;
    int i0 = w*8, sb = blockIdx.x*64 + i0;
    float db2v = db2[0];
    int nid[8]; bool val[8];
    #pragma unroll
    for(int v=0;v<8;v++){
        int slot = sb+v; val[v] = (slot < cnt);
        nid[v] = val[v]? list[slot] : 0;
        float2 h = val[v]? *(const float2*)&g_H[nid[v]*L+c0] : make_float2(0.f,0.f);
        *(float2*)&sHn[(i0+v)*L+c0] = h;
    }
    __syncwarp();
    float ad0[8],ad1[8];
    #pragma unroll
    for(int v=0;v<8;v++){ ad0[v]=sdb1[c0]; ad1[v]=sdb1[c0+1]; }
    for(int k=0;k<L;k++){
        float2 wd = __ldg((const float2*)&dW1[k*L+c0]);
        #pragma unroll
        for(int v=0;v<8;v++){
            float hk = sHn[(i0+v)*L+k];
            ad0[v]=fmaf(hk,wd.x,ad0[v]); ad1[v]=fmaf(hk,wd.y,ad1[v]);
        }
    }
    float Uv[8];
    #pragma unroll
    for(int v=0;v<8;v++){
        float pu = fmaxf(ad0[v],0.f)*sdW2[c0] + fmaxf(ad1[v],0.f)*sdW2[c0+1];
        for(int o=16;o;o>>=1) pu += __shfl_xor_sync(0xffffffffu, pu, o);
        Uv[v] = pu + db2v;
        if(val[v] && lane==0) g_U[nid[v]] = Uv[v];
        float eh0 = fmaxf(fmaf(Uv[v],sE1[c0],sEb1[c0]),0.f);
        float eh1 = fmaxf(fmaf(Uv[v],sE1[c0+1],sEb1[c0+1]),0.f);
        sB[(i0+v)*L+c0]=eh0; sB[(i0+v)*L+c0+1]=eh1;
    }
    __syncwarp();
    float ae0[8],ae1[8];
    #pragma unroll
    for(int v=0;v<8;v++){ ae0[v]=sEb2[c0]; ae1[v]=sEb2[c0+1]; }
    for(int k=0;k<L;k++){
        float2 we = __ldg((const float2*)&eW2[k*L+c0]);
        #pragma unroll
        for(int v=0;v<8;v++){
            float ek = sB[(i0+v)*L+k];
            ae0[v]=fmaf(ek,we.x,ae0[v]); ae1[v]=fmaf(ek,we.y,ae1[v]);
        }
    }
    float encS = 0.f;
    #pragma unroll
    for(int v=0;v<8;v++){
        if(val[v]){
            float d0 = ae0[v]-sHn[(i0+v)*L+c0], d1 = ae1[v]-sHn[(i0+v)*L+c0+1];
            encS += d0*d0 + d1*d1;
        }
        sE[(i0+v)*L+c0]=ae0[v]; sE[(i0+v)*L+c0+1]=ae1[v];
    }
    __syncwarp();
    float ag0[8],ag1[8];
    #pragma unroll
    for(int v=0;v<8;v++){ ag0[v]=sdb1[c0]; ag1[v]=sdb1[c0+1]; }
    for(int k=0;k<L;k++){
        float2 wd = __ldg((const float2*)&dW1[k*L+c0]);
        #pragma unroll
        for(int v=0;v<8;v++){
            float ek = sE[(i0+v)*L+k];
            ag0[v]=fmaf(ek,wd.x,ag0[v]); ag1[v]=fmaf(ek,wd.y,ag1[v]);
        }
    }
    float autoS = 0.f;
    #pragma unroll
    for(int v=0;v<8;v++){
        float pa = fmaxf(ag0[v],0.f)*sdW2[c0] + fmaxf(ag1[v],0.f)*sdW2[c0+1];
        for(int o=16;o;o>>=1) pa += __shfl_xor_sync(0xffffffffu, pa, o);
        float aout = pa + db2v;
        if(val[v] && lane==0){ float d = aout - Uv[v]; autoS += d*d; }
    }
    float tot = encS;
    for(int o=16;o;o>>=1) tot += __shfl_xor_sync(0xffffffffu, tot, o);
    float at = autoS;
    for(int o=16;o;o>>=1) at += __shfl_xor_sync(0xffffffffu, at, o);
    if(lane==0) red[w] = (double)lossW * ((double)tot/((double)NN*64.0) + (double)at/(double)NN);
    __syncthreads();
    if(tid==0){
        double s = 0.0;
        for(int i=0;i<8;i++) s += red[i];
        atomicAdd(&g_loss, s);
    }
}

// ---------------- residual loss (rowJ/rowA: 8B/edge) ----------------
__global__ __launch_bounds__(256) void k_res(const float* __restrict__ y, float wgt){
    __shared__ double red[8];
    int lane = threadIdx.x&31, w = threadIdx.x>>5;
    int wid = blockIdx.x*8 + w;
    int nwarps = gridDim.x*8;
    float ls = 0.f;
    for(int n = wid; n < NN; n += nwarps){
        int s = g_rowptr[n], e = g_rowptr[n+1];
        float part = 0.f;
        for(int p = s+lane; p < e; p += 32){
            part += g_rowA[p] * g_U[g_rowJ[p]];
        }
        for(int o=16;o;o>>=1) part += __shfl_xor_sync(0xffffffffu, part, o);
        if(lane==0){ float d = part - y[n]; ls += d*d; }
    }
    for(int o=16;o;o>>=1) ls += __shfl_xor_sync(0xffffffffu, ls, o);
    if(lane==0) red[w] = (double)ls;
    __syncthreads();
    if(threadIdx.x==0){
        double s=0.0; for(int i=0;i<8;i++) s+=red[i];
        atomicAdd(&g_loss, s * (double)wgt / (double)NN);
    }
}

// ---------------- finalize + reset state for next replay ----------------
__global__ void k_fin(float* __restrict__ out, int out_size){
    int i = blockIdx.x*blockDim.x + threadIdx.x;
    if(i < NN && i < out_size) out[i] = g_U[i];
    if(i == NN){
        if(i < out_size) out[NN] = (float)g_loss;
        g_loss = 0.0;
    }
    if(i < NN){ g_cntr[i]=0; g_cntc[i]=0; }
}

extern "C" void kernel_launch(void* const* d_in, const int* in_sizes, int n_in,
                              void* d_out, int out_size){
    const float* x    = (const float*)d_in[0];
    const float* y    = (const float*)d_in[2];
    const int*   tags = (const int*)  d_in[3];
    const int*   ei   = (const int*)  d_in[4];
    const float* ea   = (const float*)d_in[5];
    const float* aij  = (const float*)d_in[6];
    const float* prb  = (const float*)d_in[7];
    const float* ptW1 = (const float*)d_in[8];
    const float* ptb1 = (const float*)d_in[9];
    const float* ptW2 = (const float*)d_in[10];
    const float* ptb2 = (const float*)d_in[11];
    const float* pfW1 = (const float*)d_in[12];
    const float* pfb1 = (const float*)d_in[13];
    const float* pfW2 = (const float*)d_in[14];
    const float* pfb2 = (const float*)d_in[15];
    const float* zkW  = (const float*)d_in[16];
    const float* zkb  = (const float*)d_in[17];
    const float* rkW  = (const float*)d_in[18];
    const float* rkb  = (const float*)d_in[19];
    const float* cW   = (const float*)d_in[20];
    const float* cb   = (const float*)d_in[21];
    const float* eW1  = (const float*)d_in[22];
    const float* eb1  = (const float*)d_in[23];
    const float* eW2  = (const float*)d_in[24];
    const float* eb2  = (const float*)d_in[25];
    const float* dW1  = (const float*)d_in[26];
    const float* db1  = (const float*)d_in[27];
    const float* dW2  = (const float*)d_in[28];
    const float* db2  = (const float*)d_in[29];

    cudaFuncSetAttribute(k_prep,   cudaFuncAttributeMaxDynamicSharedMemorySize, PREP_SMEM);
    cudaFuncSetAttribute(k_gate,   cudaFuncAttributeMaxDynamicSharedMemorySize, GATE_SMEM);
    cudaFuncSetAttribute(k_decode, cudaFuncAttributeMaxDynamicSharedMemorySize, DEC_SMEM);

    int *rowptr, *colptr;
    float4 *rowE4, *colE4;
    float *Pt, *Qt, *Pf, *Qf, *mt, *mf;
    cudaGetSymbolAddress((void**)&rowptr, g_rowptr);
    cudaGetSymbolAddress((void**)&colptr, g_colptr);
    cudaGetSymbolAddress((void**)&rowE4,  g_rowE4);
    cudaGetSymbolAddress((void**)&colE4,  g_colE4);
    cudaGetSymbolAddress((void**)&Pt, g_Pt);
    cudaGetSymbolAddress((void**)&Qt, g_Qt);
    cudaGetSymbolAddress((void**)&Pf, g_Pf);
    cudaGetSymbolAddress((void**)&Qf, g_Qf);
    cudaGetSymbolAddress((void**)&mt, g_mt);
    cudaGetSymbolAddress((void**)&mf, g_mf);

    k_enc0<<<NB32, 256>>>(x, eW1, eb1, eW2, eb2);                        // 0
    k_hist<<<(NE+255)/256, 256>>>(ei);                                   // 1
    k_scan<<<1, 1024>>>(tags);                                           // 2
    k_prep<<<NB64, 256, PREP_SMEM>>>(ptW1, ptb1, pfW1, pfb1, 0);         // 3 (profiled control)
    k_scatter<<<(NE+255)/256, 256>>>(ei, ea, aij);                       // 4
    // Dirichlet nodes: losses identical both steps -> once, weight 2
    k_decode<<<NB64, 256, DEC_SMEM>>>(0, 2.0f, dW1, db1, dW2, db2, eW1, eb1, eW2, eb2);

    const float gammaw[2] = {0.9f, 1.0f};
    for(int step=0; step<2; step++){
        k_aggr<<<2*NB32, 256>>>(colptr, colE4, rowptr, rowE4,
                                Pt, Qt, Pf, Qf,
                                ptW1, ptb2, ptW2, pfW1, pfb2, pfW2, mt, mf);
        k_gate<<<NBG, 256, GATE_SMEM>>>(prb, zkW, zkb, rkW, rkb, cW, cb);
        k_decode<<<NB64, 256, DEC_SMEM>>>(1, 1.0f, dW1, db1, dW2, db2, eW1, eb1, eW2, eb2);
        k_res<<<NB32, 256>>>(y, gammaw[step]);
        if(step == 0)
            k_prep<<<NB64, 256, PREP_SMEM>>>(ptW1, ptb1, pfW1, pfb1, 1);
    }
    k_fin<<<(NN+256)/256, 256>>>((float*)d_out, out_size);
}

// round 13
// speedup vs baseline: 1.0711x; 1.0711x over previous
#include <cuda_runtime.h>
#include <math.h>

#define NN 50000
#define NE 800000
#define L  64
#define NB32 ((NN + 31) / 32)
#define NB64 ((NN + 63) / 64)

// ------------- device scratch (statics zero-initialized; k_fin re-zeroes) -------------
__device__ float  g_H [NN*L];
__device__ float  g_H0[NN*L];
__device__ float  g_Pt[NN*L];
__device__ float  g_Qt[NN*L];
__device__ float  g_Pf[NN*L];
__device__ float  g_Qf[NN*L];
__device__ float  g_mt[NN*L];
__device__ float  g_mf[NN*L];
__device__ float  g_U [NN];
__device__ int    g_rowptr[NN+1];
__device__ int    g_colptr[NN+1];
__device__ int    g_cntr[NN];
__device__ int    g_cntc[NN];
__device__ int    g_nd[NN];
__device__ int    g_dr[NN];
__device__ int    g_ndcount;
__device__ int    g_drcount;
__device__ float4 g_rowE4[NE];
__device__ float4 g_colE4[NE];
__device__ float  g_rowA[NE];
__device__ int    g_rowJ[NE];
__device__ double g_loss;

__device__ __forceinline__ float sigf(float v){ return 1.f/(1.f+__expf(-v)); }

// ---------------- CSR build ----------------
__global__ void k_hist(const int* __restrict__ ei){
    int e = blockIdx.x*blockDim.x + threadIdx.x;
    if(e < NE){
        atomicAdd(&g_cntr[ei[e]], 1);
        atomicAdd(&g_cntc[ei[NE+e]], 1);
    }
}

__device__ void scan_one(int* cnt, int* ptr, int* part){
    const int C = (NN + 1023)/1024;
    int t = threadIdx.x;
    int s = 0;
    for(int k=0;k<C;k++){ int id=t*C+k; if(id<NN) s += cnt[id]; }
    part[t] = s; __syncthreads();
    for(int off=1; off<1024; off<<=1){
        int v = (t>=off)? part[t-off] : 0;
        __syncthreads();
        part[t] += v;
        __syncthreads();
    }
    int run = (t==0)? 0 : part[t-1];
    for(int k=0;k<C;k++){
        int id = t*C+k;
        if(id<NN){ int v=cnt[id]; ptr[id]=run; run+=v; cnt[id]=0; }
    }
    if(t==0) ptr[NN] = part[1023];
    __syncthreads();
}

__global__ void k_scan(const int* __restrict__ tags){
    __shared__ int part[1024];
    scan_one(g_cntr, g_rowptr, part);
    scan_one(g_cntc, g_colptr, part);
    const int C = (NN + 1023)/1024;
    int t = threadIdx.x;
    int cN = 0;
    for(int k=0;k<C;k++){ int id=t*C+k; if(id<NN && tags[id]!=1) cN++; }
    part[t] = cN; __syncthreads();
    for(int off=1; off<1024; off<<=1){
        int v = (t>=off)? part[t-off] : 0;
        __syncthreads();
        part[t] += v;
        __syncthreads();
    }
    int ndBase = (t==0)? 0 : part[t-1];
    int idsBefore = t*C; if(idsBefore > NN) idsBefore = NN;
    int drBase = idsBefore - ndBase;
    for(int k=0;k<C;k++){
        int id = t*C+k;
        if(id<NN){
            if(tags[id]!=1) g_nd[ndBase++] = id;
            else            g_dr[drBase++] = id;
        }
    }
    if(t==1023){ g_ndcount = part[1023]; g_drcount = NN - part[1023]; }
}

__global__ void k_scatter(const int* __restrict__ ei, const float* __restrict__ ea,
                          const float* __restrict__ aij){
    int e = blockIdx.x*blockDim.x + threadIdx.x;
    if(e >= NE) return;
    int r = ei[e], c = ei[NE+e];
    float a0 = ea[3*e], a1 = ea[3*e+1], a2 = ea[3*e+2];
    int pr = atomicAdd(&g_cntr[r], 1);
    int p  = g_rowptr[r] + pr;
    g_rowE4[p] = make_float4(a0,a1,a2,__int_as_float(c));
    g_rowA[p]  = aij[e];
    g_rowJ[p]  = c;
    int pc = atomicAdd(&g_cntc[c], 1);
    int q  = g_colptr[c] + pc;
    g_colE4[q] = make_float4(a0,a1,a2,__int_as_float(r));
}

// ---------------- encoder: x -> H0, H ----------------
__global__ __launch_bounds__(256) void k_enc0(const float* __restrict__ x,
        const float* __restrict__ eW1, const float* __restrict__ eb1,
        const float* __restrict__ eW2, const float* __restrict__ eb2){
    __shared__ float sW[L*L];
    __shared__ float sh[8][4][L];
    int tid = threadIdx.x;
    for(int i=tid;i<L*L/4;i+=256) ((float4*)sW)[i] = ((const float4*)eW2)[i];
    __syncthreads();
    int lane = tid&31, w = tid>>5, c0 = 2*lane;
    int nb = blockIdx.x*32 + w*4;
    float w1a=eW1[c0], w1b=eW1[c0+1], b1a=eb1[c0], b1b=eb1[c0+1];
    float b2a=eb2[c0], b2b=eb2[c0+1];
    bool val[4];
    #pragma unroll
    for(int v=0;v<4;v++){
        int n = nb+v; val[v] = (n<NN);
        float xv = val[v]? x[n] : 0.f;
        sh[w][v][c0]   = fmaxf(fmaf(xv,w1a,b1a),0.f);
        sh[w][v][c0+1] = fmaxf(fmaf(xv,w1b,b1b),0.f);
    }
    __syncwarp();
    float a0[4]={b2a,b2a,b2a,b2a}, a1[4]={b2b,b2b,b2b,b2b};
    for(int k=0;k<L;k++){
        float2 wv = *(const float2*)&sW[k*L+c0];
        #pragma unroll
        for(int v=0;v<4;v++){ float s=sh[w][v][k]; a0[v]=fmaf(s,wv.x,a0[v]); a1[v]=fmaf(s,wv.y,a1[v]); }
    }
    #pragma unroll
    for(int v=0;v<4;v++) if(val[v]){
        int n = nb+v;
        g_H0[n*L+c0]=a0[v]; g_H0[n*L+c0+1]=a1[v];
        g_H [n*L+c0]=a0[v]; g_H [n*L+c0+1]=a1[v];
    }
}

// ---------------- P/Q precompute (both phis), 8 nodes/warp, optional nd-perm ----------------
#define PREP_SMEM ((4*L*L + 64*L)*4)
__global__ __launch_bounds__(256) void k_prep(
        const float* __restrict__ ptW1, const float* __restrict__ ptb1,
        const float* __restrict__ pfW1, const float* __restrict__ pfb1,
        int use_perm){
    if(use_perm && blockIdx.x*64 >= g_ndcount) return;
    extern __shared__ float sm[];
    float* Wat = sm;
    float* Wbt = sm + L*L;
    float* Waf = sm + 2*L*L;
    float* Wbf = sm + 3*L*L;
    float* stg = sm + 4*L*L;
    int tid = threadIdx.x;
    for(int i=tid;i<L*L/4;i+=256){
        ((float4*)Wat)[i] = ((const float4*)ptW1)[i];
        ((float4*)Wbt)[i] = ((const float4*)(ptW1+L*L))[i];
        ((float4*)Waf)[i] = ((const float4*)pfW1)[i];
        ((float4*)Wbf)[i] = ((const float4*)(pfW1+L*L))[i];
    }
    int lane = tid&31, w = tid>>5, c0 = 2*lane;
    int i0 = w*8, sb = blockIdx.x*64 + i0;
    int nid[8]; bool val[8];
    #pragma unroll
    for(int v=0;v<8;v++){
        int slot = sb+v;
        if(use_perm){ val[v] = (slot < g_ndcount); nid[v] = val[v]? g_nd[slot] : 0; }
        else        { val[v] = (slot < NN);        nid[v] = slot; }
        float2 h = val[v]? *(const float2*)&g_H[nid[v]*L+c0] : make_float2(0.f,0.f);
        *(float2*)&stg[(i0+v)*L+c0] = h;
    }
    __syncthreads();
    float pt0[8],pt1[8],qt0[8],qt1[8],pf0[8],pf1[8],qf0[8],qf1[8];
    float bt0=ptb1[c0], bt1=ptb1[c0+1], bf0=pfb1[c0], bf1=pfb1[c0+1];
    #pragma unroll
    for(int v=0;v<8;v++){ pt0[v]=bt0; pt1[v]=bt1; pf0[v]=bf0; pf1[v]=bf1;
                          qt0[v]=0.f; qt1[v]=0.f; qf0[v]=0.f; qf1[v]=0.f; }
    for(int k=0;k<L;k++){
        float2 wat = *(const float2*)&Wat[k*L+c0];
        float2 wbt = *(const float2*)&Wbt[k*L+c0];
        float2 waf = *(const float2*)&Waf[k*L+c0];
        float2 wbf = *(const float2*)&Wbf[k*L+c0];
        #pragma unroll
        for(int v=0;v<8;v++){
            float h = stg[(i0+v)*L + k];
            pt0[v]=fmaf(h,wat.x,pt0[v]); pt1[v]=fmaf(h,wat.y,pt1[v]);
            qt0[v]=fmaf(h,wbt.x,qt0[v]); qt1[v]=fmaf(h,wbt.y,qt1[v]);
            pf0[v]=fmaf(h,waf.x,pf0[v]); pf1[v]=fmaf(h,waf.y,pf1[v]);
            qf0[v]=fmaf(h,wbf.x,qf0[v]); qf1[v]=fmaf(h,wbf.y,qf1[v]);
        }
    }
    #pragma unroll
    for(int v=0;v<8;v++) if(val[v]){
        int n = nid[v];
        g_Pt[n*L+c0]=pt0[v]; g_Pt[n*L+c0+1]=pt1[v];
        g_Qt[n*L+c0]=qt0[v]; g_Qt[n*L+c0+1]=qt1[v];
        g_Pf[n*L+c0]=pf0[v]; g_Pf[n*L+c0+1]=pf1[v];
        g_Qf[n*L+c0]=qf0[v]; g_Qf[n*L+c0+1]=qf1[v];
    }
}

// ---------------- edge aggregation + W2 fold (R9 champion version) ----------------
__global__ __launch_bounds__(256) void k_aggr(
        const int* __restrict__ colptr, const float4* __restrict__ colE4,
        const int* __restrict__ rowptr, const float4* __restrict__ rowE4,
        const float* __restrict__ Pt, const float* __restrict__ Qt,
        const float* __restrict__ Pf, const float* __restrict__ Qf,
        const float* __restrict__ ptW1, const float* __restrict__ ptb2, const float* __restrict__ ptW2,
        const float* __restrict__ pfW1, const float* __restrict__ pfb2, const float* __restrict__ pfW2,
        float* __restrict__ mt, float* __restrict__ mf){
    bool toDir = (blockIdx.x < NB32);
    int bb = toDir ? blockIdx.x : blockIdx.x - NB32;
    if(bb*32 >= g_ndcount) return;
    __shared__ float sW2[L*L];
    __shared__ float sWe[3*L];
    __shared__ float sS[8][4][L];
    const int*    ptr = toDir ? colptr : rowptr;
    const float4* e4  = toDir ? colE4  : rowE4;
    const float*  P   = toDir ? Pt     : Pf;
    const float*  Q   = toDir ? Qt     : Qf;
    const float*  W1  = toDir ? ptW1   : pfW1;
    const float*  b2  = toDir ? ptb2   : pfb2;
    const float*  W2  = toDir ? ptW2   : pfW2;
    float*        out = toDir ? mt     : mf;
    int tid = threadIdx.x;
    for(int i=tid;i<L*L/4;i+=256) ((float4*)sW2)[i] = ((const float4*)W2)[i];
    for(int i=tid;i<3*L;i+=256) sWe[i] = W1[2*L*L + i];
    __syncthreads();
    int lane = tid&31, w = tid>>5, c0 = 2*lane;
    int sb = bb*32 + w*4;
    float we0a=sWe[c0],     we0b=sWe[c0+1];
    float we1a=sWe[L+c0],   we1b=sWe[L+c0+1];
    float we2a=sWe[2*L+c0], we2b=sWe[2*L+c0+1];
    float degv[4]; bool val[4]; int nid[4];
    #pragma unroll
    for(int v=0;v<4;v++){
        int slot = sb+v;
        val[v] = (slot < g_ndcount);
        int n = val[v]? g_nd[slot] : 0;
        nid[v] = n;
        float acc0=0.f, acc1=0.f; int cnt=0;
        if(val[v]){
            float base0 = P[n*L+c0], base1 = P[n*L+c0+1];
            int s = ptr[n], e = ptr[n+1];
            for(int p=s; p<e; p++){
                float4 E = e4[p];
                int j = __float_as_int(E.w);
                if(j == n) continue;
                cnt++;
                float2 qv = *(const float2*)&Q[j*L+c0];
                float pre0 = base0 + qv.x + E.x*we0a + E.y*we1a + E.z*we2a;
                float pre1 = base1 + qv.y + E.x*we0b + E.y*we1b + E.z*we2b;
                acc0 += fmaxf(pre0, 0.f);
                acc1 += fmaxf(pre1, 0.f);
            }
        }
        sS[w][v][c0]=acc0; sS[w][v][c0+1]=acc1; degv[v]=(float)cnt;
    }
    __syncwarp();
    float b2a=b2[c0], b2b=b2[c0+1];
    float o0[4],o1[4];
    #pragma unroll
    for(int v=0;v<4;v++){ o0[v]=degv[v]*b2a; o1[v]=degv[v]*b2b; }
    for(int k=0;k<L;k++){
        float2 wv = *(const float2*)&sW2[k*L+c0];
        #pragma unroll
        for(int v=0;v<4;v++){ float s=sS[w][v][k]; o0[v]=fmaf(s,wv.x,o0[v]); o1[v]=fmaf(s,wv.y,o1[v]); }
    }
    #pragma unroll
    for(int v=0;v<4;v++) if(val[v]){
        int n = nid[v];
        out[n*L+c0]=o0[v]; out[n*L+c0+1]=o1[v];
    }
}

// ---------------- gates: non-dir nodes only, 64/block, 8/warp (R9 champion version) ----------------
#define GATE_SMEM ((3*194*L + 64*196 + 64*L)*4)
__global__ __launch_bounds__(256) void k_gate(
        const float* __restrict__ prb,
        const float* __restrict__ zkW, const float* __restrict__ zkb,
        const float* __restrict__ rkW, const float* __restrict__ rkb,
        const float* __restrict__ cW,  const float* __restrict__ cb){
    if(blockIdx.x*64 >= g_ndcount) return;
    extern __shared__ float sm[];
    float* szk  = sm;
    float* srk  = szk + 194*L;
    float* scw  = srk + 194*L;
    float* stgA = scw + 194*L;        // [64][196]
    float* stgB = stgA + 64*196;      // [64][64]
    __shared__ float szb[L], srb[L], scb[L];
    int tid = threadIdx.x;
    for(int i=tid;i<194*L/4;i+=256){
        ((float4*)szk)[i] = ((const float4*)zkW)[i];
        ((float4*)srk)[i] = ((const float4*)rkW)[i];
        ((float4*)scw)[i] = ((const float4*)cW)[i];
    }
    if(tid<L){ szb[tid]=zkb[tid]; srb[tid]=rkb[tid]; scb[tid]=cb[tid]; }
    int lane = tid&31, w = tid>>5, c0 = 2*lane;
    int i0 = w*8, sb = blockIdx.x*64 + i0;
    int nid[8]; bool val[8];
    #pragma unroll
    for(int v=0;v<8;v++){
        int slot = sb+v; val[v] = (slot < g_ndcount);
        int n = val[v]? g_nd[slot] : 0; nid[v] = n;
        float* A = stgA + (i0+v)*196;
        if(val[v]){
            *(float2*)&A[c0]     = *(const float2*)&g_H [n*L+c0];
            *(float2*)&A[64+c0]  = *(const float2*)&g_mt[n*L+c0];
            *(float2*)&A[128+c0] = *(const float2*)&g_mf[n*L+c0];
            if(lane==0){ A[192]=prb[2*n]; A[193]=prb[2*n+1]; }
        } else {
            *(float2*)&A[c0]     = make_float2(0.f,0.f);
            *(float2*)&A[64+c0]  = make_float2(0.f,0.f);
            *(float2*)&A[128+c0] = make_float2(0.f,0.f);
            if(lane==0){ A[192]=0.f; A[193]=0.f; }
        }
    }
    __syncthreads();
    float az0[8],az1[8],ar0[8],ar1[8],ac0[8],ac1[8];
    #pragma unroll
    for(int v=0;v<8;v++){ az0[v]=0.f; az1[v]=0.f; ar0[v]=0.f; ar1[v]=0.f; ac0[v]=0.f; ac1[v]=0.f; }
    for(int k=0;k<64;k++){
        float2 wz = *(const float2*)&szk[k*L+c0];
        float2 wr = *(const float2*)&srk[k*L+c0];
        #pragma unroll
        for(int v=0;v<8;v++){
            float cv = stgA[(i0+v)*196 + k];
            az0[v]=fmaf(cv,wz.x,az0[v]); az1[v]=fmaf(cv,wz.y,az1[v]);
            ar0[v]=fmaf(cv,wr.x,ar0[v]); ar1[v]=fmaf(cv,wr.y,ar1[v]);
        }
    }
    for(int k=64;k<194;k++){
        float2 wz = *(const float2*)&szk[k*L+c0];
        float2 wr = *(const float2*)&srk[k*L+c0];
        float2 wc = *(const float2*)&scw[k*L+c0];
        #pragma unroll
        for(int v=0;v<8;v++){
            float cv = stgA[(i0+v)*196 + k];
            az0[v]=fmaf(cv,wz.x,az0[v]); az1[v]=fmaf(cv,wz.y,az1[v]);
            ar0[v]=fmaf(cv,wr.x,ar0[v]); ar1[v]=fmaf(cv,wr.y,ar1[v]);
            ac0[v]=fmaf(cv,wc.x,ac0[v]); ac1[v]=fmaf(cv,wc.y,ac1[v]);
        }
    }
    float z0[8],z1[8];
    #pragma unroll
    for(int v=0;v<8;v++){
        z0[v]=sigf(az0[v]+szb[c0]); z1[v]=sigf(az1[v]+szb[c0+1]);
        float rr0=sigf(ar0[v]+srb[c0]), rr1=sigf(ar1[v]+srb[c0+1]);
        stgB[(i0+v)*L+c0]=rr0; stgB[(i0+v)*L+c0+1]=rr1;
    }
    __syncwarp();
    for(int k=0;k<64;k++){
        float2 wc = *(const float2*)&scw[k*L+c0];
        #pragma unroll
        for(int v=0;v<8;v++){
            float rh = stgB[(i0+v)*L+k] * stgA[(i0+v)*196+k];
            ac0[v]=fmaf(rh,wc.x,ac0[v]); ac1[v]=fmaf(rh,wc.y,ac1[v]);
        }
    }
    #pragma unroll
    for(int v=0;v<8;v++) if(val[v]){
        int n = nid[v];
        float* A = stgA + (i0+v)*196;
        float co0 = tanhf(ac0[v]+scb[c0]);
        float co1 = tanhf(ac1[v]+scb[c0+1]);
        float hn0 = A[c0]   + z0[v]*co0;
        float hn1 = A[c0+1] + z1[v]*co1;
        g_H[n*L+c0]   = hn0;
        g_H[n*L+c0+1] = hn1;
    }
}

// ---------------- decode + enc/autoenc losses over a node list (R9 champion version) ----------------
#define DEC_SMEM (3*64*L*4)
__global__ __launch_bounds__(256) void k_decode(
        int mode, float lossW,
        const float* __restrict__ dW1, const float* __restrict__ db1,
        const float* __restrict__ dW2, const float* __restrict__ db2,
        const float* __restrict__ eW1, const float* __restrict__ eb1,
        const float* __restrict__ eW2, const float* __restrict__ eb2){
    int cnt = mode ? g_ndcount : g_drcount;
    if(blockIdx.x*64 >= cnt) return;
    const int* list = mode ? g_nd : g_dr;
    extern __shared__ float sm[];
    float* sHn = sm;
    float* sB  = sm + 64*L;
    float* sE  = sm + 2*64*L;
    __shared__ float sdW2[L], sdb1[L], sE1[L], sEb1[L], sEb2[L];
    __shared__ double red[8];
    int tid = threadIdx.x;
    if(tid<L){ sdW2[tid]=dW2[tid]; sdb1[tid]=db1[tid]; sE1[tid]=eW1[tid];
               sEb1[tid]=eb1[tid]; sEb2[tid]=eb2[tid]; }
    __syncthreads();
    int lane = tid&31, w = tid>>5, c0 = 2*lane;
    int i0 = w*8, sb = blockIdx.x*64 + i0;
    float db2v = db2[0];
    int nid[8]; bool val[8];
    #pragma unroll
    for(int v=0;v<8;v++){
        int slot = sb+v; val[v] = (slot < cnt);
        nid[v] = val[v]? list[slot] : 0;
        float2 h = val[v]? *(const float2*)&g_H[nid[v]*L+c0] : make_float2(0.f,0.f);
        *(float2*)&sHn[(i0+v)*L+c0] = h;
    }
    __syncwarp();
    float ad0[8],ad1[8];
    #pragma unroll
    for(int v=0;v<8;v++){ ad0[v]=sdb1[c0]; ad1[v]=sdb1[c0+1]; }
    for(int k=0;k<L;k++){
        float2 wd = __ldg((const float2*)&dW1[k*L+c0]);
        #pragma unroll
        for(int v=0;v<8;v++){
            float hk = sHn[(i0+v)*L+k];
            ad0[v]=fmaf(hk,wd.x,ad0[v]); ad1[v]=fmaf(hk,wd.y,ad1[v]);
        }
    }
    float Uv[8];
    #pragma unroll
    for(int v=0;v<8;v++){
        float pu = fmaxf(ad0[v],0.f)*sdW2[c0] + fmaxf(ad1[v],0.f)*sdW2[c0+1];
        for(int o=16;o;o>>=1) pu += __shfl_xor_sync(0xffffffffu, pu, o);
        Uv[v] = pu + db2v;
        if(val[v] && lane==0) g_U[nid[v]] = Uv[v];
        float eh0 = fmaxf(fmaf(Uv[v],sE1[c0],sEb1[c0]),0.f);
        float eh1 = fmaxf(fmaf(Uv[v],sE1[c0+1],sEb1[c0+1]),0.f);
        sB[(i0+v)*L+c0]=eh0; sB[(i0+v)*L+c0+1]=eh1;
    }
    __syncwarp();
    float ae0[8],ae1[8];
    #pragma unroll
    for(int v=0;v<8;v++){ ae0[v]=sEb2[c0]; ae1[v]=sEb2[c0+1]; }
    for(int k=0;k<L;k++){
        float2 we = __ldg((const float2*)&eW2[k*L+c0]);
        #pragma unroll
        for(int v=0;v<8;v++){
            float ek = sB[(i0+v)*L+k];
            ae0[v]=fmaf(ek,we.x,ae0[v]); ae1[v]=fmaf(ek,we.y,ae1[v]);
        }
    }
    float encS = 0.f;
    #pragma unroll
    for(int v=0;v<8;v++){
        if(val[v]){
            float d0 = ae0[v]-sHn[(i0+v)*L+c0], d1 = ae1[v]-sHn[(i0+v)*L+c0+1];
            encS += d0*d0 + d1*d1;
        }
        sE[(i0+v)*L+c0]=ae0[v]; sE[(i0+v)*L+c0+1]=ae1[v];
    }
    __syncwarp();
    float ag0[8],ag1[8];
    #pragma unroll
    for(int v=0;v<8;v++){ ag0[v]=sdb1[c0]; ag1[v]=sdb1[c0+1]; }
    for(int k=0;k<L;k++){
        float2 wd = __ldg((const float2*)&dW1[k*L+c0]);
        #pragma unroll
        for(int v=0;v<8;v++){
            float ek = sE[(i0+v)*L+k];
            ag0[v]=fmaf(ek,wd.x,ag0[v]); ag1[v]=fmaf(ek,wd.y,ag1[v]);
        }
    }
    float autoS = 0.f;
    #pragma unroll
    for(int v=0;v<8;v++){
        float pa = fmaxf(ag0[v],0.f)*sdW2[c0] + fmaxf(ag1[v],0.f)*sdW2[c0+1];
        for(int o=16;o;o>>=1) pa += __shfl_xor_sync(0xffffffffu, pa, o);
        float aout = pa + db2v;
        if(val[v] && lane==0){ float d = aout - Uv[v]; autoS += d*d; }
    }
    float tot = encS;
    for(int o=16;o;o>>=1) tot += __shfl_xor_sync(0xffffffffu, tot, o);
    float at = autoS;
    for(int o=16;o;o>>=1) at += __shfl_xor_sync(0xffffffffu, at, o);
    if(lane==0) red[w] = (double)lossW * ((double)tot/((double)NN*64.0) + (double)at/(double)NN);
    __syncthreads();
    if(tid==0){
        double s = 0.0;
        for(int i=0;i<8;i++) s += red[i];
        atomicAdd(&g_loss, s);
    }
}

// ---------------- residual loss (rowJ/rowA: 8B/edge) ----------------
__global__ __launch_bounds__(256) void k_res(const float* __restrict__ y, float wgt){
    __shared__ double red[8];
    int lane = threadIdx.x&31, w = threadIdx.x>>5;
    int wid = blockIdx.x*8 + w;
    int nwarps = gridDim.x*8;
    float ls = 0.f;
    for(int n = wid; n < NN; n += nwarps){
        int s = g_rowptr[n], e = g_rowptr[n+1];
        float part = 0.f;
        for(int p = s+lane; p < e; p += 32){
            part += g_rowA[p] * g_U[g_rowJ[p]];
        }
        for(int o=16;o;o>>=1) part += __shfl_xor_sync(0xffffffffu, part, o);
        if(lane==0){ float d = part - y[n]; ls += d*d; }
    }
    for(int o=16;o;o>>=1) ls += __shfl_xor_sync(0xffffffffu, ls, o);
    if(lane==0) red[w] = (double)ls;
    __syncthreads();
    if(threadIdx.x==0){
        double s=0.0; for(int i=0;i<8;i++) s+=red[i];
        atomicAdd(&g_loss, s * (double)wgt / (double)NN);
    }
}

// ---------------- finalize + reset state for next replay ----------------
__global__ void k_fin(float* __restrict__ out, int out_size){
    int i = blockIdx.x*blockDim.x + threadIdx.x;
    if(i < NN && i < out_size) out[i] = g_U[i];
    if(i == NN){
        if(i < out_size) out[NN] = (float)g_loss;
        g_loss = 0.0;
    }
    if(i < NN){ g_cntr[i]=0; g_cntc[i]=0; }
}

extern "C" void kernel_launch(void* const* d_in, const int* in_sizes, int n_in,
                              void* d_out, int out_size){
    const float* x    = (const float*)d_in[0];
    const float* y    = (const float*)d_in[2];
    const int*   tags = (const int*)  d_in[3];
    const int*   ei   = (const int*)  d_in[4];
    const float* ea   = (const float*)d_in[5];
    const float* aij  = (const float*)d_in[6];
    const float* prb  = (const float*)d_in[7];
    const float* ptW1 = (const float*)d_in[8];
    const float* ptb1 = (const float*)d_in[9];
    const float* ptW2 = (const float*)d_in[10];
    const float* ptb2 = (const float*)d_in[11];
    const float* pfW1 = (const float*)d_in[12];
    const float* pfb1 = (const float*)d_in[13];
    const float* pfW2 = (const float*)d_in[14];
    const float* pfb2 = (const float*)d_in[15];
    const float* zkW  = (const float*)d_in[16];
    const float* zkb  = (const float*)d_in[17];
    const float* rkW  = (const float*)d_in[18];
    const float* rkb  = (const float*)d_in[19];
    const float* cW   = (const float*)d_in[20];
    const float* cb   = (const float*)d_in[21];
    const float* eW1  = (const float*)d_in[22];
    const float* eb1  = (const float*)d_in[23];
    const float* eW2  = (const float*)d_in[24];
    const float* eb2  = (const float*)d_in[25];
    const float* dW1  = (const float*)d_in[26];
    const float* db1  = (const float*)d_in[27];
    const float* dW2  = (const float*)d_in[28];
    const float* db2  = (const float*)d_in[29];

    cudaFuncSetAttribute(k_prep,   cudaFuncAttributeMaxDynamicSharedMemorySize, PREP_SMEM);
    cudaFuncSetAttribute(k_gate,   cudaFuncAttributeMaxDynamicSharedMemorySize, GATE_SMEM);
    cudaFuncSetAttribute(k_decode, cudaFuncAttributeMaxDynamicSharedMemorySize, DEC_SMEM);

    int *rowptr, *colptr;
    float4 *rowE4, *colE4;
    float *Pt, *Qt, *Pf, *Qf, *mt, *mf;
    cudaGetSymbolAddress((void**)&rowptr, g_rowptr);
    cudaGetSymbolAddress((void**)&colptr, g_colptr);
    cudaGetSymbolAddress((void**)&rowE4,  g_rowE4);
    cudaGetSymbolAddress((void**)&colE4,  g_colE4);
    cudaGetSymbolAddress((void**)&Pt, g_Pt);
    cudaGetSymbolAddress((void**)&Qt, g_Qt);
    cudaGetSymbolAddress((void**)&Pf, g_Pf);
    cudaGetSymbolAddress((void**)&Qf, g_Qf);
    cudaGetSymbolAddress((void**)&mt, g_mt);
    cudaGetSymbolAddress((void**)&mf, g_mf);

    // side stream + events: created lazily on the first (eager) call, reused thereafter
    static cudaStream_t s1 = 0;
    static cudaEvent_t evA=0, evB=0, evP=0, evC=0, evG=0, evD=0;
    if(!s1){
        cudaStreamCreateWithFlags(&s1, cudaStreamNonBlocking);
        cudaEventCreateWithFlags(&evA, cudaEventDisableTiming);
        cudaEventCreateWithFlags(&evB, cudaEventDisableTiming);
        cudaEventCreateWithFlags(&evP, cudaEventDisableTiming);
        cudaEventCreateWithFlags(&evC, cudaEventDisableTiming);
        cudaEventCreateWithFlags(&evG, cudaEventDisableTiming);
        cudaEventCreateWithFlags(&evD, cudaEventDisableTiming);
    }

    // ---- fork: s1 runs enc0 + full prep (fma-bound) ----
    cudaEventRecord(evA, 0);
    cudaStreamWaitEvent(s1, evA, 0);
    k_enc0<<<NB32, 256, 0, s1>>>(x, eW1, eb1, eW2, eb2);
    k_prep<<<NB64, 256, PREP_SMEM, s1>>>(ptW1, ptb1, pfW1, pfb1, 0);
    cudaEventRecord(evP, s1);

    // ---- main stream: CSR build (memory/atomic-bound) ----
    k_hist<<<(NE+255)/256, 256>>>(ei);
    k_scan<<<1, 1024>>>(tags);
    cudaEventRecord(evB, 0);               // nd/dr lists ready
    k_scatter<<<(NE+255)/256, 256>>>(ei, ea, aij);

    // ---- s1: Dirichlet decode (needs enc0 + lists), runs parallel with scatter/aggr0 ----
    cudaStreamWaitEvent(s1, evB, 0);
    k_decode<<<NB64, 256, DEC_SMEM, s1>>>(0, 2.0f, dW1, db1, dW2, db2, eW1, eb1, eW2, eb2);
    cudaEventRecord(evC, s1);

    // ---- main stream: join prep before aggr0 ----
    cudaStreamWaitEvent(0, evP, 0);
    const float gammaw[2] = {0.9f, 1.0f};

    // step 0
    k_aggr<<<2*NB32, 256>>>(colptr, colE4, rowptr, rowE4, Pt, Qt, Pf, Qf,
                            ptW1, ptb2, ptW2, pfW1, pfb2, pfW2, mt, mf);
    k_gate<<<NB64, 256, GATE_SMEM>>>(prb, zkW, zkb, rkW, rkb, cW, cb);
    cudaEventRecord(evG, 0);               // g_H[nd] updated
    // s1: recompute P/Q for changed (non-dir) nodes, parallel with decode_nd0 + res0
    cudaStreamWaitEvent(s1, evG, 0);
    k_prep<<<NB64, 256, PREP_SMEM, s1>>>(ptW1, ptb1, pfW1, pfb1, 1);
    cudaEventRecord(evD, s1);
    // main: decode + residual (res0 needs dr decode too)
    k_decode<<<NB64, 256, DEC_SMEM>>>(1, 1.0f, dW1, db1, dW2, db2, eW1, eb1, eW2, eb2);
    cudaStreamWaitEvent(0, evC, 0);
    k_res<<<NB32, 256>>>(y, gammaw[0]);

    // step 1 (join prep_nd first)
    cudaStreamWaitEvent(0, evD, 0);
    k_aggr<<<2*NB32, 256>>>(colptr, colE4, rowptr, rowE4, Pt, Qt, Pf, Qf,
                            ptW1, ptb2, ptW2, pfW1, pfb2, pfW2, mt, mf);
    k_gate<<<NB64, 256, GATE_SMEM>>>(prb, zkW, zkb, rkW, rkb, cW, cb);
    k_decode<<<NB64, 256, DEC_SMEM>>>(1, 1.0f, dW1, db1, dW2, db2, eW1, eb1, eW2, eb2);
    k_res<<<NB32, 256>>>(y, gammaw[1]);

    k_fin<<<(NN+256)/256, 256>>>((float*)d_out, out_size);
}

// round 14
// speedup vs baseline: 1.4361x; 1.3407x over previous
#include <cuda_runtime.h>
#include <math.h>

#define NN 50000
#define NE 800000
#define L  64
#define NB32 ((NN + 31) / 32)
#define NB64 ((NN + 63) / 64)
#define SBLK ((NN + 255) / 256)

// ------------- device scratch (statics zero-initialized; k_fin re-zeroes) -------------
__device__ float  g_H [NN*L];
__device__ float  g_H0[NN*L];
__device__ float  g_Pt[NN*L];
__device__ float  g_Qt[NN*L];
__device__ float  g_Pf[NN*L];
__device__ float  g_Qf[NN*L];
__device__ float  g_mt[NN*L];
__device__ float  g_mf[NN*L];
__device__ float  g_U [NN];
__device__ int    g_rowptr[NN+1];
__device__ int    g_colptr[NN+1];
__device__ int    g_cntr[NN];
__device__ int    g_cntc[NN];
__device__ int    g_nd[NN];
__device__ int    g_dr[NN];
__device__ int    g_ndcount;
__device__ int    g_drcount;
__device__ int    g_partR[256], g_partC[256], g_partN[256];
__device__ int    g_baseR[256], g_baseC[256], g_baseN[256];
__device__ float4 g_rowE4[NE];
__device__ float4 g_colE4[NE];
__device__ float  g_rowA[NE];
__device__ int    g_rowJ[NE];
__device__ double g_loss;

__device__ __forceinline__ float sigf(float v){ return 1.f/(1.f+__expf(-v)); }

// ---------------- CSR build ----------------
__global__ void k_hist(const int* __restrict__ ei){
    int e = blockIdx.x*blockDim.x + threadIdx.x;
    if(e < NE){
        atomicAdd(&g_cntr[ei[e]], 1);
        atomicAdd(&g_cntc[ei[NE+e]], 1);
    }
}

// phase A: per-block sums
__global__ __launch_bounds__(256) void k_scanA(const int* __restrict__ tags){
    __shared__ int sR[256], sC[256], sN[256];
    int tid = threadIdx.x;
    int t = blockIdx.x*256 + tid;
    int cr=0, cc=0, nd=0;
    if(t < NN){ cr = g_cntr[t]; cc = g_cntc[t]; nd = (tags[t]!=1); }
    sR[tid]=cr; sC[tid]=cc; sN[tid]=nd;
    __syncthreads();
    for(int off=128; off; off>>=1){
        if(tid < off){ sR[tid]+=sR[tid+off]; sC[tid]+=sC[tid+off]; sN[tid]+=sN[tid+off]; }
        __syncthreads();
    }
    if(tid==0){ g_partR[blockIdx.x]=sR[0]; g_partC[blockIdx.x]=sC[0]; g_partN[blockIdx.x]=sN[0]; }
}

// phase B: scan partials (1 small block)
__global__ __launch_bounds__(256) void k_scanB(){
    __shared__ int sR[256], sC[256], sN[256];
    int i = threadIdx.x;
    int vR = (i<SBLK)? g_partR[i] : 0;
    int vC = (i<SBLK)? g_partC[i] : 0;
    int vN = (i<SBLK)? g_partN[i] : 0;
    sR[i]=vR; sC[i]=vC; sN[i]=vN;
    __syncthreads();
    for(int off=1; off<256; off<<=1){
        int aR=0,aC=0,aN=0;
        if(i>=off){ aR=sR[i-off]; aC=sC[i-off]; aN=sN[i-off]; }
        __syncthreads();
        sR[i]+=aR; sC[i]+=aC; sN[i]+=aN;
        __syncthreads();
    }
    if(i<SBLK){
        g_baseR[i] = sR[i]-vR;   // exclusive
        g_baseC[i] = sC[i]-vC;
        g_baseN[i] = sN[i]-vN;
    }
    if(i==0){
        int totR = sR[SBLK-1], totC = sC[SBLK-1], totN = sN[SBLK-1];
        g_rowptr[NN] = totR;
        g_colptr[NN] = totC;
        g_ndcount = totN;
        g_drcount = NN - totN;
    }
}

// phase C: intra-block scan, write ptrs, zero counters, compact nd/dr
__global__ __launch_bounds__(256) void k_scanC(const int* __restrict__ tags){
    __shared__ int sR[256], sC[256], sN[256];
    int tid = threadIdx.x;
    int t = blockIdx.x*256 + tid;
    int cr=0, cc=0, nd=0;
    if(t < NN){ cr = g_cntr[t]; cc = g_cntc[t]; nd = (tags[t]!=1); }
    sR[tid]=cr; sC[tid]=cc; sN[tid]=nd;
    __syncthreads();
    for(int off=1; off<256; off<<=1){
        int aR=0,aC=0,aN=0;
        if(tid>=off){ aR=sR[tid-off]; aC=sC[tid-off]; aN=sN[tid-off]; }
        __syncthreads();
        sR[tid]+=aR; sC[tid]+=aC; sN[tid]+=aN;
        __syncthreads();
    }
    if(t < NN){
        int exR = sR[tid]-cr, exC = sC[tid]-cc, exN = sN[tid]-nd;
        g_rowptr[t] = g_baseR[blockIdx.x] + exR;
        g_colptr[t] = g_baseC[blockIdx.x] + exC;
        g_cntr[t] = 0; g_cntc[t] = 0;
        int ndpos = g_baseN[blockIdx.x] + exN;
        if(nd) g_nd[ndpos] = t;
        else   g_dr[t - ndpos] = t;
    }
}

__global__ void k_scatter(const int* __restrict__ ei, const float* __restrict__ ea,
                          const float* __restrict__ aij){
    int e = blockIdx.x*blockDim.x + threadIdx.x;
    if(e >= NE) return;
    int r = ei[e], c = ei[NE+e];
    float a0 = ea[3*e], a1 = ea[3*e+1], a2 = ea[3*e+2];
    int pr = atomicAdd(&g_cntr[r], 1);
    int p  = g_rowptr[r] + pr;
    g_rowE4[p] = make_float4(a0,a1,a2,__int_as_float(c));
    g_rowA[p]  = aij[e];
    g_rowJ[p]  = c;
    int pc = atomicAdd(&g_cntc[c], 1);
    int q  = g_colptr[c] + pc;
    g_colE4[q] = make_float4(a0,a1,a2,__int_as_float(r));
}

// ---------------- encoder: x -> H0, H ----------------
__global__ __launch_bounds__(256) void k_enc0(const float* __restrict__ x,
        const float* __restrict__ eW1, const float* __restrict__ eb1,
        const float* __restrict__ eW2, const float* __restrict__ eb2){
    __shared__ float sW[L*L];
    __shared__ float sh[8][4][L];
    int tid = threadIdx.x;
    for(int i=tid;i<L*L/4;i+=256) ((float4*)sW)[i] = ((const float4*)eW2)[i];
    __syncthreads();
    int lane = tid&31, w = tid>>5, c0 = 2*lane;
    int nb = blockIdx.x*32 + w*4;
    float w1a=eW1[c0], w1b=eW1[c0+1], b1a=eb1[c0], b1b=eb1[c0+1];
    float b2a=eb2[c0], b2b=eb2[c0+1];
    bool val[4];
    #pragma unroll
    for(int v=0;v<4;v++){
        int n = nb+v; val[v] = (n<NN);
        float xv = val[v]? x[n] : 0.f;
        sh[w][v][c0]   = fmaxf(fmaf(xv,w1a,b1a),0.f);
        sh[w][v][c0+1] = fmaxf(fmaf(xv,w1b,b1b),0.f);
    }
    __syncwarp();
    float a0[4]={b2a,b2a,b2a,b2a}, a1[4]={b2b,b2b,b2b,b2b};
    for(int k=0;k<L;k++){
        float2 wv = *(const float2*)&sW[k*L+c0];
        #pragma unroll
        for(int v=0;v<4;v++){ float s=sh[w][v][k]; a0[v]=fmaf(s,wv.x,a0[v]); a1[v]=fmaf(s,wv.y,a1[v]); }
    }
    #pragma unroll
    for(int v=0;v<4;v++) if(val[v]){
        int n = nb+v;
        g_H0[n*L+c0]=a0[v]; g_H0[n*L+c0+1]=a1[v];
        g_H [n*L+c0]=a0[v]; g_H [n*L+c0+1]=a1[v];
    }
}

// ---------------- P/Q precompute (both phis), 8 nodes/warp, optional nd-perm ----------------
#define PREP_SMEM ((4*L*L + 64*L)*4)
__global__ __launch_bounds__(256) void k_prep(
        const float* __restrict__ ptW1, const float* __restrict__ ptb1,
        const float* __restrict__ pfW1, const float* __restrict__ pfb1,
        int use_perm){
    if(use_perm && blockIdx.x*64 >= g_ndcount) return;
    extern __shared__ float sm[];
    float* Wat = sm;
    float* Wbt = sm + L*L;
    float* Waf = sm + 2*L*L;
    float* Wbf = sm + 3*L*L;
    float* stg = sm + 4*L*L;
    int tid = threadIdx.x;
    for(int i=tid;i<L*L/4;i+=256){
        ((float4*)Wat)[i] = ((const float4*)ptW1)[i];
        ((float4*)Wbt)[i] = ((const float4*)(ptW1+L*L))[i];
        ((float4*)Waf)[i] = ((const float4*)pfW1)[i];
        ((float4*)Wbf)[i] = ((const float4*)(pfW1+L*L))[i];
    }
    int lane = tid&31, w = tid>>5, c0 = 2*lane;
    int i0 = w*8, sb = blockIdx.x*64 + i0;
    int nid[8]; bool val[8];
    #pragma unroll
    for(int v=0;v<8;v++){
        int slot = sb+v;
        if(use_perm){ val[v] = (slot < g_ndcount); nid[v] = val[v]? g_nd[slot] : 0; }
        else        { val[v] = (slot < NN);        nid[v] = slot; }
        float2 h = val[v]? *(const float2*)&g_H[nid[v]*L+c0] : make_float2(0.f,0.f);
        *(float2*)&stg[(i0+v)*L+c0] = h;
    }
    __syncthreads();
    float pt0[8],pt1[8],qt0[8],qt1[8],pf0[8],pf1[8],qf0[8],qf1[8];
    float bt0=ptb1[c0], bt1=ptb1[c0+1], bf0=pfb1[c0], bf1=pfb1[c0+1];
    #pragma unroll
    for(int v=0;v<8;v++){ pt0[v]=bt0; pt1[v]=bt1; pf0[v]=bf0; pf1[v]=bf1;
                          qt0[v]=0.f; qt1[v]=0.f; qf0[v]=0.f; qf1[v]=0.f; }
    for(int k=0;k<L;k++){
        float2 wat = *(const float2*)&Wat[k*L+c0];
        float2 wbt = *(const float2*)&Wbt[k*L+c0];
        float2 waf = *(const float2*)&Waf[k*L+c0];
        float2 wbf = *(const float2*)&Wbf[k*L+c0];
        #pragma unroll
        for(int v=0;v<8;v++){
            float h = stg[(i0+v)*L + k];
            pt0[v]=fmaf(h,wat.x,pt0[v]); pt1[v]=fmaf(h,wat.y,pt1[v]);
            qt0[v]=fmaf(h,wbt.x,qt0[v]); qt1[v]=fmaf(h,wbt.y,qt1[v]);
            pf0[v]=fmaf(h,waf.x,pf0[v]); pf1[v]=fmaf(h,waf.y,pf1[v]);
            qf0[v]=fmaf(h,wbf.x,qf0[v]); qf1[v]=fmaf(h,wbf.y,qf1[v]);
        }
    }
    #pragma unroll
    for(int v=0;v<8;v++) if(val[v]){
        int n = nid[v];
        g_Pt[n*L+c0]=pt0[v]; g_Pt[n*L+c0+1]=pt1[v];
        g_Qt[n*L+c0]=qt0[v]; g_Qt[n*L+c0+1]=qt1[v];
        g_Pf[n*L+c0]=pf0[v]; g_Pf[n*L+c0+1]=pf1[v];
        g_Qf[n*L+c0]=qf0[v]; g_Qf[n*L+c0+1]=qf1[v];
    }
}

// ---------------- edge aggregation + W2 fold (R9 champion version) ----------------
__global__ __launch_bounds__(256) void k_aggr(
        const int* __restrict__ colptr, const float4* __restrict__ colE4,
        const int* __restrict__ rowptr, const float4* __restrict__ rowE4,
        const float* __restrict__ Pt, const float* __restrict__ Qt,
        const float* __restrict__ Pf, const float* __restrict__ Qf,
        const float* __restrict__ ptW1, const float* __restrict__ ptb2, const float* __restrict__ ptW2,
        const float* __restrict__ pfW1, const float* __restrict__ pfb2, const float* __restrict__ pfW2,
        float* __restrict__ mt, float* __restrict__ mf){
    bool toDir = (blockIdx.x < NB32);
    int bb = toDir ? blockIdx.x : blockIdx.x - NB32;
    if(bb*32 >= g_ndcount) return;
    __shared__ float sW2[L*L];
    __shared__ float sWe[3*L];
    __shared__ float sS[8][4][L];
    const int*    ptr = toDir ? colptr : rowptr;
    const float4* e4  = toDir ? colE4  : rowE4;
    const float*  P   = toDir ? Pt     : Pf;
    const float*  Q   = toDir ? Qt     : Qf;
    const float*  W1  = toDir ? ptW1   : pfW1;
    const float*  b2  = toDir ? ptb2   : pfb2;
    const float*  W2  = toDir ? ptW2   : pfW2;
    float*        out = toDir ? mt     : mf;
    int tid = threadIdx.x;
    for(int i=tid;i<L*L/4;i+=256) ((float4*)sW2)[i] = ((const float4*)W2)[i];
    for(int i=tid;i<3*L;i+=256) sWe[i] = W1[2*L*L + i];
    __syncthreads();
    int lane = tid&31, w = tid>>5, c0 = 2*lane;
    int sb = bb*32 + w*4;
    float we0a=sWe[c0],     we0b=sWe[c0+1];
    float we1a=sWe[L+c0],   we1b=sWe[L+c0+1];
    float we2a=sWe[2*L+c0], we2b=sWe[2*L+c0+1];
    float degv[4]; bool val[4]; int nid[4];
    #pragma unroll
    for(int v=0;v<4;v++){
        int slot = sb+v;
        val[v] = (slot < g_ndcount);
        int n = val[v]? g_nd[slot] : 0;
        nid[v] = n;
        float acc0=0.f, acc1=0.f; int cnt=0;
        if(val[v]){
            float base0 = P[n*L+c0], base1 = P[n*L+c0+1];
            int s = ptr[n], e = ptr[n+1];
            for(int p=s; p<e; p++){
                float4 E = e4[p];
                int j = __float_as_int(E.w);
                if(j == n) continue;
                cnt++;
                float2 qv = *(const float2*)&Q[j*L+c0];
                float pre0 = base0 + qv.x + E.x*we0a + E.y*we1a + E.z*we2a;
                float pre1 = base1 + qv.y + E.x*we0b + E.y*we1b + E.z*we2b;
                acc0 += fmaxf(pre0, 0.f);
                acc1 += fmaxf(pre1, 0.f);
            }
        }
        sS[w][v][c0]=acc0; sS[w][v][c0+1]=acc1; degv[v]=(float)cnt;
    }
    __syncwarp();
    float b2a=b2[c0], b2b=b2[c0+1];
    float o0[4],o1[4];
    #pragma unroll
    for(int v=0;v<4;v++){ o0[v]=degv[v]*b2a; o1[v]=degv[v]*b2b; }
    for(int k=0;k<L;k++){
        float2 wv = *(const float2*)&sW2[k*L+c0];
        #pragma unroll
        for(int v=0;v<4;v++){ float s=sS[w][v][k]; o0[v]=fmaf(s,wv.x,o0[v]); o1[v]=fmaf(s,wv.y,o1[v]); }
    }
    #pragma unroll
    for(int v=0;v<4;v++) if(val[v]){
        int n = nid[v];
        out[n*L+c0]=o0[v]; out[n*L+c0+1]=o1[v];
    }
}

// ---------------- gates: non-dir nodes only, 64/block, 8/warp (R9 champion version) ----------------
#define GATE_SMEM ((3*194*L + 64*196 + 64*L)*4)
__global__ __launch_bounds__(256) void k_gate(
        const float* __restrict__ prb,
        const float* __restrict__ zkW, const float* __restrict__ zkb,
        const float* __restrict__ rkW, const float* __restrict__ rkb,
        const float* __restrict__ cW,  const float* __restrict__ cb){
    if(blockIdx.x*64 >= g_ndcount) return;
    extern __shared__ float sm[];
    float* szk  = sm;
    float* srk  = szk + 194*L;
    float* scw  = srk + 194*L;
    float* stgA = scw + 194*L;        // [64][196]
    float* stgB = stgA + 64*196;      // [64][64]
    __shared__ float szb[L], srb[L], scb[L];
    int tid = threadIdx.x;
    for(int i=tid;i<194*L/4;i+=256){
        ((float4*)szk)[i] = ((const float4*)zkW)[i];
        ((float4*)srk)[i] = ((const float4*)rkW)[i];
        ((float4*)scw)[i] = ((const float4*)cW)[i];
    }
    if(tid<L){ szb[tid]=zkb[tid]; srb[tid]=rkb[tid]; scb[tid]=cb[tid]; }
    int lane = tid&31, w = tid>>5, c0 = 2*lane;
    int i0 = w*8, sb = blockIdx.x*64 + i0;
    int nid[8]; bool val[8];
    #pragma unroll
    for(int v=0;v<8;v++){
        int slot = sb+v; val[v] = (slot < g_ndcount);
        int n = val[v]? g_nd[slot] : 0; nid[v] = n;
        float* A = stgA + (i0+v)*196;
        if(val[v]){
            *(float2*)&A[c0]     = *(const float2*)&g_H [n*L+c0];
            *(float2*)&A[64+c0]  = *(const float2*)&g_mt[n*L+c0];
            *(float2*)&A[128+c0] = *(const float2*)&g_mf[n*L+c0];
            if(lane==0){ A[192]=prb[2*n]; A[193]=prb[2*n+1]; }
        } else {
            *(float2*)&A[c0]     = make_float2(0.f,0.f);
            *(float2*)&A[64+c0]  = make_float2(0.f,0.f);
            *(float2*)&A[128+c0] = make_float2(0.f,0.f);
            if(lane==0){ A[192]=0.f; A[193]=0.f; }
        }
    }
    __syncthreads();
    float az0[8],az1[8],ar0[8],ar1[8],ac0[8],ac1[8];
    #pragma unroll
    for(int v=0;v<8;v++){ az0[v]=0.f; az1[v]=0.f; ar0[v]=0.f; ar1[v]=0.f; ac0[v]=0.f; ac1[v]=0.f; }
    for(int k=0;k<64;k++){
        float2 wz = *(const float2*)&szk[k*L+c0];
        float2 wr = *(const float2*)&srk[k*L+c0];
        #pragma unroll
        for(int v=0;v<8;v++){
            float cv = stgA[(i0+v)*196 + k];
            az0[v]=fmaf(cv,wz.x,az0[v]); az1[v]=fmaf(cv,wz.y,az1[v]);
            ar0[v]=fmaf(cv,wr.x,ar0[v]); ar1[v]=fmaf(cv,wr.y,ar1[v]);
        }
    }
    for(int k=64;k<194;k++){
        float2 wz = *(const float2*)&szk[k*L+c0];
        float2 wr = *(const float2*)&srk[k*L+c0];
        float2 wc = *(const float2*)&scw[k*L+c0];
        #pragma unroll
        for(int v=0;v<8;v++){
            float cv = stgA[(i0+v)*196 + k];
            az0[v]=fmaf(cv,wz.x,az0[v]); az1[v]=fmaf(cv,wz.y,az1[v]);
            ar0[v]=fmaf(cv,wr.x,ar0[v]); ar1[v]=fmaf(cv,wr.y,ar1[v]);
            ac0[v]=fmaf(cv,wc.x,ac0[v]); ac1[v]=fmaf(cv,wc.y,ac1[v]);
        }
    }
    float z0[8],z1[8];
    #pragma unroll
    for(int v=0;v<8;v++){
        z0[v]=sigf(az0[v]+szb[c0]); z1[v]=sigf(az1[v]+szb[c0+1]);
        float rr0=sigf(ar0[v]+srb[c0]), rr1=sigf(ar1[v]+srb[c0+1]);
        stgB[(i0+v)*L+c0]=rr0; stgB[(i0+v)*L+c0+1]=rr1;
    }
    __syncwarp();
    for(int k=0;k<64;k++){
        float2 wc = *(const float2*)&scw[k*L+c0];
        #pragma unroll
        for(int v=0;v<8;v++){
            float rh = stgB[(i0+v)*L+k] * stgA[(i0+v)*196+k];
            ac0[v]=fmaf(rh,wc.x,ac0[v]); ac1[v]=fmaf(rh,wc.y,ac1[v]);
        }
    }
    #pragma unroll
    for(int v=0;v<8;v++) if(val[v]){
        int n = nid[v];
        float* A = stgA + (i0+v)*196;
        float co0 = tanhf(ac0[v]+scb[c0]);
        float co1 = tanhf(ac1[v]+scb[c0+1]);
        float hn0 = A[c0]   + z0[v]*co0;
        float hn1 = A[c0+1] + z1[v]*co1;
        g_H[n*L+c0]   = hn0;
        g_H[n*L+c0+1] = hn1;
    }
}

// ---------------- decode + enc/autoenc losses over a node list (R9 champion version) ----------------
#define DEC_SMEM (3*64*L*4)
__global__ __launch_bounds__(256) void k_decode(
        int mode, float lossW,
        const float* __restrict__ dW1, const float* __restrict__ db1,
        const float* __restrict__ dW2, const float* __restrict__ db2,
        const float* __restrict__ eW1, const float* __restrict__ eb1,
        const float* __restrict__ eW2, const float* __restrict__ eb2){
    int cnt = mode ? g_ndcount : g_drcount;
    if(blockIdx.x*64 >= cnt) return;
    const int* list = mode ? g_nd : g_dr;
    extern __shared__ float sm[];
    float* sHn = sm;
    float* sB  = sm + 64*L;
    float* sE  = sm + 2*64*L;
    __shared__ float sdW2[L], sdb1[L], sE1[L], sEb1[L], sEb2[L];
    __shared__ double red[8];
    int tid = threadIdx.x;
    if(tid<L){ sdW2[tid]=dW2[tid]; sdb1[tid]=db1[tid]; sE1[tid]=eW1[tid];
               sEb1[tid]=eb1[tid]; sEb2[tid]=eb2[tid]; }
    __syncthreads();
    int lane = tid&31, w = tid>>5, c0 = 2*lane;
    int i0 = w*8, sb = blockIdx.x*64 + i0;
    float db2v = db2[0];
    int nid[8]; bool val[8];
    #pragma unroll
    for(int v=0;v<8;v++){
        int slot = sb+v; val[v] = (slot < cnt);
        nid[v] = val[v]? list[slot] : 0;
        float2 h = val[v]? *(const float2*)&g_H[nid[v]*L+c0] : make_float2(0.f,0.f);
        *(float2*)&sHn[(i0+v)*L+c0] = h;
    }
    __syncwarp();
    float ad0[8],ad1[8];
    #pragma unroll
    for(int v=0;v<8;v++){ ad0[v]=sdb1[c0]; ad1[v]=sdb1[c0+1]; }
    for(int k=0;k<L;k++){
        float2 wd = __ldg((const float2*)&dW1[k*L+c0]);
        #pragma unroll
        for(int v=0;v<8;v++){
            float hk = sHn[(i0+v)*L+k];
            ad0[v]=fmaf(hk,wd.x,ad0[v]); ad1[v]=fmaf(hk,wd.y,ad1[v]);
        }
    }
    float Uv[8];
    #pragma unroll
    for(int v=0;v<8;v++){
        float pu = fmaxf(ad0[v],0.f)*sdW2[c0] + fmaxf(ad1[v],0.f)*sdW2[c0+1];
        for(int o=16;o;o>>=1) pu += __shfl_xor_sync(0xffffffffu, pu, o);
        Uv[v] = pu + db2v;
        if(val[v] && lane==0) g_U[nid[v]] = Uv[v];
        float eh0 = fmaxf(fmaf(Uv[v],sE1[c0],sEb1[c0]),0.f);
        float eh1 = fmaxf(fmaf(Uv[v],sE1[c0+1],sEb1[c0+1]),0.f);
        sB[(i0+v)*L+c0]=eh0; sB[(i0+v)*L+c0+1]=eh1;
    }
    __syncwarp();
    float ae0[8],ae1[8];
    #pragma unroll
    for(int v=0;v<8;v++){ ae0[v]=sEb2[c0]; ae1[v]=sEb2[c0+1]; }
    for(int k=0;k<L;k++){
        float2 we = __ldg((const float2*)&eW2[k*L+c0]);
        #pragma unroll
        for(int v=0;v<8;v++){
            float ek = sB[(i0+v)*L+k];
            ae0[v]=fmaf(ek,we.x,ae0[v]); ae1[v]=fmaf(ek,we.y,ae1[v]);
        }
    }
    float encS = 0.f;
    #pragma unroll
    for(int v=0;v<8;v++){
        if(val[v]){
            float d0 = ae0[v]-sHn[(i0+v)*L+c0], d1 = ae1[v]-sHn[(i0+v)*L+c0+1];
            encS += d0*d0 + d1*d1;
        }
        sE[(i0+v)*L+c0]=ae0[v]; sE[(i0+v)*L+c0+1]=ae1[v];
    }
    __syncwarp();
    float ag0[8],ag1[8];
    #pragma unroll
    for(int v=0;v<8;v++){ ag0[v]=sdb1[c0]; ag1[v]=sdb1[c0+1]; }
    for(int k=0;k<L;k++){
        float2 wd = __ldg((const float2*)&dW1[k*L+c0]);
        #pragma unroll
        for(int v=0;v<8;v++){
            float ek = sE[(i0+v)*L+k];
            ag0[v]=fmaf(ek,wd.x,ag0[v]); ag1[v]=fmaf(ek,wd.y,ag1[v]);
        }
    }
    float autoS = 0.f;
    #pragma unroll
    for(int v=0;v<8;v++){
        float pa = fmaxf(ag0[v],0.f)*sdW2[c0] + fmaxf(ag1[v],0.f)*sdW2[c0+1];
        for(int o=16;o;o>>=1) pa += __shfl_xor_sync(0xffffffffu, pa, o);
        float aout = pa + db2v;
        if(val[v] && lane==0){ float d = aout - Uv[v]; autoS += d*d; }
    }
    float tot = encS;
    for(int o=16;o;o>>=1) tot += __shfl_xor_sync(0xffffffffu, tot, o);
    float at = autoS;
    for(int o=16;o;o>>=1) at += __shfl_xor_sync(0xffffffffu, at, o);
    if(lane==0) red[w] = (double)lossW * ((double)tot/((double)NN*64.0) + (double)at/(double)NN);
    __syncthreads();
    if(tid==0){
        double s = 0.0;
        for(int i=0;i<8;i++) s += red[i];
        atomicAdd(&g_loss, s);
    }
}

// ---------------- residual loss (rowJ/rowA: 8B/edge) ----------------
__global__ __launch_bounds__(256) void k_res(const float* __restrict__ y, float wgt){
    __shared__ double red[8];
    int lane = threadIdx.x&31, w = threadIdx.x>>5;
    int wid = blockIdx.x*8 + w;
    int nwarps = gridDim.x*8;
    float ls = 0.f;
    for(int n = wid; n < NN; n += nwarps){
        int s = g_rowptr[n], e = g_rowptr[n+1];
        float part = 0.f;
        for(int p = s+lane; p < e; p += 32){
            part += g_rowA[p] * g_U[g_rowJ[p]];
        }
        for(int o=16;o;o>>=1) part += __shfl_xor_sync(0xffffffffu, part, o);
        if(lane==0){ float d = part - y[n]; ls += d*d; }
    }
    for(int o=16;o;o>>=1) ls += __shfl_xor_sync(0xffffffffu, ls, o);
    if(lane==0) red[w] = (double)ls;
    __syncthreads();
    if(threadIdx.x==0){
        double s=0.0; for(int i=0;i<8;i++) s+=red[i];
        atomicAdd(&g_loss, s * (double)wgt / (double)NN);
    }
}

// ---------------- finalize + reset state for next replay ----------------
__global__ void k_fin(float* __restrict__ out, int out_size){
    int i = blockIdx.x*blockDim.x + threadIdx.x;
    if(i < NN && i < out_size) out[i] = g_U[i];
    if(i == NN){
        if(i < out_size) out[NN] = (float)g_loss;
        g_loss = 0.0;
    }
    if(i < NN){ g_cntr[i]=0; g_cntc[i]=0; }
}

extern "C" void kernel_launch(void* const* d_in, const int* in_sizes, int n_in,
                              void* d_out, int out_size){
    const float* x    = (const float*)d_in[0];
    const float* y    = (const float*)d_in[2];
    const int*   tags = (const int*)  d_in[3];
    const int*   ei   = (const int*)  d_in[4];
    const float* ea   = (const float*)d_in[5];
    const float* aij  = (const float*)d_in[6];
    const float* prb  = (const float*)d_in[7];
    const float* ptW1 = (const float*)d_in[8];
    const float* ptb1 = (const float*)d_in[9];
    const float* ptW2 = (const float*)d_in[10];
    const float* ptb2 = (const float*)d_in[11];
    const float* pfW1 = (const float*)d_in[12];
    const float* pfb1 = (const float*)d_in[13];
    const float* pfW2 = (const float*)d_in[14];
    const float* pfb2 = (const float*)d_in[15];
    const float* zkW  = (const float*)d_in[16];
    const float* zkb  = (const float*)d_in[17];
    const float* rkW  = (const float*)d_in[18];
    const float* rkb  = (const float*)d_in[19];
    const float* cW   = (const float*)d_in[20];
    const float* cb   = (const float*)d_in[21];
    const float* eW1  = (const float*)d_in[22];
    const float* eb1  = (const float*)d_in[23];
    const float* eW2  = (const float*)d_in[24];
    const float* eb2  = (const float*)d_in[25];
    const float* dW1  = (const float*)d_in[26];
    const float* db1  = (const float*)d_in[27];
    const float* dW2  = (const float*)d_in[28];
    const float* db2  = (const float*)d_in[29];

    cudaFuncSetAttribute(k_prep,   cudaFuncAttributeMaxDynamicSharedMemorySize, PREP_SMEM);
    cudaFuncSetAttribute(k_gate,   cudaFuncAttributeMaxDynamicSharedMemorySize, GATE_SMEM);
    cudaFuncSetAttribute(k_decode, cudaFuncAttributeMaxDynamicSharedMemorySize, DEC_SMEM);

    int *rowptr, *colptr;
    float4 *rowE4, *colE4;
    float *Pt, *Qt, *Pf, *Qf, *mt, *mf;
    cudaGetSymbolAddress((void**)&rowptr, g_rowptr);
    cudaGetSymbolAddress((void**)&colptr, g_colptr);
    cudaGetSymbolAddress((void**)&rowE4,  g_rowE4);
    cudaGetSymbolAddress((void**)&colE4,  g_colE4);
    cudaGetSymbolAddress((void**)&Pt, g_Pt);
    cudaGetSymbolAddress((void**)&Qt, g_Qt);
    cudaGetSymbolAddress((void**)&Pf, g_Pf);
    cudaGetSymbolAddress((void**)&Qf, g_Qf);
    cudaGetSymbolAddress((void**)&mt, g_mt);
    cudaGetSymbolAddress((void**)&mf, g_mf);

    k_enc0<<<NB32, 256>>>(x, eW1, eb1, eW2, eb2);                        // 0
    k_hist<<<(NE+255)/256, 256>>>(ei);                                   // 1
    k_scanA<<<SBLK, 256>>>(tags);                                        // 2
    k_prep<<<NB64, 256, PREP_SMEM>>>(ptW1, ptb1, pfW1, pfb1, 0);         // 3 (profiled control)
    k_scanB<<<1, 256>>>();                                               // 4
    k_scanC<<<SBLK, 256>>>(tags);                                        // 5
    k_scatter<<<(NE+255)/256, 256>>>(ei, ea, aij);                       // 6
    // Dirichlet nodes: losses identical both steps -> once, weight 2
    k_decode<<<NB64, 256, DEC_SMEM>>>(0, 2.0f, dW1, db1, dW2, db2, eW1, eb1, eW2, eb2);

    const float gammaw[2] = {0.9f, 1.0f};
    for(int step=0; step<2; step++){
        k_aggr<<<2*NB32, 256>>>(colptr, colE4, rowptr, rowE4,
                                Pt, Qt, Pf, Qf,
                                ptW1, ptb2, ptW2, pfW1, pfb2, pfW2, mt, mf);
        k_gate<<<NB64, 256, GATE_SMEM>>>(prb, zkW, zkb, rkW, rkb, cW, cb);
        k_decode<<<NB64, 256, DEC_SMEM>>>(1, 1.0f, dW1, db1, dW2, db2, eW1, eb1, eW2, eb2);
        k_res<<<NB32, 256>>>(y, gammaw[step]);
        if(step == 0)
            k_prep<<<NB64, 256, PREP_SMEM>>>(ptW1, ptb1, pfW1, pfb1, 1);
    }
    k_fin<<<(NN+256)/256, 256>>>((float*)d_out, out_size);
}

// round 15
// speedup vs baseline: 1.4594x; 1.0162x over previous
#include <cuda_runtime.h>
#include <math.h>

#define NN 50000
#define NE 800000
#define L  64
#define NB32 ((NN + 31) / 32)
#define NB64 ((NN + 63) / 64)
#define SBLK ((NN + 255) / 256)
#define GN   48
#define NBG  ((NN + GN - 1) / GN)

// ------------- device scratch (statics zero-initialized; k_fin re-zeroes) -------------
__device__ float  g_H [NN*L];
__device__ float  g_H0[NN*L];
__device__ float  g_Pt[NN*L];
__device__ float  g_Qt[NN*L];
__device__ float  g_Pf[NN*L];
__device__ float  g_Qf[NN*L];
__device__ float  g_mt[NN*L];
__device__ float  g_mf[NN*L];
__device__ float  g_U [NN];
__device__ int    g_rowptr[NN+1];
__device__ int    g_colptr[NN+1];
__device__ int    g_cntr[NN];
__device__ int    g_cntc[NN];
__device__ int    g_nd[NN];
__device__ int    g_dr[NN];
__device__ int    g_ndcount;
__device__ int    g_drcount;
__device__ int    g_partR[256], g_partC[256], g_partN[256];
__device__ int    g_baseR[256], g_baseC[256], g_baseN[256];
__device__ float4 g_rowE4[NE];
__device__ float4 g_colE4[NE];
__device__ float  g_rowA[NE];
__device__ int    g_rowJ[NE];
__device__ double g_loss;

__device__ __forceinline__ float sigf(float v){ return 1.f/(1.f+__expf(-v)); }

// ---------------- CSR build ----------------
__global__ void k_hist(const int* __restrict__ ei){
    int e = blockIdx.x*blockDim.x + threadIdx.x;
    if(e < NE){
        atomicAdd(&g_cntr[ei[e]], 1);
        atomicAdd(&g_cntc[ei[NE+e]], 1);
    }
}

// phase A: per-block sums
__global__ __launch_bounds__(256) void k_scanA(const int* __restrict__ tags){
    __shared__ int sR[256], sC[256], sN[256];
    int tid = threadIdx.x;
    int t = blockIdx.x*256 + tid;
    int cr=0, cc=0, nd=0;
    if(t < NN){ cr = g_cntr[t]; cc = g_cntc[t]; nd = (tags[t]!=1); }
    sR[tid]=cr; sC[tid]=cc; sN[tid]=nd;
    __syncthreads();
    for(int off=128; off; off>>=1){
        if(tid < off){ sR[tid]+=sR[tid+off]; sC[tid]+=sC[tid+off]; sN[tid]+=sN[tid+off]; }
        __syncthreads();
    }
    if(tid==0){ g_partR[blockIdx.x]=sR[0]; g_partC[blockIdx.x]=sC[0]; g_partN[blockIdx.x]=sN[0]; }
}

// phase B: scan partials (1 small block)
__global__ __launch_bounds__(256) void k_scanB(){
    __shared__ int sR[256], sC[256], sN[256];
    int i = threadIdx.x;
    int vR = (i<SBLK)? g_partR[i] : 0;
    int vC = (i<SBLK)? g_partC[i] : 0;
    int vN = (i<SBLK)? g_partN[i] : 0;
    sR[i]=vR; sC[i]=vC; sN[i]=vN;
    __syncthreads();
    for(int off=1; off<256; off<<=1){
        int aR=0,aC=0,aN=0;
        if(i>=off){ aR=sR[i-off]; aC=sC[i-off]; aN=sN[i-off]; }
        __syncthreads();
        sR[i]+=aR; sC[i]+=aC; sN[i]+=aN;
        __syncthreads();
    }
    if(i<SBLK){
        g_baseR[i] = sR[i]-vR;   // exclusive
        g_baseC[i] = sC[i]-vC;
        g_baseN[i] = sN[i]-vN;
    }
    if(i==0){
        int totR = sR[SBLK-1], totC = sC[SBLK-1], totN = sN[SBLK-1];
        g_rowptr[NN] = totR;
        g_colptr[NN] = totC;
        g_ndcount = totN;
        g_drcount = NN - totN;
    }
}

// phase C: intra-block scan, write ptrs, zero counters, compact nd/dr
__global__ __launch_bounds__(256) void k_scanC(const int* __restrict__ tags){
    __shared__ int sR[256], sC[256], sN[256];
    int tid = threadIdx.x;
    int t = blockIdx.x*256 + tid;
    int cr=0, cc=0, nd=0;
    if(t < NN){ cr = g_cntr[t]; cc = g_cntc[t]; nd = (tags[t]!=1); }
    sR[tid]=cr; sC[tid]=cc; sN[tid]=nd;
    __syncthreads();
    for(int off=1; off<256; off<<=1){
        int aR=0,aC=0,aN=0;
        if(tid>=off){ aR=sR[tid-off]; aC=sC[tid-off]; aN=sN[tid-off]; }
        __syncthreads();
        sR[tid]+=aR; sC[tid]+=aC; sN[tid]+=aN;
        __syncthreads();
    }
    if(t < NN){
        int exR = sR[tid]-cr, exC = sC[tid]-cc, exN = sN[tid]-nd;
        g_rowptr[t] = g_baseR[blockIdx.x] + exR;
        g_colptr[t] = g_baseC[blockIdx.x] + exC;
        g_cntr[t] = 0; g_cntc[t] = 0;
        int ndpos = g_baseN[blockIdx.x] + exN;
        if(nd) g_nd[ndpos] = t;
        else   g_dr[t - ndpos] = t;
    }
}

__global__ void k_scatter(const int* __restrict__ ei, const float* __restrict__ ea,
                          const float* __restrict__ aij){
    int e = blockIdx.x*blockDim.x + threadIdx.x;
    if(e >= NE) return;
    int r = ei[e], c = ei[NE+e];
    float a0 = ea[3*e], a1 = ea[3*e+1], a2 = ea[3*e+2];
    int pr = atomicAdd(&g_cntr[r], 1);
    int p  = g_rowptr[r] + pr;
    g_rowE4[p] = make_float4(a0,a1,a2,__int_as_float(c));
    g_rowA[p]  = aij[e];
    g_rowJ[p]  = c;
    int pc = atomicAdd(&g_cntc[c], 1);
    int q  = g_colptr[c] + pc;
    g_colE4[q] = make_float4(a0,a1,a2,__int_as_float(r));
}

// ---------------- encoder: x -> H0, H ----------------
__global__ __launch_bounds__(256) void k_enc0(const float* __restrict__ x,
        const float* __restrict__ eW1, const float* __restrict__ eb1,
        const float* __restrict__ eW2, const float* __restrict__ eb2){
    __shared__ float sW[L*L];
    __shared__ float sh[8][4][L];
    int tid = threadIdx.x;
    for(int i=tid;i<L*L/4;i+=256) ((float4*)sW)[i] = ((const float4*)eW2)[i];
    __syncthreads();
    int lane = tid&31, w = tid>>5, c0 = 2*lane;
    int nb = blockIdx.x*32 + w*4;
    float w1a=eW1[c0], w1b=eW1[c0+1], b1a=eb1[c0], b1b=eb1[c0+1];
    float b2a=eb2[c0], b2b=eb2[c0+1];
    bool val[4];
    #pragma unroll
    for(int v=0;v<4;v++){
        int n = nb+v; val[v] = (n<NN);
        float xv = val[v]? x[n] : 0.f;
        sh[w][v][c0]   = fmaxf(fmaf(xv,w1a,b1a),0.f);
        sh[w][v][c0+1] = fmaxf(fmaf(xv,w1b,b1b),0.f);
    }
    __syncwarp();
    float a0[4]={b2a,b2a,b2a,b2a}, a1[4]={b2b,b2b,b2b,b2b};
    for(int k=0;k<L;k++){
        float2 wv = *(const float2*)&sW[k*L+c0];
        #pragma unroll
        for(int v=0;v<4;v++){ float s=sh[w][v][k]; a0[v]=fmaf(s,wv.x,a0[v]); a1[v]=fmaf(s,wv.y,a1[v]); }
    }
    #pragma unroll
    for(int v=0;v<4;v++) if(val[v]){
        int n = nb+v;
        g_H0[n*L+c0]=a0[v]; g_H0[n*L+c0+1]=a1[v];
        g_H [n*L+c0]=a0[v]; g_H [n*L+c0+1]=a1[v];
    }
}

// ---------------- P/Q precompute (both phis), 8 nodes/warp, optional nd-perm ----------------
#define PREP_SMEM ((4*L*L + 64*L)*4)
__global__ __launch_bounds__(256) void k_prep(
        const float* __restrict__ ptW1, const float* __restrict__ ptb1,
        const float* __restrict__ pfW1, const float* __restrict__ pfb1,
        int use_perm){
    if(use_perm && blockIdx.x*64 >= g_ndcount) return;
    extern __shared__ float sm[];
    float* Wat = sm;
    float* Wbt = sm + L*L;
    float* Waf = sm + 2*L*L;
    float* Wbf = sm + 3*L*L;
    float* stg = sm + 4*L*L;
    int tid = threadIdx.x;
    for(int i=tid;i<L*L/4;i+=256){
        ((float4*)Wat)[i] = ((const float4*)ptW1)[i];
        ((float4*)Wbt)[i] = ((const float4*)(ptW1+L*L))[i];
        ((float4*)Waf)[i] = ((const float4*)pfW1)[i];
        ((float4*)Wbf)[i] = ((const float4*)(pfW1+L*L))[i];
    }
    int lane = tid&31, w = tid>>5, c0 = 2*lane;
    int i0 = w*8, sb = blockIdx.x*64 + i0;
    int nid[8]; bool val[8];
    #pragma unroll
    for(int v=0;v<8;v++){
        int slot = sb+v;
        if(use_perm){ val[v] = (slot < g_ndcount); nid[v] = val[v]? g_nd[slot] : 0; }
        else        { val[v] = (slot < NN);        nid[v] = slot; }
        float2 h = val[v]? *(const float2*)&g_H[nid[v]*L+c0] : make_float2(0.f,0.f);
        *(float2*)&stg[(i0+v)*L+c0] = h;
    }
    __syncthreads();
    float pt0[8],pt1[8],qt0[8],qt1[8],pf0[8],pf1[8],qf0[8],qf1[8];
    float bt0=ptb1[c0], bt1=ptb1[c0+1], bf0=pfb1[c0], bf1=pfb1[c0+1];
    #pragma unroll
    for(int v=0;v<8;v++){ pt0[v]=bt0; pt1[v]=bt1; pf0[v]=bf0; pf1[v]=bf1;
                          qt0[v]=0.f; qt1[v]=0.f; qf0[v]=0.f; qf1[v]=0.f; }
    for(int k=0;k<L;k++){
        float2 wat = *(const float2*)&Wat[k*L+c0];
        float2 wbt = *(const float2*)&Wbt[k*L+c0];
        float2 waf = *(const float2*)&Waf[k*L+c0];
        float2 wbf = *(const float2*)&Wbf[k*L+c0];
        #pragma unroll
        for(int v=0;v<8;v++){
            float h = stg[(i0+v)*L + k];
            pt0[v]=fmaf(h,wat.x,pt0[v]); pt1[v]=fmaf(h,wat.y,pt1[v]);
            qt0[v]=fmaf(h,wbt.x,qt0[v]); qt1[v]=fmaf(h,wbt.y,qt1[v]);
            pf0[v]=fmaf(h,waf.x,pf0[v]); pf1[v]=fmaf(h,waf.y,pf1[v]);
            qf0[v]=fmaf(h,wbf.x,qf0[v]); qf1[v]=fmaf(h,wbf.y,qf1[v]);
        }
    }
    #pragma unroll
    for(int v=0;v<8;v++) if(val[v]){
        int n = nid[v];
        g_Pt[n*L+c0]=pt0[v]; g_Pt[n*L+c0+1]=pt1[v];
        g_Qt[n*L+c0]=qt0[v]; g_Qt[n*L+c0+1]=qt1[v];
        g_Pf[n*L+c0]=pf0[v]; g_Pf[n*L+c0+1]=pf1[v];
        g_Qf[n*L+c0]=qf0[v]; g_Qf[n*L+c0+1]=qf1[v];
    }
}

// ---------------- edge aggregation + W2 fold (R9 champion version) ----------------
__global__ __launch_bounds__(256) void k_aggr(
        const int* __restrict__ colptr, const float4* __restrict__ colE4,
        const int* __restrict__ rowptr, const float4* __restrict__ rowE4,
        const float* __restrict__ Pt, const float* __restrict__ Qt,
        const float* __restrict__ Pf, const float* __restrict__ Qf,
        const float* __restrict__ ptW1, const float* __restrict__ ptb2, const float* __restrict__ ptW2,
        const float* __restrict__ pfW1, const float* __restrict__ pfb2, const float* __restrict__ pfW2,
        float* __restrict__ mt, float* __restrict__ mf){
    bool toDir = (blockIdx.x < NB32);
    int bb = toDir ? blockIdx.x : blockIdx.x - NB32;
    if(bb*32 >= g_ndcount) return;
    __shared__ float sW2[L*L];
    __shared__ float sWe[3*L];
    __shared__ float sS[8][4][L];
    const int*    ptr = toDir ? colptr : rowptr;
    const float4* e4  = toDir ? colE4  : rowE4;
    const float*  P   = toDir ? Pt     : Pf;
    const float*  Q   = toDir ? Qt     : Qf;
    const float*  W1  = toDir ? ptW1   : pfW1;
    const float*  b2  = toDir ? ptb2   : pfb2;
    const float*  W2  = toDir ? ptW2   : pfW2;
    float*        out = toDir ? mt     : mf;
    int tid = threadIdx.x;
    for(int i=tid;i<L*L/4;i+=256) ((float4*)sW2)[i] = ((const float4*)W2)[i];
    for(int i=tid;i<3*L;i+=256) sWe[i] = W1[2*L*L + i];
    __syncthreads();
    int lane = tid&31, w = tid>>5, c0 = 2*lane;
    int sb = bb*32 + w*4;
    float we0a=sWe[c0],     we0b=sWe[c0+1];
    float we1a=sWe[L+c0],   we1b=sWe[L+c0+1];
    float we2a=sWe[2*L+c0], we2b=sWe[2*L+c0+1];
    float degv[4]; bool val[4]; int nid[4];
    #pragma unroll
    for(int v=0;v<4;v++){
        int slot = sb+v;
        val[v] = (slot < g_ndcount);
        int n = val[v]? g_nd[slot] : 0;
        nid[v] = n;
        float acc0=0.f, acc1=0.f; int cnt=0;
        if(val[v]){
            float base0 = P[n*L+c0], base1 = P[n*L+c0+1];
            int s = ptr[n], e = ptr[n+1];
            for(int p=s; p<e; p++){
                float4 E = e4[p];
                int j = __float_as_int(E.w);
                if(j == n) continue;
                cnt++;
                float2 qv = *(const float2*)&Q[j*L+c0];
                float pre0 = base0 + qv.x + E.x*we0a + E.y*we1a + E.z*we2a;
                float pre1 = base1 + qv.y + E.x*we0b + E.y*we1b + E.z*we2b;
                acc0 += fmaxf(pre0, 0.f);
                acc1 += fmaxf(pre1, 0.f);
            }
        }
        sS[w][v][c0]=acc0; sS[w][v][c0+1]=acc1; degv[v]=(float)cnt;
    }
    __syncwarp();
    float b2a=b2[c0], b2b=b2[c0+1];
    float o0[4],o1[4];
    #pragma unroll
    for(int v=0;v<4;v++){ o0[v]=degv[v]*b2a; o1[v]=degv[v]*b2b; }
    for(int k=0;k<L;k++){
        float2 wv = *(const float2*)&sW2[k*L+c0];
        #pragma unroll
        for(int v=0;v<4;v++){ float s=sS[w][v][k]; o0[v]=fmaf(s,wv.x,o0[v]); o1[v]=fmaf(s,wv.y,o1[v]); }
    }
    #pragma unroll
    for(int v=0;v<4;v++) if(val[v]){
        int n = nid[v];
        out[n*L+c0]=o0[v]; out[n*L+c0+1]=o1[v];
    }
}

// ---------------- gates: 48 nodes/block, 2-chunk weight streaming -> 2 blocks/SM ----------------
#define KC1 98
#define GATE_SMEM ((GN*196 + 3*KC1*L)*4)
__global__ __launch_bounds__(256) void k_gate(
        const float* __restrict__ prb,
        const float* __restrict__ zkW, const float* __restrict__ zkb,
        const float* __restrict__ rkW, const float* __restrict__ rkb,
        const float* __restrict__ cW,  const float* __restrict__ cb){
    if(blockIdx.x*GN >= g_ndcount) return;
    extern __shared__ float sm[];
    float* stgA = sm;                  // [48][196]
    float* Wz   = sm + GN*196;         // [98][64]
    float* Wr   = Wz + KC1*L;
    float* Wc   = Wr + KC1*L;
    __shared__ float szb[L], srb[L], scb[L];
    int tid = threadIdx.x;
    if(tid<L){ szb[tid]=zkb[tid]; srb[tid]=rkb[tid]; scb[tid]=cb[tid]; }
    int lane = tid&31, w = tid>>5, c0 = 2*lane;
    int i0 = w*6, sb = blockIdx.x*GN + i0;
    int nid[6]; bool val[6];
    #pragma unroll
    for(int v=0;v<6;v++){
        int slot = sb+v; val[v] = (slot < g_ndcount);
        int n = val[v]? g_nd[slot] : 0; nid[v] = n;
        float* A = stgA + (i0+v)*196;
        if(val[v]){
            *(float2*)&A[c0]     = *(const float2*)&g_H [n*L+c0];
            *(float2*)&A[64+c0]  = *(const float2*)&g_mt[n*L+c0];
            *(float2*)&A[128+c0] = *(const float2*)&g_mf[n*L+c0];
            if(lane==0){ A[192]=prb[2*n]; A[193]=prb[2*n+1]; }
        } else {
            *(float2*)&A[c0]     = make_float2(0.f,0.f);
            *(float2*)&A[64+c0]  = make_float2(0.f,0.f);
            *(float2*)&A[128+c0] = make_float2(0.f,0.f);
            if(lane==0){ A[192]=0.f; A[193]=0.f; }
        }
    }
    // load chunk 1 (rows 0..97)
    __syncthreads();
    for(int i=tid;i<KC1*L/4;i+=256){
        ((float4*)Wz)[i] = ((const float4*)zkW)[i];
        ((float4*)Wr)[i] = ((const float4*)rkW)[i];
        ((float4*)Wc)[i] = ((const float4*)cW)[i];
    }
    __syncthreads();
    float az0[6],az1[6],ar0[6],ar1[6],ac0[6],ac1[6];
    #pragma unroll
    for(int v=0;v<6;v++){ az0[v]=0.f; az1[v]=0.f; ar0[v]=0.f; ar1[v]=0.f; ac0[v]=0.f; ac1[v]=0.f; }
    for(int k=0;k<64;k++){
        float2 wz = *(const float2*)&Wz[k*L+c0];
        float2 wr = *(const float2*)&Wr[k*L+c0];
        #pragma unroll
        for(int v=0;v<6;v++){
            float cv = stgA[(i0+v)*196 + k];
            az0[v]=fmaf(cv,wz.x,az0[v]); az1[v]=fmaf(cv,wz.y,az1[v]);
            ar0[v]=fmaf(cv,wr.x,ar0[v]); ar1[v]=fmaf(cv,wr.y,ar1[v]);
        }
    }
    for(int k=64;k<KC1;k++){
        float2 wz = *(const float2*)&Wz[k*L+c0];
        float2 wr = *(const float2*)&Wr[k*L+c0];
        float2 wc = *(const float2*)&Wc[k*L+c0];
        #pragma unroll
        for(int v=0;v<6;v++){
            float cv = stgA[(i0+v)*196 + k];
            az0[v]=fmaf(cv,wz.x,az0[v]); az1[v]=fmaf(cv,wz.y,az1[v]);
            ar0[v]=fmaf(cv,wr.x,ar0[v]); ar1[v]=fmaf(cv,wr.y,ar1[v]);
            ac0[v]=fmaf(cv,wc.x,ac0[v]); ac1[v]=fmaf(cv,wc.y,ac1[v]);
        }
    }
    // load chunk 2 (rows 98..193)
    __syncthreads();
    for(int i=tid;i<(194-KC1)*L/4;i+=256){
        ((float4*)Wz)[i] = ((const float4*)(zkW+KC1*L))[i];
        ((float4*)Wr)[i] = ((const float4*)(rkW+KC1*L))[i];
        ((float4*)Wc)[i] = ((const float4*)(cW +KC1*L))[i];
    }
    __syncthreads();
    for(int k=KC1;k<194;k++){
        int kk = k - KC1;
        float2 wz = *(const float2*)&Wz[kk*L+c0];
        float2 wr = *(const float2*)&Wr[kk*L+c0];
        float2 wc = *(const float2*)&Wc[kk*L+c0];
        #pragma unroll
        for(int v=0;v<6;v++){
            float cv = stgA[(i0+v)*196 + k];
            az0[v]=fmaf(cv,wz.x,az0[v]); az1[v]=fmaf(cv,wz.y,az1[v]);
            ar0[v]=fmaf(cv,wr.x,ar0[v]); ar1[v]=fmaf(cv,wr.y,ar1[v]);
            ac0[v]=fmaf(cv,wc.x,ac0[v]); ac1[v]=fmaf(cv,wc.y,ac1[v]);
        }
    }
    // phase 3: overlay r-values + cW[0:64) into the weight region
    __syncthreads();
    float* stgB  = Wz;            // [48][64]
    float* scwlo = Wz + GN*L;     // [64][64]
    for(int i=tid;i<L*L/4;i+=256)
        ((float4*)scwlo)[i] = ((const float4*)cW)[i];
    float z0[6],z1[6];
    #pragma unroll
    for(int v=0;v<6;v++){
        z0[v]=sigf(az0[v]+szb[c0]); z1[v]=sigf(az1[v]+szb[c0+1]);
        float rr0=sigf(ar0[v]+srb[c0]), rr1=sigf(ar1[v]+srb[c0+1]);
        stgB[(i0+v)*L+c0]=rr0; stgB[(i0+v)*L+c0+1]=rr1;
    }
    __syncthreads();
    for(int k=0;k<64;k++){
        float2 wc = *(const float2*)&scwlo[k*L+c0];
        #pragma unroll
        for(int v=0;v<6;v++){
            float rh = stgB[(i0+v)*L+k] * stgA[(i0+v)*196+k];
            ac0[v]=fmaf(rh,wc.x,ac0[v]); ac1[v]=fmaf(rh,wc.y,ac1[v]);
        }
    }
    #pragma unroll
    for(int v=0;v<6;v++) if(val[v]){
        int n = nid[v];
        float* A = stgA + (i0+v)*196;
        float co0 = tanhf(ac0[v]+scb[c0]);
        float co1 = tanhf(ac1[v]+scb[c0+1]);
        float hn0 = A[c0]   + z0[v]*co0;
        float hn1 = A[c0+1] + z1[v]*co1;
        g_H[n*L+c0]   = hn0;
        g_H[n*L+c0+1] = hn1;
    }
}

// ---------------- decode + enc/autoenc losses over a node list (R9 champion version) ----------------
#define DEC_SMEM (3*64*L*4)
__global__ __launch_bounds__(256) void k_decode(
        int mode, float lossW,
        const float* __restrict__ dW1, const float* __restrict__ db1,
        const float* __restrict__ dW2, const float* __restrict__ db2,
        const float* __restrict__ eW1, const float* __restrict__ eb1,
        const float* __restrict__ eW2, const float* __restrict__ eb2){
    int cnt = mode ? g_ndcount : g_drcount;
    if(blockIdx.x*64 >= cnt) return;
    const int* list = mode ? g_nd : g_dr;
    extern __shared__ float sm[];
    float* sHn = sm;
    float* sB  = sm + 64*L;
    float* sE  = sm + 2*64*L;
    __shared__ float sdW2[L], sdb1[L], sE1[L], sEb1[L], sEb2[L];
    __shared__ double red[8];
    int tid = threadIdx.x;
    if(tid<L){ sdW2[tid]=dW2[tid]; sdb1[tid]=db1[tid]; sE1[tid]=eW1[tid];
               sEb1[tid]=eb1[tid]; sEb2[tid]=eb2[tid]; }
    __syncthreads();
    int lane = tid&31, w = tid>>5, c0 = 2*lane;
    int i0 = w*8, sb = blockIdx.x*64 + i0;
    float db2v = db2[0];
    int nid[8]; bool val[8];
    #pragma unroll
    for(int v=0;v<8;v++){
        int slot = sb+v; val[v] = (slot < cnt);
        nid[v] = val[v]? list[slot] : 0;
        float2 h = val[v]? *(const float2*)&g_H[nid[v]*L+c0] : make_float2(0.f,0.f);
        *(float2*)&sHn[(i0+v)*L+c0] = h;
    }
    __syncwarp();
    float ad0[8],ad1[8];
    #pragma unroll
    for(int v=0;v<8;v++){ ad0[v]=sdb1[c0]; ad1[v]=sdb1[c0+1]; }
    for(int k=0;k<L;k++){
        float2 wd = __ldg((const float2*)&dW1[k*L+c0]);
        #pragma unroll
        for(int v=0;v<8;v++){
            float hk = sHn[(i0+v)*L+k];
            ad0[v]=fmaf(hk,wd.x,ad0[v]); ad1[v]=fmaf(hk,wd.y,ad1[v]);
        }
    }
    float Uv[8];
    #pragma unroll
    for(int v=0;v<8;v++){
        float pu = fmaxf(ad0[v],0.f)*sdW2[c0] + fmaxf(ad1[v],0.f)*sdW2[c0+1];
        for(int o=16;o;o>>=1) pu += __shfl_xor_sync(0xffffffffu, pu, o);
        Uv[v] = pu + db2v;
        if(val[v] && lane==0) g_U[nid[v]] = Uv[v];
        float eh0 = fmaxf(fmaf(Uv[v],sE1[c0],sEb1[c0]),0.f);
        float eh1 = fmaxf(fmaf(Uv[v],sE1[c0+1],sEb1[c0+1]),0.f);
        sB[(i0+v)*L+c0]=eh0; sB[(i0+v)*L+c0+1]=eh1;
    }
    __syncwarp();
    float ae0[8],ae1[8];
    #pragma unroll
    for(int v=0;v<8;v++){ ae0[v]=sEb2[c0]; ae1[v]=sEb2[c0+1]; }
    for(int k=0;k<L;k++){
        float2 we = __ldg((const float2*)&eW2[k*L+c0]);
        #pragma unroll
        for(int v=0;v<8;v++){
            float ek = sB[(i0+v)*L+k];
            ae0[v]=fmaf(ek,we.x,ae0[v]); ae1[v]=fmaf(ek,we.y,ae1[v]);
        }
    }
    float encS = 0.f;
    #pragma unroll
    for(int v=0;v<8;v++){
        if(val[v]){
            float d0 = ae0[v]-sHn[(i0+v)*L+c0], d1 = ae1[v]-sHn[(i0+v)*L+c0+1];
            encS += d0*d0 + d1*d1;
        }
        sE[(i0+v)*L+c0]=ae0[v]; sE[(i0+v)*L+c0+1]=ae1[v];
    }
    __syncwarp();
    float ag0[8],ag1[8];
    #pragma unroll
    for(int v=0;v<8;v++){ ag0[v]=sdb1[c0]; ag1[v]=sdb1[c0+1]; }
    for(int k=0;k<L;k++){
        float2 wd = __ldg((const float2*)&dW1[k*L+c0]);
        #pragma unroll
        for(int v=0;v<8;v++){
            float ek = sE[(i0+v)*L+k];
            ag0[v]=fmaf(ek,wd.x,ag0[v]); ag1[v]=fmaf(ek,wd.y,ag1[v]);
        }
    }
    float autoS = 0.f;
    #pragma unroll
    for(int v=0;v<8;v++){
        float pa = fmaxf(ag0[v],0.f)*sdW2[c0] + fmaxf(ag1[v],0.f)*sdW2[c0+1];
        for(int o=16;o;o>>=1) pa += __shfl_xor_sync(0xffffffffu, pa, o);
        float aout = pa + db2v;
        if(val[v] && lane==0){ float d = aout - Uv[v]; autoS += d*d; }
    }
    float tot = encS;
    for(int o=16;o;o>>=1) tot += __shfl_xor_sync(0xffffffffu, tot, o);
    float at = autoS;
    for(int o=16;o;o>>=1) at += __shfl_xor_sync(0xffffffffu, at, o);
    if(lane==0) red[w] = (double)lossW * ((double)tot/((double)NN*64.0) + (double)at/(double)NN);
    __syncthreads();
    if(tid==0){
        double s = 0.0;
        for(int i=0;i<8;i++) s += red[i];
        atomicAdd(&g_loss, s);
    }
}

// ---------------- residual loss (rowJ/rowA: 8B/edge) ----------------
__global__ __launch_bounds__(256) void k_res(const float* __restrict__ y, float wgt){
    __shared__ double red[8];
    int lane = threadIdx.x&31, w = threadIdx.x>>5;
    int wid = blockIdx.x*8 + w;
    int nwarps = gridDim.x*8;
    float ls = 0.f;
    for(int n = wid; n < NN; n += nwarps){
        int s = g_rowptr[n], e = g_rowptr[n+1];
        float part = 0.f;
        for(int p = s+lane; p < e; p += 32){
            part += g_rowA[p] * g_U[g_rowJ[p]];
        }
        for(int o=16;o;o>>=1) part += __shfl_xor_sync(0xffffffffu, part, o);
        if(lane==0){ float d = part - y[n]; ls += d*d; }
    }
    for(int o=16;o;o>>=1) ls += __shfl_xor_sync(0xffffffffu, ls, o);
    if(lane==0) red[w] = (double)ls;
    __syncthreads();
    if(threadIdx.x==0){
        double s=0.0; for(int i=0;i<8;i++) s+=red[i];
        atomicAdd(&g_loss, s * (double)wgt / (double)NN);
    }
}

// ---------------- finalize + reset state for next replay ----------------
__global__ void k_fin(float* __restrict__ out, int out_size){
    int i = blockIdx.x*blockDim.x + threadIdx.x;
    if(i < NN && i < out_size) out[i] = g_U[i];
    if(i == NN){
        if(i < out_size) out[NN] = (float)g_loss;
        g_loss = 0.0;
    }
    if(i < NN){ g_cntr[i]=0; g_cntc[i]=0; }
}

extern "C" void kernel_launch(void* const* d_in, const int* in_sizes, int n_in,
                              void* d_out, int out_size){
    const float* x    = (const float*)d_in[0];
    const float* y    = (const float*)d_in[2];
    const int*   tags = (const int*)  d_in[3];
    const int*   ei   = (const int*)  d_in[4];
    const float* ea   = (const float*)d_in[5];
    const float* aij  = (const float*)d_in[6];
    const float* prb  = (const float*)d_in[7];
    const float* ptW1 = (const float*)d_in[8];
    const float* ptb1 = (const float*)d_in[9];
    const float* ptW2 = (const float*)d_in[10];
    const float* ptb2 = (const float*)d_in[11];
    const float* pfW1 = (const float*)d_in[12];
    const float* pfb1 = (const float*)d_in[13];
    const float* pfW2 = (const float*)d_in[14];
    const float* pfb2 = (const float*)d_in[15];
    const float* zkW  = (const float*)d_in[16];
    const float* zkb  = (const float*)d_in[17];
    const float* rkW  = (const float*)d_in[18];
    const float* rkb  = (const float*)d_in[19];
    const float* cW   = (const float*)d_in[20];
    const float* cb   = (const float*)d_in[21];
    const float* eW1  = (const float*)d_in[22];
    const float* eb1  = (const float*)d_in[23];
    const float* eW2  = (const float*)d_in[24];
    const float* eb2  = (const float*)d_in[25];
    const float* dW1  = (const float*)d_in[26];
    const float* db1  = (const float*)d_in[27];
    const float* dW2  = (const float*)d_in[28];
    const float* db2  = (const float*)d_in[29];

    cudaFuncSetAttribute(k_prep,   cudaFuncAttributeMaxDynamicSharedMemorySize, PREP_SMEM);
    cudaFuncSetAttribute(k_gate,   cudaFuncAttributeMaxDynamicSharedMemorySize, GATE_SMEM);
    cudaFuncSetAttribute(k_decode, cudaFuncAttributeMaxDynamicSharedMemorySize, DEC_SMEM);

    int *rowptr, *colptr;
    float4 *rowE4, *colE4;
    float *Pt, *Qt, *Pf, *Qf, *mt, *mf;
    cudaGetSymbolAddress((void**)&rowptr, g_rowptr);
    cudaGetSymbolAddress((void**)&colptr, g_colptr);
    cudaGetSymbolAddress((void**)&rowE4,  g_rowE4);
    cudaGetSymbolAddress((void**)&colE4,  g_colE4);
    cudaGetSymbolAddress((void**)&Pt, g_Pt);
    cudaGetSymbolAddress((void**)&Qt, g_Qt);
    cudaGetSymbolAddress((void**)&Pf, g_Pf);
    cudaGetSymbolAddress((void**)&Qf, g_Qf);
    cudaGetSymbolAddress((void**)&mt, g_mt);
    cudaGetSymbolAddress((void**)&mf, g_mf);

    k_enc0<<<NB32, 256>>>(x, eW1, eb1, eW2, eb2);                        // 0
    k_hist<<<(NE+255)/256, 256>>>(ei);                                   // 1
    k_scanA<<<SBLK, 256>>>(tags);                                        // 2
    k_prep<<<NB64, 256, PREP_SMEM>>>(ptW1, ptb1, pfW1, pfb1, 0);         // 3 (profiled control)
    k_scanB<<<1, 256>>>();                                               // 4
    k_scanC<<<SBLK, 256>>>(tags);                                        // 5
    k_scatter<<<(NE+255)/256, 256>>>(ei, ea, aij);                       // 6
    // Dirichlet nodes: losses identical both steps -> once, weight 2
    k_decode<<<NB64, 256, DEC_SMEM>>>(0, 2.0f, dW1, db1, dW2, db2, eW1, eb1, eW2, eb2);

    const float gammaw[2] = {0.9f, 1.0f};
    for(int step=0; step<2; step++){
        k_aggr<<<2*NB32, 256>>>(colptr, colE4, rowptr, rowE4,
                                Pt, Qt, Pf, Qf,
                                ptW1, ptb2, ptW2, pfW1, pfb2, pfW2, mt, mf);
        k_gate<<<NBG, 256, GATE_SMEM>>>(prb, zkW, zkb, rkW, rkb, cW, cb);
        k_decode<<<NB64, 256, DEC_SMEM>>>(1, 1.0f, dW1, db1, dW2, db2, eW1, eb1, eW2, eb2);
        k_res<<<NB32, 256>>>(y, gammaw[step]);
        if(step == 0)
            k_prep<<<NB64, 256, PREP_SMEM>>>(ptW1, ptb1, pfW1, pfb1, 1);
    }
    k_fin<<<(NN+256)/256, 256>>>((float*)d_out, out_size);
}

// round 16
// speedup vs baseline: 1.6014x; 1.0973x over previous
#include <cuda_runtime.h>
#include <cuda_fp16.h>
#include <math.h>

#define NN 50000
#define NE 800000
#define L  64
#define NB32 ((NN + 31) / 32)
#define NB64 ((NN + 63) / 64)
#define SBLK ((NN + 255) / 256)
#define GN   48
#define NBG  ((NN + GN - 1) / GN)

// ------------- device scratch (statics zero-initialized; k_fin re-zeroes) -------------
__device__ float   g_H [NN*L];
__device__ float   g_H0[NN*L];
__device__ float   g_Pt[NN*L];
__device__ float   g_Pf[NN*L];
__device__ __half2 g_Qt16[NN*32];
__device__ __half2 g_Qf16[NN*32];
__device__ float   g_mt[NN*L];
__device__ float   g_mf[NN*L];
__device__ float   g_U [NN];
__device__ int     g_rowptr[NN+1];
__device__ int     g_colptr[NN+1];
__device__ int     g_cntr[NN];
__device__ int     g_cntc[NN];
__device__ int     g_nd[NN];
__device__ int     g_dr[NN];
__device__ int     g_ndcount;
__device__ int     g_drcount;
__device__ int     g_partR[256], g_partC[256], g_partN[256];
__device__ int     g_baseR[256], g_baseC[256], g_baseN[256];
__device__ float4  g_rowE4[NE];
__device__ float4  g_colE4[NE];
__device__ float   g_rowA[NE];
__device__ int     g_rowJ[NE];
__device__ double  g_loss;

__device__ __forceinline__ float sigf(float v){ return 1.f/(1.f+__expf(-v)); }

// ---------------- CSR build ----------------
__global__ void k_hist(const int* __restrict__ ei){
    int e = blockIdx.x*blockDim.x + threadIdx.x;
    if(e < NE){
        atomicAdd(&g_cntr[ei[e]], 1);
        atomicAdd(&g_cntc[ei[NE+e]], 1);
    }
}

// phase A: per-block sums
__global__ __launch_bounds__(256) void k_scanA(const int* __restrict__ tags){
    __shared__ int sR[256], sC[256], sN[256];
    int tid = threadIdx.x;
    int t = blockIdx.x*256 + tid;
    int cr=0, cc=0, nd=0;
    if(t < NN){ cr = g_cntr[t]; cc = g_cntc[t]; nd = (tags[t]!=1); }
    sR[tid]=cr; sC[tid]=cc; sN[tid]=nd;
    __syncthreads();
    for(int off=128; off; off>>=1){
        if(tid < off){ sR[tid]+=sR[tid+off]; sC[tid]+=sC[tid+off]; sN[tid]+=sN[tid+off]; }
        __syncthreads();
    }
    if(tid==0){ g_partR[blockIdx.x]=sR[0]; g_partC[blockIdx.x]=sC[0]; g_partN[blockIdx.x]=sN[0]; }
}

// phase B: scan partials (1 small block)
__global__ __launch_bounds__(256) void k_scanB(){
    __shared__ int sR[256], sC[256], sN[256];
    int i = threadIdx.x;
    int vR = (i<SBLK)? g_partR[i] : 0;
    int vC = (i<SBLK)? g_partC[i] : 0;
    int vN = (i<SBLK)? g_partN[i] : 0;
    sR[i]=vR; sC[i]=vC; sN[i]=vN;
    __syncthreads();
    for(int off=1; off<256; off<<=1){
        int aR=0,aC=0,aN=0;
        if(i>=off){ aR=sR[i-off]; aC=sC[i-off]; aN=sN[i-off]; }
        __syncthreads();
        sR[i]+=aR; sC[i]+=aC; sN[i]+=aN;
        __syncthreads();
    }
    if(i<SBLK){
        g_baseR[i] = sR[i]-vR;   // exclusive
        g_baseC[i] = sC[i]-vC;
        g_baseN[i] = sN[i]-vN;
    }
    if(i==0){
        int totR = sR[SBLK-1], totC = sC[SBLK-1], totN = sN[SBLK-1];
        g_rowptr[NN] = totR;
        g_colptr[NN] = totC;
        g_ndcount = totN;
        g_drcount = NN - totN;
    }
}

// phase C: intra-block scan, write ptrs, zero counters, compact nd/dr
__global__ __launch_bounds__(256) void k_scanC(const int* __restrict__ tags){
    __shared__ int sR[256], sC[256], sN[256];
    int tid = threadIdx.x;
    int t = blockIdx.x*256 + tid;
    int cr=0, cc=0, nd=0;
    if(t < NN){ cr = g_cntr[t]; cc = g_cntc[t]; nd = (tags[t]!=1); }
    sR[tid]=cr; sC[tid]=cc; sN[tid]=nd;
    __syncthreads();
    for(int off=1; off<256; off<<=1){
        int aR=0,aC=0,aN=0;
        if(tid>=off){ aR=sR[tid-off]; aC=sC[tid-off]; aN=sN[tid-off]; }
        __syncthreads();
        sR[tid]+=aR; sC[tid]+=aC; sN[tid]+=aN;
        __syncthreads();
    }
    if(t < NN){
        int exR = sR[tid]-cr, exC = sC[tid]-cc, exN = sN[tid]-nd;
        g_rowptr[t] = g_baseR[blockIdx.x] + exR;
        g_colptr[t] = g_baseC[blockIdx.x] + exC;
        g_cntr[t] = 0; g_cntc[t] = 0;
        int ndpos = g_baseN[blockIdx.x] + exN;
        if(nd) g_nd[ndpos] = t;
        else   g_dr[t - ndpos] = t;
    }
}

__global__ void k_scatter(const int* __restrict__ ei, const float* __restrict__ ea,
                          const float* __restrict__ aij){
    int e = blockIdx.x*blockDim.x + threadIdx.x;
    if(e >= NE) return;
    int r = ei[e], c = ei[NE+e];
    float a0 = ea[3*e], a1 = ea[3*e+1], a2 = ea[3*e+2];
    int pr = atomicAdd(&g_cntr[r], 1);
    int p  = g_rowptr[r] + pr;
    g_rowE4[p] = make_float4(a0,a1,a2,__int_as_float(c));
    g_rowA[p]  = aij[e];
    g_rowJ[p]  = c;
    int pc = atomicAdd(&g_cntc[c], 1);
    int q  = g_colptr[c] + pc;
    g_colE4[q] = make_float4(a0,a1,a2,__int_as_float(r));
}

// ---------------- encoder: x -> H0, H ----------------
__global__ __launch_bounds__(256) void k_enc0(const float* __restrict__ x,
        const float* __restrict__ eW1, const float* __restrict__ eb1,
        const float* __restrict__ eW2, const float* __restrict__ eb2){
    __shared__ float sW[L*L];
    __shared__ float sh[8][4][L];
    int tid = threadIdx.x;
    for(int i=tid;i<L*L/4;i+=256) ((float4*)sW)[i] = ((const float4*)eW2)[i];
    __syncthreads();
    int lane = tid&31, w = tid>>5, c0 = 2*lane;
    int nb = blockIdx.x*32 + w*4;
    float w1a=eW1[c0], w1b=eW1[c0+1], b1a=eb1[c0], b1b=eb1[c0+1];
    float b2a=eb2[c0], b2b=eb2[c0+1];
    bool val[4];
    #pragma unroll
    for(int v=0;v<4;v++){
        int n = nb+v; val[v] = (n<NN);
        float xv = val[v]? x[n] : 0.f;
        sh[w][v][c0]   = fmaxf(fmaf(xv,w1a,b1a),0.f);
        sh[w][v][c0+1] = fmaxf(fmaf(xv,w1b,b1b),0.f);
    }
    __syncwarp();
    float a0[4]={b2a,b2a,b2a,b2a}, a1[4]={b2b,b2b,b2b,b2b};
    for(int k=0;k<L;k++){
        float2 wv = *(const float2*)&sW[k*L+c0];
        #pragma unroll
        for(int v=0;v<4;v++){ float s=sh[w][v][k]; a0[v]=fmaf(s,wv.x,a0[v]); a1[v]=fmaf(s,wv.y,a1[v]); }
    }
    #pragma unroll
    for(int v=0;v<4;v++) if(val[v]){
        int n = nb+v;
        g_H0[n*L+c0]=a0[v]; g_H0[n*L+c0+1]=a1[v];
        g_H [n*L+c0]=a0[v]; g_H [n*L+c0+1]=a1[v];
    }
}

// ---------------- P/Q precompute (both phis), 8 nodes/warp; Q stored as half2 ----------------
#define PREP_SMEM ((4*L*L + 64*L)*4)
__global__ __launch_bounds__(256) void k_prep(
        const float* __restrict__ ptW1, const float* __restrict__ ptb1,
        const float* __restrict__ pfW1, const float* __restrict__ pfb1,
        int use_perm){
    if(use_perm && blockIdx.x*64 >= g_ndcount) return;
    extern __shared__ float sm[];
    float* Wat = sm;
    float* Wbt = sm + L*L;
    float* Waf = sm + 2*L*L;
    float* Wbf = sm + 3*L*L;
    float* stg = sm + 4*L*L;
    int tid = threadIdx.x;
    for(int i=tid;i<L*L/4;i+=256){
        ((float4*)Wat)[i] = ((const float4*)ptW1)[i];
        ((float4*)Wbt)[i] = ((const float4*)(ptW1+L*L))[i];
        ((float4*)Waf)[i] = ((const float4*)pfW1)[i];
        ((float4*)Wbf)[i] = ((const float4*)(pfW1+L*L))[i];
    }
    int lane = tid&31, w = tid>>5, c0 = 2*lane;
    int i0 = w*8, sb = blockIdx.x*64 + i0;
    int nid[8]; bool val[8];
    #pragma unroll
    for(int v=0;v<8;v++){
        int slot = sb+v;
        if(use_perm){ val[v] = (slot < g_ndcount); nid[v] = val[v]? g_nd[slot] : 0; }
        else        { val[v] = (slot < NN);        nid[v] = slot; }
        float2 h = val[v]? *(const float2*)&g_H[nid[v]*L+c0] : make_float2(0.f,0.f);
        *(float2*)&stg[(i0+v)*L+c0] = h;
    }
    __syncthreads();
    float pt0[8],pt1[8],qt0[8],qt1[8],pf0[8],pf1[8],qf0[8],qf1[8];
    float bt0=ptb1[c0], bt1=ptb1[c0+1], bf0=pfb1[c0], bf1=pfb1[c0+1];
    #pragma unroll
    for(int v=0;v<8;v++){ pt0[v]=bt0; pt1[v]=bt1; pf0[v]=bf0; pf1[v]=bf1;
                          qt0[v]=0.f; qt1[v]=0.f; qf0[v]=0.f; qf1[v]=0.f; }
    for(int k=0;k<L;k++){
        float2 wat = *(const float2*)&Wat[k*L+c0];
        float2 wbt = *(const float2*)&Wbt[k*L+c0];
        float2 waf = *(const float2*)&Waf[k*L+c0];
        float2 wbf = *(const float2*)&Wbf[k*L+c0];
        #pragma unroll
        for(int v=0;v<8;v++){
            float h = stg[(i0+v)*L + k];
            pt0[v]=fmaf(h,wat.x,pt0[v]); pt1[v]=fmaf(h,wat.y,pt1[v]);
            qt0[v]=fmaf(h,wbt.x,qt0[v]); qt1[v]=fmaf(h,wbt.y,qt1[v]);
            pf0[v]=fmaf(h,waf.x,pf0[v]); pf1[v]=fmaf(h,waf.y,pf1[v]);
            qf0[v]=fmaf(h,wbf.x,qf0[v]); qf1[v]=fmaf(h,wbf.y,qf1[v]);
        }
    }
    #pragma unroll
    for(int v=0;v<8;v++) if(val[v]){
        int n = nid[v];
        g_Pt[n*L+c0]=pt0[v]; g_Pt[n*L+c0+1]=pt1[v];
        g_Pf[n*L+c0]=pf0[v]; g_Pf[n*L+c0+1]=pf1[v];
        g_Qt16[n*32+lane] = __floats2half2_rn(qt0[v], qt1[v]);
        g_Qf16[n*32+lane] = __floats2half2_rn(qf0[v], qf1[v]);
    }
}

// ---------------- edge aggregation + W2 fold; Q gathered as half2 (halved traffic) ----------------
__global__ __launch_bounds__(256) void k_aggr(
        const int* __restrict__ colptr, const float4* __restrict__ colE4,
        const int* __restrict__ rowptr, const float4* __restrict__ rowE4,
        const float* __restrict__ Pt, const __half2* __restrict__ Qt,
        const float* __restrict__ Pf, const __half2* __restrict__ Qf,
        const float* __restrict__ ptW1, const float* __restrict__ ptb2, const float* __restrict__ ptW2,
        const float* __restrict__ pfW1, const float* __restrict__ pfb2, const float* __restrict__ pfW2,
        float* __restrict__ mt, float* __restrict__ mf){
    bool toDir = (blockIdx.x < NB32);
    int bb = toDir ? blockIdx.x : blockIdx.x - NB32;
    if(bb*32 >= g_ndcount) return;
    __shared__ float sW2[L*L];
    __shared__ float sWe[3*L];
    __shared__ float sS[8][4][L];
    const int*     ptr = toDir ? colptr : rowptr;
    const float4*  e4  = toDir ? colE4  : rowE4;
    const float*   P   = toDir ? Pt     : Pf;
    const __half2* Q   = toDir ? Qt     : Qf;
    const float*   W1  = toDir ? ptW1   : pfW1;
    const float*   b2  = toDir ? ptb2   : pfb2;
    const float*   W2  = toDir ? ptW2   : pfW2;
    float*         out = toDir ? mt     : mf;
    int tid = threadIdx.x;
    for(int i=tid;i<L*L/4;i+=256) ((float4*)sW2)[i] = ((const float4*)W2)[i];
    for(int i=tid;i<3*L;i+=256) sWe[i] = W1[2*L*L + i];
    __syncthreads();
    int lane = tid&31, w = tid>>5, c0 = 2*lane;
    int sb = bb*32 + w*4;
    float we0a=sWe[c0],     we0b=sWe[c0+1];
    float we1a=sWe[L+c0],   we1b=sWe[L+c0+1];
    float we2a=sWe[2*L+c0], we2b=sWe[2*L+c0+1];
    float degv[4]; bool val[4]; int nid[4];
    #pragma unroll
    for(int v=0;v<4;v++){
        int slot = sb+v;
        val[v] = (slot < g_ndcount);
        int n = val[v]? g_nd[slot] : 0;
        nid[v] = n;
        float acc0=0.f, acc1=0.f; int cnt=0;
        if(val[v]){
            float base0 = P[n*L+c0], base1 = P[n*L+c0+1];
            int s = ptr[n], e = ptr[n+1];
            for(int p=s; p<e; p++){
                float4 E = e4[p];
                int j = __float_as_int(E.w);
                if(j == n) continue;
                cnt++;
                float2 qv = __half22float2(Q[j*32+lane]);
                float pre0 = base0 + qv.x + E.x*we0a + E.y*we1a + E.z*we2a;
                float pre1 = base1 + qv.y + E.x*we0b + E.y*we1b + E.z*we2b;
                acc0 += fmaxf(pre0, 0.f);
                acc1 += fmaxf(pre1, 0.f);
            }
        }
        sS[w][v][c0]=acc0; sS[w][v][c0+1]=acc1; degv[v]=(float)cnt;
    }
    __syncwarp();
    float b2a=b2[c0], b2b=b2[c0+1];
    float o0[4],o1[4];
    #pragma unroll
    for(int v=0;v<4;v++){ o0[v]=degv[v]*b2a; o1[v]=degv[v]*b2b; }
    for(int k=0;k<L;k++){
        float2 wv = *(const float2*)&sW2[k*L+c0];
        #pragma unroll
        for(int v=0;v<4;v++){ float s=sS[w][v][k]; o0[v]=fmaf(s,wv.x,o0[v]); o1[v]=fmaf(s,wv.y,o1[v]); }
    }
    #pragma unroll
    for(int v=0;v<4;v++) if(val[v]){
        int n = nid[v];
        out[n*L+c0]=o0[v]; out[n*L+c0+1]=o1[v];
    }
}

// ---------------- gates: 48 nodes/block, 2-chunk weight streaming -> 2 blocks/SM ----------------
#define KC1 98
#define GATE_SMEM ((GN*196 + 3*KC1*L)*4)
__global__ __launch_bounds__(256) void k_gate(
        const float* __restrict__ prb,
        const float* __restrict__ zkW, const float* __restrict__ zkb,
        const float* __restrict__ rkW, const float* __restrict__ rkb,
        const float* __restrict__ cW,  const float* __restrict__ cb){
    if(blockIdx.x*GN >= g_ndcount) return;
    extern __shared__ float sm[];
    float* stgA = sm;                  // [48][196]
    float* Wz   = sm + GN*196;         // [98][64]
    float* Wr   = Wz + KC1*L;
    float* Wc   = Wr + KC1*L;
    __shared__ float szb[L], srb[L], scb[L];
    int tid = threadIdx.x;
    if(tid<L){ szb[tid]=zkb[tid]; srb[tid]=rkb[tid]; scb[tid]=cb[tid]; }
    int lane = tid&31, w = tid>>5, c0 = 2*lane;
    int i0 = w*6, sb = blockIdx.x*GN + i0;
    int nid[6]; bool val[6];
    #pragma unroll
    for(int v=0;v<6;v++){
        int slot = sb+v; val[v] = (slot < g_ndcount);
        int n = val[v]? g_nd[slot] : 0; nid[v] = n;
        float* A = stgA + (i0+v)*196;
        if(val[v]){
            *(float2*)&A[c0]     = *(const float2*)&g_H [n*L+c0];
            *(float2*)&A[64+c0]  = *(const float2*)&g_mt[n*L+c0];
            *(float2*)&A[128+c0] = *(const float2*)&g_mf[n*L+c0];
            if(lane==0){ A[192]=prb[2*n]; A[193]=prb[2*n+1]; }
        } else {
            *(float2*)&A[c0]     = make_float2(0.f,0.f);
            *(float2*)&A[64+c0]  = make_float2(0.f,0.f);
            *(float2*)&A[128+c0] = make_float2(0.f,0.f);
            if(lane==0){ A[192]=0.f; A[193]=0.f; }
        }
    }
    // load chunk 1 (rows 0..97)
    __syncthreads();
    for(int i=tid;i<KC1*L/4;i+=256){
        ((float4*)Wz)[i] = ((const float4*)zkW)[i];
        ((float4*)Wr)[i] = ((const float4*)rkW)[i];
        ((float4*)Wc)[i] = ((const float4*)cW)[i];
    }
    __syncthreads();
    float az0[6],az1[6],ar0[6],ar1[6],ac0[6],ac1[6];
    #pragma unroll
    for(int v=0;v<6;v++){ az0[v]=0.f; az1[v]=0.f; ar0[v]=0.f; ar1[v]=0.f; ac0[v]=0.f; ac1[v]=0.f; }
    for(int k=0;k<64;k++){
        float2 wz = *(const float2*)&Wz[k*L+c0];
        float2 wr = *(const float2*)&Wr[k*L+c0];
        #pragma unroll
        for(int v=0;v<6;v++){
            float cv = stgA[(i0+v)*196 + k];
            az0[v]=fmaf(cv,wz.x,az0[v]); az1[v]=fmaf(cv,wz.y,az1[v]);
            ar0[v]=fmaf(cv,wr.x,ar0[v]); ar1[v]=fmaf(cv,wr.y,ar1[v]);
        }
    }
    for(int k=64;k<KC1;k++){
        float2 wz = *(const float2*)&Wz[k*L+c0];
        float2 wr = *(const float2*)&Wr[k*L+c0];
        float2 wc = *(const float2*)&Wc[k*L+c0];
        #pragma unroll
        for(int v=0;v<6;v++){
            float cv = stgA[(i0+v)*196 + k];
            az0[v]=fmaf(cv,wz.x,az0[v]); az1[v]=fmaf(cv,wz.y,az1[v]);
            ar0[v]=fmaf(cv,wr.x,ar0[v]); ar1[v]=fmaf(cv,wr.y,ar1[v]);
            ac0[v]=fmaf(cv,wc.x,ac0[v]); ac1[v]=fmaf(cv,wc.y,ac1[v]);
        }
    }
    // load chunk 2 (rows 98..193)
    __syncthreads();
    for(int i=tid;i<(194-KC1)*L/4;i+=256){
        ((float4*)Wz)[i] = ((const float4*)(zkW+KC1*L))[i];
        ((float4*)Wr)[i] = ((const float4*)(rkW+KC1*L))[i];
        ((float4*)Wc)[i] = ((const float4*)(cW +KC1*L))[i];
    }
    __syncthreads();
    for(int k=KC1;k<194;k++){
        int kk = k - KC1;
        float2 wz = *(const float2*)&Wz[kk*L+c0];
        float2 wr = *(const float2*)&Wr[kk*L+c0];
        float2 wc = *(const float2*)&Wc[kk*L+c0];
        #pragma unroll
        for(int v=0;v<6;v++){
            float cv = stgA[(i0+v)*196 + k];
            az0[v]=fmaf(cv,wz.x,az0[v]); az1[v]=fmaf(cv,wz.y,az1[v]);
            ar0[v]=fmaf(cv,wr.x,ar0[v]); ar1[v]=fmaf(cv,wr.y,ar1[v]);
            ac0[v]=fmaf(cv,wc.x,ac0[v]); ac1[v]=fmaf(cv,wc.y,ac1[v]);
        }
    }
    // phase 3: overlay r-values + cW[0:64) into the weight region
    __syncthreads();
    float* stgB  = Wz;            // [48][64]
    float* scwlo = Wz + GN*L;     // [64][64]
    for(int i=tid;i<L*L/4;i+=256)
        ((float4*)scwlo)[i] = ((const float4*)cW)[i];
    float z0[6],z1[6];
    #pragma unroll
    for(int v=0;v<6;v++){
        z0[v]=sigf(az0[v]+szb[c0]); z1[v]=sigf(az1[v]+szb[c0+1]);
        float rr0=sigf(ar0[v]+srb[c0]), rr1=sigf(ar1[v]+srb[c0+1]);
        stgB[(i0+v)*L+c0]=rr0; stgB[(i0+v)*L+c0+1]=rr1;
    }
    __syncthreads();
    for(int k=0;k<64;k++){
        float2 wc = *(const float2*)&scwlo[k*L+c0];
        #pragma unroll
        for(int v=0;v<6;v++){
            float rh = stgB[(i0+v)*L+k] * stgA[(i0+v)*196+k];
            ac0[v]=fmaf(rh,wc.x,ac0[v]); ac1[v]=fmaf(rh,wc.y,ac1[v]);
        }
    }
    #pragma unroll
    for(int v=0;v<6;v++) if(val[v]){
        int n = nid[v];
        float* A = stgA + (i0+v)*196;
        float co0 = tanhf(ac0[v]+scb[c0]);
        float co1 = tanhf(ac1[v]+scb[c0+1]);
        float hn0 = A[c0]   + z0[v]*co0;
        float hn1 = A[c0+1] + z1[v]*co1;
        g_H[n*L+c0]   = hn0;
        g_H[n*L+c0+1] = hn1;
    }
}

// ---------------- decode + enc/autoenc losses over a node list ----------------
#define DEC_SMEM (3*64*L*4)
__global__ __launch_bounds__(256) void k_decode(
        int mode, float lossW,
        const float* __restrict__ dW1, const float* __restrict__ db1,
        const float* __restrict__ dW2, const float* __restrict__ db2,
        const float* __restrict__ eW1, const float* __restrict__ eb1,
        const float* __restrict__ eW2, const float* __restrict__ eb2){
    int cnt = mode ? g_ndcount : g_drcount;
    if(blockIdx.x*64 >= cnt) return;
    const int* list = mode ? g_nd : g_dr;
    extern __shared__ float sm[];
    float* sHn = sm;
    float* sB  = sm + 64*L;
    float* sE  = sm + 2*64*L;
    __shared__ float sdW2[L], sdb1[L], sE1[L], sEb1[L], sEb2[L];
    __shared__ double red[8];
    int tid = threadIdx.x;
    if(tid<L){ sdW2[tid]=dW2[tid]; sdb1[tid]=db1[tid]; sE1[tid]=eW1[tid];
               sEb1[tid]=eb1[tid]; sEb2[tid]=eb2[tid]; }
    __syncthreads();
    int lane = tid&31, w = tid>>5, c0 = 2*lane;
    int i0 = w*8, sb = blockIdx.x*64 + i0;
    float db2v = db2[0];
    int nid[8]; bool val[8];
    #pragma unroll
    for(int v=0;v<8;v++){
        int slot = sb+v; val[v] = (slot < cnt);
        nid[v] = val[v]? list[slot] : 0;
        float2 h = val[v]? *(const float2*)&g_H[nid[v]*L+c0] : make_float2(0.f,0.f);
        *(float2*)&sHn[(i0+v)*L+c0] = h;
    }
    __syncwarp();
    float ad0[8],ad1[8];
    #pragma unroll
    for(int v=0;v<8;v++){ ad0[v]=sdb1[c0]; ad1[v]=sdb1[c0+1]; }
    for(int k=0;k<L;k++){
        float2 wd = __ldg((const float2*)&dW1[k*L+c0]);
        #pragma unroll
        for(int v=0;v<8;v++){
            float hk = sHn[(i0+v)*L+k];
            ad0[v]=fmaf(hk,wd.x,ad0[v]); ad1[v]=fmaf(hk,wd.y,ad1[v]);
        }
    }
    float Uv[8];
    #pragma unroll
    for(int v=0;v<8;v++){
        float pu = fmaxf(ad0[v],0.f)*sdW2[c0] + fmaxf(ad1[v],0.f)*sdW2[c0+1];
        for(int o=16;o;o>>=1) pu += __shfl_xor_sync(0xffffffffu, pu, o);
        Uv[v] = pu + db2v;
        if(val[v] && lane==0) g_U[nid[v]] = Uv[v];
        float eh0 = fmaxf(fmaf(Uv[v],sE1[c0],sEb1[c0]),0.f);
        float eh1 = fmaxf(fmaf(Uv[v],sE1[c0+1],sEb1[c0+1]),0.f);
        sB[(i0+v)*L+c0]=eh0; sB[(i0+v)*L+c0+1]=eh1;
    }
    __syncwarp();
    float ae0[8],ae1[8];
    #pragma unroll
    for(int v=0;v<8;v++){ ae0[v]=sEb2[c0]; ae1[v]=sEb2[c0+1]; }
    for(int k=0;k<L;k++){
        float2 we = __ldg((const float2*)&eW2[k*L+c0]);
        #pragma unroll
        for(int v=0;v<8;v++){
            float ek = sB[(i0+v)*L+k];
            ae0[v]=fmaf(ek,we.x,ae0[v]); ae1[v]=fmaf(ek,we.y,ae1[v]);
        }
    }
    float encS = 0.f;
    #pragma unroll
    for(int v=0;v<8;v++){
        if(val[v]){
            float d0 = ae0[v]-sHn[(i0+v)*L+c0], d1 = ae1[v]-sHn[(i0+v)*L+c0+1];
            encS += d0*d0 + d1*d1;
        }
        sE[(i0+v)*L+c0]=ae0[v]; sE[(i0+v)*L+c0+1]=ae1[v];
    }
    __syncwarp();
    float ag0[8],ag1[8];
    #pragma unroll
    for(int v=0;v<8;v++){ ag0[v]=sdb1[c0]; ag1[v]=sdb1[c0+1]; }
    for(int k=0;k<L;k++){
        float2 wd = __ldg((const float2*)&dW1[k*L+c0]);
        #pragma unroll
        for(int v=0;v<8;v++){
            float ek = sE[(i0+v)*L+k];
            ag0[v]=fmaf(ek,wd.x,ag0[v]); ag1[v]=fmaf(ek,wd.y,ag1[v]);
        }
    }
    float autoS = 0.f;
    #pragma unroll
    for(int v=0;v<8;v++){
        float pa = fmaxf(ag0[v],0.f)*sdW2[c0] + fmaxf(ag1[v],0.f)*sdW2[c0+1];
        for(int o=16;o;o>>=1) pa += __shfl_xor_sync(0xffffffffu, pa, o);
        float aout = pa + db2v;
        if(val[v] && lane==0){ float d = aout - Uv[v]; autoS += d*d; }
    }
    float tot = encS;
    for(int o=16;o;o>>=1) tot += __shfl_xor_sync(0xffffffffu, tot, o);
    float at = autoS;
    for(int o=16;o;o>>=1) at += __shfl_xor_sync(0xffffffffu, at, o);
    if(lane==0) red[w] = (double)lossW * ((double)tot/((double)NN*64.0) + (double)at/(double)NN);
    __syncthreads();
    if(tid==0){
        double s = 0.0;
        for(int i=0;i<8;i++) s += red[i];
        atomicAdd(&g_loss, s);
    }
}

// ---------------- residual loss (rowJ/rowA: 8B/edge) ----------------
__global__ __launch_bounds__(256) void k_res(const float* __restrict__ y, float wgt){
    __shared__ double red[8];
    int lane = threadIdx.x&31, w = threadIdx.x>>5;
    int wid = blockIdx.x*8 + w;
    int nwarps = gridDim.x*8;
    float ls = 0.f;
    for(int n = wid; n < NN; n += nwarps){
        int s = g_rowptr[n], e = g_rowptr[n+1];
        float part = 0.f;
        for(int p = s+lane; p < e; p += 32){
            part += g_rowA[p] * g_U[g_rowJ[p]];
        }
        for(int o=16;o;o>>=1) part += __shfl_xor_sync(0xffffffffu, part, o);
        if(lane==0){ float d = part - y[n]; ls += d*d; }
    }
    for(int o=16;o;o>>=1) ls += __shfl_xor_sync(0xffffffffu, ls, o);
    if(lane==0) red[w] = (double)ls;
    __syncthreads();
    if(threadIdx.x==0){
        double s=0.0; for(int i=0;i<8;i++) s+=red[i];
        atomicAdd(&g_loss, s * (double)wgt / (double)NN);
    }
}

// ---------------- finalize + reset state for next replay ----------------
__global__ void k_fin(float* __restrict__ out, int out_size){
    int i = blockIdx.x*blockDim.x + threadIdx.x;
    if(i < NN && i < out_size) out[i] = g_U[i];
    if(i == NN){
        if(i < out_size) out[NN] = (float)g_loss;
        g_loss = 0.0;
    }
    if(i < NN){ g_cntr[i]=0; g_cntc[i]=0; }
}

extern "C" void kernel_launch(void* const* d_in, const int* in_sizes, int n_in,
                              void* d_out, int out_size){
    const float* x    = (const float*)d_in[0];
    const float* y    = (const float*)d_in[2];
    const int*   tags = (const int*)  d_in[3];
    const int*   ei   = (const int*)  d_in[4];
    const float* ea   = (const float*)d_in[5];
    const float* aij  = (const float*)d_in[6];
    const float* prb  = (const float*)d_in[7];
    const float* ptW1 = (const float*)d_in[8];
    const float* ptb1 = (const float*)d_in[9];
    const float* ptW2 = (const float*)d_in[10];
    const float* ptb2 = (const float*)d_in[11];
    const float* pfW1 = (const float*)d_in[12];
    const float* pfb1 = (const float*)d_in[13];
    const float* pfW2 = (const float*)d_in[14];
    const float* pfb2 = (const float*)d_in[15];
    const float* zkW  = (const float*)d_in[16];
    const float* zkb  = (const float*)d_in[17];
    const float* rkW  = (const float*)d_in[18];
    const float* rkb  = (const float*)d_in[19];
    const float* cW   = (const float*)d_in[20];
    const float* cb   = (const float*)d_in[21];
    const float* eW1  = (const float*)d_in[22];
    const float* eb1  = (const float*)d_in[23];
    const float* eW2  = (const float*)d_in[24];
    const float* eb2  = (const float*)d_in[25];
    const float* dW1  = (const float*)d_in[26];
    const float* db1  = (const float*)d_in[27];
    const float* dW2  = (const float*)d_in[28];
    const float* db2  = (const float*)d_in[29];

    cudaFuncSetAttribute(k_prep,   cudaFuncAttributeMaxDynamicSharedMemorySize, PREP_SMEM);
    cudaFuncSetAttribute(k_gate,   cudaFuncAttributeMaxDynamicSharedMemorySize, GATE_SMEM);
    cudaFuncSetAttribute(k_decode, cudaFuncAttributeMaxDynamicSharedMemorySize, DEC_SMEM);

    int *rowptr, *colptr;
    float4 *rowE4, *colE4;
    float *Pt, *Pf, *mt, *mf;
    __half2 *Qt16, *Qf16;
    cudaGetSymbolAddress((void**)&rowptr, g_rowptr);
    cudaGetSymbolAddress((void**)&colptr, g_colptr);
    cudaGetSymbolAddress((void**)&rowE4,  g_rowE4);
    cudaGetSymbolAddress((void**)&colE4,  g_colE4);
    cudaGetSymbolAddress((void**)&Pt, g_Pt);
    cudaGetSymbolAddress((void**)&Pf, g_Pf);
    cudaGetSymbolAddress((void**)&Qt16, g_Qt16);
    cudaGetSymbolAddress((void**)&Qf16, g_Qf16);
    cudaGetSymbolAddress((void**)&mt, g_mt);
    cudaGetSymbolAddress((void**)&mf, g_mf);

    k_enc0<<<NB32, 256>>>(x, eW1, eb1, eW2, eb2);                        // 0
    k_hist<<<(NE+255)/256, 256>>>(ei);                                   // 1
    k_scanA<<<SBLK, 256>>>(tags);                                        // 2
    k_prep<<<NB64, 256, PREP_SMEM>>>(ptW1, ptb1, pfW1, pfb1, 0);         // 3 (profiled control)
    k_scanB<<<1, 256>>>();                                               // 4
    k_scanC<<<SBLK, 256>>>(tags);                                        // 5
    k_scatter<<<(NE+255)/256, 256>>>(ei, ea, aij);                       // 6
    // Dirichlet nodes: losses identical both steps -> once, weight 2
    k_decode<<<NB64, 256, DEC_SMEM>>>(0, 2.0f, dW1, db1, dW2, db2, eW1, eb1, eW2, eb2);

    const float gammaw[2] = {0.9f, 1.0f};
    for(int step=0; step<2; step++){
        k_aggr<<<2*NB32, 256>>>(colptr, colE4, rowptr, rowE4,
                                Pt, Qt16, Pf, Qf16,
                                ptW1, ptb2, ptW2, pfW1, pfb2, pfW2, mt, mf);
        k_gate<<<NBG, 256, GATE_SMEM>>>(prb, zkW, zkb, rkW, rkb, cW, cb);
        k_decode<<<NB64, 256, DEC_SMEM>>>(1, 1.0f, dW1, db1, dW2, db2, eW1, eb1, eW2, eb2);
        k_res<<<NB32, 256>>>(y, gammaw[step]);
        if(step == 0)
            k_prep<<<NB64, 256, PREP_SMEM>>>(ptW1, ptb1, pfW1, pfb1, 1);
    }
    k_fin<<<(NN+256)/256, 256>>>((float*)d_out, out_size);
}

// round 17
// speedup vs baseline: 1.6609x; 1.0371x over previous
#include <cuda_runtime.h>
#include <cuda_fp16.h>
#include <math.h>

#define NN 50000
#define NE 800000
#define L  64
#define NB32 ((NN + 31) / 32)
#define NB64 ((NN + 63) / 64)
#define SBLK ((NN + 255) / 256)
#define GN   48
#define NBG  ((NN + GN - 1) / GN)

// ------------- device scratch (statics zero-initialized; k_fin re-zeroes) -------------
__device__ float   g_H [NN*L];
__device__ float   g_H0[NN*L];
__device__ float   g_Pt[NN*L];
__device__ float   g_Pf[NN*L];
__device__ __half2 g_Qt16[NN*32];
__device__ __half2 g_Qf16[NN*32];
__device__ float   g_mt[NN*L];
__device__ float   g_mf[NN*L];
__device__ float   g_U [NN];
__device__ int     g_rowptr[NN+1];
__device__ int     g_colptr[NN+1];
__device__ int     g_cntr[NN];
__device__ int     g_cntc[NN];
__device__ int     g_nd[NN];
__device__ int     g_dr[NN];
__device__ int     g_ndcount;
__device__ int     g_drcount;
__device__ int     g_partR[256], g_partC[256], g_partN[256];
__device__ int     g_baseR[256], g_baseC[256], g_baseN[256];
__device__ float4  g_rowE4[NE];
__device__ float4  g_colE4[NE];
__device__ float   g_rowA[NE];
__device__ int     g_rowJ[NE];
__device__ double  g_loss;

__device__ __forceinline__ float sigf(float v){ return 1.f/(1.f+__expf(-v)); }

// ---------------- CSR build ----------------
__global__ void k_hist(const int* __restrict__ ei){
    int e = blockIdx.x*blockDim.x + threadIdx.x;
    if(e < NE){
        atomicAdd(&g_cntr[ei[e]], 1);
        atomicAdd(&g_cntc[ei[NE+e]], 1);
    }
}

// phase A: per-block sums
__global__ __launch_bounds__(256) void k_scanA(const int* __restrict__ tags){
    __shared__ int sR[256], sC[256], sN[256];
    int tid = threadIdx.x;
    int t = blockIdx.x*256 + tid;
    int cr=0, cc=0, nd=0;
    if(t < NN){ cr = g_cntr[t]; cc = g_cntc[t]; nd = (tags[t]!=1); }
    sR[tid]=cr; sC[tid]=cc; sN[tid]=nd;
    __syncthreads();
    for(int off=128; off; off>>=1){
        if(tid < off){ sR[tid]+=sR[tid+off]; sC[tid]+=sC[tid+off]; sN[tid]+=sN[tid+off]; }
        __syncthreads();
    }
    if(tid==0){ g_partR[blockIdx.x]=sR[0]; g_partC[blockIdx.x]=sC[0]; g_partN[blockIdx.x]=sN[0]; }
}

// phase B: scan partials (1 small block)
__global__ __launch_bounds__(256) void k_scanB(){
    __shared__ int sR[256], sC[256], sN[256];
    int i = threadIdx.x;
    int vR = (i<SBLK)? g_partR[i] : 0;
    int vC = (i<SBLK)? g_partC[i] : 0;
    int vN = (i<SBLK)? g_partN[i] : 0;
    sR[i]=vR; sC[i]=vC; sN[i]=vN;
    __syncthreads();
    for(int off=1; off<256; off<<=1){
        int aR=0,aC=0,aN=0;
        if(i>=off){ aR=sR[i-off]; aC=sC[i-off]; aN=sN[i-off]; }
        __syncthreads();
        sR[i]+=aR; sC[i]+=aC; sN[i]+=aN;
        __syncthreads();
    }
    if(i<SBLK){
        g_baseR[i] = sR[i]-vR;   // exclusive
        g_baseC[i] = sC[i]-vC;
        g_baseN[i] = sN[i]-vN;
    }
    if(i==0){
        int totR = sR[SBLK-1], totC = sC[SBLK-1], totN = sN[SBLK-1];
        g_rowptr[NN] = totR;
        g_colptr[NN] = totC;
        g_ndcount = totN;
        g_drcount = NN - totN;
    }
}

// phase C: intra-block scan, write ptrs, zero counters, compact nd/dr
__global__ __launch_bounds__(256) void k_scanC(const int* __restrict__ tags){
    __shared__ int sR[256], sC[256], sN[256];
    int tid = threadIdx.x;
    int t = blockIdx.x*256 + tid;
    int cr=0, cc=0, nd=0;
    if(t < NN){ cr = g_cntr[t]; cc = g_cntc[t]; nd = (tags[t]!=1); }
    sR[tid]=cr; sC[tid]=cc; sN[tid]=nd;
    __syncthreads();
    for(int off=1; off<256; off<<=1){
        int aR=0,aC=0,aN=0;
        if(tid>=off){ aR=sR[tid-off]; aC=sC[tid-off]; aN=sN[tid-off]; }
        __syncthreads();
        sR[tid]+=aR; sC[tid]+=aC; sN[tid]+=aN;
        __syncthreads();
    }
    if(t < NN){
        int exR = sR[tid]-cr, exC = sC[tid]-cc, exN = sN[tid]-nd;
        g_rowptr[t] = g_baseR[blockIdx.x] + exR;
        g_colptr[t] = g_baseC[blockIdx.x] + exC;
        g_cntr[t] = 0; g_cntc[t] = 0;
        int ndpos = g_baseN[blockIdx.x] + exN;
        if(nd) g_nd[ndpos] = t;
        else   g_dr[t - ndpos] = t;
    }
}

__global__ void k_scatter(const int* __restrict__ ei, const float* __restrict__ ea,
                          const float* __restrict__ aij){
    int e = blockIdx.x*blockDim.x + threadIdx.x;
    if(e >= NE) return;
    int r = ei[e], c = ei[NE+e];
    float a0 = ea[3*e], a1 = ea[3*e+1], a2 = ea[3*e+2];
    int pr = atomicAdd(&g_cntr[r], 1);
    int p  = g_rowptr[r] + pr;
    g_rowE4[p] = make_float4(a0,a1,a2,__int_as_float(c));
    g_rowA[p]  = aij[e];
    g_rowJ[p]  = c;
    int pc = atomicAdd(&g_cntc[c], 1);
    int q  = g_colptr[c] + pc;
    g_colE4[q] = make_float4(a0,a1,a2,__int_as_float(r));
}

// ---------------- encoder: x -> H0, H ----------------
__global__ __launch_bounds__(256) void k_enc0(const float* __restrict__ x,
        const float* __restrict__ eW1, const float* __restrict__ eb1,
        const float* __restrict__ eW2, const float* __restrict__ eb2){
    __shared__ float sW[L*L];
    __shared__ float sh[8][4][L];
    int tid = threadIdx.x;
    for(int i=tid;i<L*L/4;i+=256) ((float4*)sW)[i] = ((const float4*)eW2)[i];
    __syncthreads();
    int lane = tid&31, w = tid>>5, c0 = 2*lane;
    int nb = blockIdx.x*32 + w*4;
    float w1a=eW1[c0], w1b=eW1[c0+1], b1a=eb1[c0], b1b=eb1[c0+1];
    float b2a=eb2[c0], b2b=eb2[c0+1];
    bool val[4];
    #pragma unroll
    for(int v=0;v<4;v++){
        int n = nb+v; val[v] = (n<NN);
        float xv = val[v]? x[n] : 0.f;
        sh[w][v][c0]   = fmaxf(fmaf(xv,w1a,b1a),0.f);
        sh[w][v][c0+1] = fmaxf(fmaf(xv,w1b,b1b),0.f);
    }
    __syncwarp();
    float a0[4]={b2a,b2a,b2a,b2a}, a1[4]={b2b,b2b,b2b,b2b};
    for(int k=0;k<L;k++){
        float2 wv = *(const float2*)&sW[k*L+c0];
        #pragma unroll
        for(int v=0;v<4;v++){ float s=sh[w][v][k]; a0[v]=fmaf(s,wv.x,a0[v]); a1[v]=fmaf(s,wv.y,a1[v]); }
    }
    #pragma unroll
    for(int v=0;v<4;v++) if(val[v]){
        int n = nb+v;
        g_H0[n*L+c0]=a0[v]; g_H0[n*L+c0+1]=a1[v];
        g_H [n*L+c0]=a0[v]; g_H [n*L+c0+1]=a1[v];
    }
}

// ---------------- P/Q precompute (both phis), 8 nodes/warp; Q stored as half2 ----------------
#define PREP_SMEM ((4*L*L + 64*L)*4)
__global__ __launch_bounds__(256) void k_prep(
        const float* __restrict__ ptW1, const float* __restrict__ ptb1,
        const float* __restrict__ pfW1, const float* __restrict__ pfb1,
        int use_perm){
    if(use_perm && blockIdx.x*64 >= g_ndcount) return;
    extern __shared__ float sm[];
    float* Wat = sm;
    float* Wbt = sm + L*L;
    float* Waf = sm + 2*L*L;
    float* Wbf = sm + 3*L*L;
    float* stg = sm + 4*L*L;
    int tid = threadIdx.x;
    for(int i=tid;i<L*L/4;i+=256){
        ((float4*)Wat)[i] = ((const float4*)ptW1)[i];
        ((float4*)Wbt)[i] = ((const float4*)(ptW1+L*L))[i];
        ((float4*)Waf)[i] = ((const float4*)pfW1)[i];
        ((float4*)Wbf)[i] = ((const float4*)(pfW1+L*L))[i];
    }
    int lane = tid&31, w = tid>>5, c0 = 2*lane;
    int i0 = w*8, sb = blockIdx.x*64 + i0;
    int nid[8]; bool val[8];
    #pragma unroll
    for(int v=0;v<8;v++){
        int slot = sb+v;
        if(use_perm){ val[v] = (slot < g_ndcount); nid[v] = val[v]? g_nd[slot] : 0; }
        else        { val[v] = (slot < NN);        nid[v] = slot; }
        float2 h = val[v]? *(const float2*)&g_H[nid[v]*L+c0] : make_float2(0.f,0.f);
        *(float2*)&stg[(i0+v)*L+c0] = h;
    }
    __syncthreads();
    float pt0[8],pt1[8],qt0[8],qt1[8],pf0[8],pf1[8],qf0[8],qf1[8];
    float bt0=ptb1[c0], bt1=ptb1[c0+1], bf0=pfb1[c0], bf1=pfb1[c0+1];
    #pragma unroll
    for(int v=0;v<8;v++){ pt0[v]=bt0; pt1[v]=bt1; pf0[v]=bf0; pf1[v]=bf1;
                          qt0[v]=0.f; qt1[v]=0.f; qf0[v]=0.f; qf1[v]=0.f; }
    for(int k=0;k<L;k++){
        float2 wat = *(const float2*)&Wat[k*L+c0];
        float2 wbt = *(const float2*)&Wbt[k*L+c0];
        float2 waf = *(const float2*)&Waf[k*L+c0];
        float2 wbf = *(const float2*)&Wbf[k*L+c0];
        #pragma unroll
        for(int v=0;v<8;v++){
            float h = stg[(i0+v)*L + k];
            pt0[v]=fmaf(h,wat.x,pt0[v]); pt1[v]=fmaf(h,wat.y,pt1[v]);
            qt0[v]=fmaf(h,wbt.x,qt0[v]); qt1[v]=fmaf(h,wbt.y,qt1[v]);
            pf0[v]=fmaf(h,waf.x,pf0[v]); pf1[v]=fmaf(h,waf.y,pf1[v]);
            qf0[v]=fmaf(h,wbf.x,qf0[v]); qf1[v]=fmaf(h,wbf.y,qf1[v]);
        }
    }
    #pragma unroll
    for(int v=0;v<8;v++) if(val[v]){
        int n = nid[v];
        g_Pt[n*L+c0]=pt0[v]; g_Pt[n*L+c0+1]=pt1[v];
        g_Pf[n*L+c0]=pf0[v]; g_Pf[n*L+c0+1]=pf1[v];
        g_Qt16[n*32+lane] = __floats2half2_rn(qt0[v], qt1[v]);
        g_Qf16[n*32+lane] = __floats2half2_rn(qf0[v], qf1[v]);
    }
}

// ---------------- edge aggregation + W2 fold; Q gathered as half2 ----------------
__global__ __launch_bounds__(256) void k_aggr(
        const int* __restrict__ colptr, const float4* __restrict__ colE4,
        const int* __restrict__ rowptr, const float4* __restrict__ rowE4,
        const float* __restrict__ Pt, const __half2* __restrict__ Qt,
        const float* __restrict__ Pf, const __half2* __restrict__ Qf,
        const float* __restrict__ ptW1, const float* __restrict__ ptb2, const float* __restrict__ ptW2,
        const float* __restrict__ pfW1, const float* __restrict__ pfb2, const float* __restrict__ pfW2,
        float* __restrict__ mt, float* __restrict__ mf){
    bool toDir = (blockIdx.x < NB32);
    int bb = toDir ? blockIdx.x : blockIdx.x - NB32;
    if(bb*32 >= g_ndcount) return;
    __shared__ float sW2[L*L];
    __shared__ float sWe[3*L];
    __shared__ float sS[8][4][L];
    const int*     ptr = toDir ? colptr : rowptr;
    const float4*  e4  = toDir ? colE4  : rowE4;
    const float*   P   = toDir ? Pt     : Pf;
    const __half2* Q   = toDir ? Qt     : Qf;
    const float*   W1  = toDir ? ptW1   : pfW1;
    const float*   b2  = toDir ? ptb2   : pfb2;
    const float*   W2  = toDir ? ptW2   : pfW2;
    float*         out = toDir ? mt     : mf;
    int tid = threadIdx.x;
    for(int i=tid;i<L*L/4;i+=256) ((float4*)sW2)[i] = ((const float4*)W2)[i];
    for(int i=tid;i<3*L;i+=256) sWe[i] = W1[2*L*L + i];
    __syncthreads();
    int lane = tid&31, w = tid>>5, c0 = 2*lane;
    int sb = bb*32 + w*4;
    float we0a=sWe[c0],     we0b=sWe[c0+1];
    float we1a=sWe[L+c0],   we1b=sWe[L+c0+1];
    float we2a=sWe[2*L+c0], we2b=sWe[2*L+c0+1];
    float degv[4]; bool val[4]; int nid[4];
    #pragma unroll
    for(int v=0;v<4;v++){
        int slot = sb+v;
        val[v] = (slot < g_ndcount);
        int n = val[v]? g_nd[slot] : 0;
        nid[v] = n;
        float acc0=0.f, acc1=0.f; int cnt=0;
        if(val[v]){
            float base0 = P[n*L+c0], base1 = P[n*L+c0+1];
            int s = ptr[n], e = ptr[n+1];
            for(int p=s; p<e; p++){
                float4 E = e4[p];
                int j = __float_as_int(E.w);
                if(j == n) continue;
                cnt++;
                float2 qv = __half22float2(Q[j*32+lane]);
                float pre0 = base0 + qv.x + E.x*we0a + E.y*we1a + E.z*we2a;
                float pre1 = base1 + qv.y + E.x*we0b + E.y*we1b + E.z*we2b;
                acc0 += fmaxf(pre0, 0.f);
                acc1 += fmaxf(pre1, 0.f);
            }
        }
        sS[w][v][c0]=acc0; sS[w][v][c0+1]=acc1; degv[v]=(float)cnt;
    }
    __syncwarp();
    float b2a=b2[c0], b2b=b2[c0+1];
    float o0[4],o1[4];
    #pragma unroll
    for(int v=0;v<4;v++){ o0[v]=degv[v]*b2a; o1[v]=degv[v]*b2b; }
    for(int k=0;k<L;k++){
        float2 wv = *(const float2*)&sW2[k*L+c0];
        #pragma unroll
        for(int v=0;v<4;v++){ float s=sS[w][v][k]; o0[v]=fmaf(s,wv.x,o0[v]); o1[v]=fmaf(s,wv.y,o1[v]); }
    }
    #pragma unroll
    for(int v=0;v<4;v++) if(val[v]){
        int n = nid[v];
        out[n*L+c0]=o0[v]; out[n*L+c0+1]=o1[v];
    }
}

// ---------------- gates: 48 nodes/block, 2-chunk weight streaming -> 2 blocks/SM ----------------
#define KC1 98
#define GATE_SMEM ((GN*196 + 3*KC1*L)*4)
__global__ __launch_bounds__(256) void k_gate(
        const float* __restrict__ prb,
        const float* __restrict__ zkW, const float* __restrict__ zkb,
        const float* __restrict__ rkW, const float* __restrict__ rkb,
        const float* __restrict__ cW,  const float* __restrict__ cb){
    if(blockIdx.x*GN >= g_ndcount) return;
    extern __shared__ float sm[];
    float* stgA = sm;                  // [48][196]
    float* Wz   = sm + GN*196;         // [98][64]
    float* Wr   = Wz + KC1*L;
    float* Wc   = Wr + KC1*L;
    __shared__ float szb[L], srb[L], scb[L];
    int tid = threadIdx.x;
    if(tid<L){ szb[tid]=zkb[tid]; srb[tid]=rkb[tid]; scb[tid]=cb[tid]; }
    int lane = tid&31, w = tid>>5, c0 = 2*lane;
    int i0 = w*6, sb = blockIdx.x*GN + i0;
    int nid[6]; bool val[6];
    #pragma unroll
    for(int v=0;v<6;v++){
        int slot = sb+v; val[v] = (slot < g_ndcount);
        int n = val[v]? g_nd[slot] : 0; nid[v] = n;
        float* A = stgA + (i0+v)*196;
        if(val[v]){
            *(float2*)&A[c0]     = *(const float2*)&g_H [n*L+c0];
            *(float2*)&A[64+c0]  = *(const float2*)&g_mt[n*L+c0];
            *(float2*)&A[128+c0] = *(const float2*)&g_mf[n*L+c0];
            if(lane==0){ A[192]=prb[2*n]; A[193]=prb[2*n+1]; }
        } else {
            *(float2*)&A[c0]     = make_float2(0.f,0.f);
            *(float2*)&A[64+c0]  = make_float2(0.f,0.f);
            *(float2*)&A[128+c0] = make_float2(0.f,0.f);
            if(lane==0){ A[192]=0.f; A[193]=0.f; }
        }
    }
    // load chunk 1 (rows 0..97)
    __syncthreads();
    for(int i=tid;i<KC1*L/4;i+=256){
        ((float4*)Wz)[i] = ((const float4*)zkW)[i];
        ((float4*)Wr)[i] = ((const float4*)rkW)[i];
        ((float4*)Wc)[i] = ((const float4*)cW)[i];
    }
    __syncthreads();
    float az0[6],az1[6],ar0[6],ar1[6],ac0[6],ac1[6];
    #pragma unroll
    for(int v=0;v<6;v++){ az0[v]=0.f; az1[v]=0.f; ar0[v]=0.f; ar1[v]=0.f; ac0[v]=0.f; ac1[v]=0.f; }
    for(int k=0;k<64;k++){
        float2 wz = *(const float2*)&Wz[k*L+c0];
        float2 wr = *(const float2*)&Wr[k*L+c0];
        #pragma unroll
        for(int v=0;v<6;v++){
            float cv = stgA[(i0+v)*196 + k];
            az0[v]=fmaf(cv,wz.x,az0[v]); az1[v]=fmaf(cv,wz.y,az1[v]);
            ar0[v]=fmaf(cv,wr.x,ar0[v]); ar1[v]=fmaf(cv,wr.y,ar1[v]);
        }
    }
    for(int k=64;k<KC1;k++){
        float2 wz = *(const float2*)&Wz[k*L+c0];
        float2 wr = *(const float2*)&Wr[k*L+c0];
        float2 wc = *(const float2*)&Wc[k*L+c0];
        #pragma unroll
        for(int v=0;v<6;v++){
            float cv = stgA[(i0+v)*196 + k];
            az0[v]=fmaf(cv,wz.x,az0[v]); az1[v]=fmaf(cv,wz.y,az1[v]);
            ar0[v]=fmaf(cv,wr.x,ar0[v]); ar1[v]=fmaf(cv,wr.y,ar1[v]);
            ac0[v]=fmaf(cv,wc.x,ac0[v]); ac1[v]=fmaf(cv,wc.y,ac1[v]);
        }
    }
    // load chunk 2 (rows 98..193)
    __syncthreads();
    for(int i=tid;i<(194-KC1)*L/4;i+=256){
        ((float4*)Wz)[i] = ((const float4*)(zkW+KC1*L))[i];
        ((float4*)Wr)[i] = ((const float4*)(rkW+KC1*L))[i];
        ((float4*)Wc)[i] = ((const float4*)(cW +KC1*L))[i];
    }
    __syncthreads();
    for(int k=KC1;k<194;k++){
        int kk = k - KC1;
        float2 wz = *(const float2*)&Wz[kk*L+c0];
        float2 wr = *(const float2*)&Wr[kk*L+c0];
        float2 wc = *(const float2*)&Wc[kk*L+c0];
        #pragma unroll
        for(int v=0;v<6;v++){
            float cv = stgA[(i0+v)*196 + k];
            az0[v]=fmaf(cv,wz.x,az0[v]); az1[v]=fmaf(cv,wz.y,az1[v]);
            ar0[v]=fmaf(cv,wr.x,ar0[v]); ar1[v]=fmaf(cv,wr.y,ar1[v]);
            ac0[v]=fmaf(cv,wc.x,ac0[v]); ac1[v]=fmaf(cv,wc.y,ac1[v]);
        }
    }
    // phase 3: overlay r-values + cW[0:64) into the weight region
    __syncthreads();
    float* stgB  = Wz;            // [48][64]
    float* scwlo = Wz + GN*L;     // [64][64]
    for(int i=tid;i<L*L/4;i+=256)
        ((float4*)scwlo)[i] = ((const float4*)cW)[i];
    float z0[6],z1[6];
    #pragma unroll
    for(int v=0;v<6;v++){
        z0[v]=sigf(az0[v]+szb[c0]); z1[v]=sigf(az1[v]+szb[c0+1]);
        float rr0=sigf(ar0[v]+srb[c0]), rr1=sigf(ar1[v]+srb[c0+1]);
        stgB[(i0+v)*L+c0]=rr0; stgB[(i0+v)*L+c0+1]=rr1;
    }
    __syncthreads();
    for(int k=0;k<64;k++){
        float2 wc = *(const float2*)&scwlo[k*L+c0];
        #pragma unroll
        for(int v=0;v<6;v++){
            float rh = stgB[(i0+v)*L+k] * stgA[(i0+v)*196+k];
            ac0[v]=fmaf(rh,wc.x,ac0[v]); ac1[v]=fmaf(rh,wc.y,ac1[v]);
        }
    }
    #pragma unroll
    for(int v=0;v<6;v++) if(val[v]){
        int n = nid[v];
        float* A = stgA + (i0+v)*196;
        float co0 = tanhf(ac0[v]+scb[c0]);
        float co1 = tanhf(ac1[v]+scb[c0+1]);
        float hn0 = A[c0]   + z0[v]*co0;
        float hn1 = A[c0+1] + z1[v]*co1;
        g_H[n*L+c0]   = hn0;
        g_H[n*L+c0+1] = hn1;
    }
}

// ---------------- decode + enc/autoenc losses over a node list ----------------
#define DEC_SMEM (3*64*L*4)
__global__ __launch_bounds__(256) void k_decode(
        int mode, float lossW,
        const float* __restrict__ dW1, const float* __restrict__ db1,
        const float* __restrict__ dW2, const float* __restrict__ db2,
        const float* __restrict__ eW1, const float* __restrict__ eb1,
        const float* __restrict__ eW2, const float* __restrict__ eb2){
    int cnt = mode ? g_ndcount : g_drcount;
    if(blockIdx.x*64 >= cnt) return;
    const int* list = mode ? g_nd : g_dr;
    extern __shared__ float sm[];
    float* sHn = sm;
    float* sB  = sm + 64*L;
    float* sE  = sm + 2*64*L;
    __shared__ float sdW2[L], sdb1[L], sE1[L], sEb1[L], sEb2[L];
    __shared__ double red[8];
    int tid = threadIdx.x;
    if(tid<L){ sdW2[tid]=dW2[tid]; sdb1[tid]=db1[tid]; sE1[tid]=eW1[tid];
               sEb1[tid]=eb1[tid]; sEb2[tid]=eb2[tid]; }
    __syncthreads();
    int lane = tid&31, w = tid>>5, c0 = 2*lane;
    int i0 = w*8, sb = blockIdx.x*64 + i0;
    float db2v = db2[0];
    int nid[8]; bool val[8];
    #pragma unroll
    for(int v=0;v<8;v++){
        int slot = sb+v; val[v] = (slot < cnt);
        nid[v] = val[v]? list[slot] : 0;
        float2 h = val[v]? *(const float2*)&g_H[nid[v]*L+c0] : make_float2(0.f,0.f);
        *(float2*)&sHn[(i0+v)*L+c0] = h;
    }
    __syncwarp();
    float ad0[8],ad1[8];
    #pragma unroll
    for(int v=0;v<8;v++){ ad0[v]=sdb1[c0]; ad1[v]=sdb1[c0+1]; }
    for(int k=0;k<L;k++){
        float2 wd = __ldg((const float2*)&dW1[k*L+c0]);
        #pragma unroll
        for(int v=0;v<8;v++){
            float hk = sHn[(i0+v)*L+k];
            ad0[v]=fmaf(hk,wd.x,ad0[v]); ad1[v]=fmaf(hk,wd.y,ad1[v]);
        }
    }
    float Uv[8];
    #pragma unroll
    for(int v=0;v<8;v++){
        float pu = fmaxf(ad0[v],0.f)*sdW2[c0] + fmaxf(ad1[v],0.f)*sdW2[c0+1];
        for(int o=16;o;o>>=1) pu += __shfl_xor_sync(0xffffffffu, pu, o);
        Uv[v] = pu + db2v;
        if(val[v] && lane==0) g_U[nid[v]] = Uv[v];
        float eh0 = fmaxf(fmaf(Uv[v],sE1[c0],sEb1[c0]),0.f);
        float eh1 = fmaxf(fmaf(Uv[v],sE1[c0+1],sEb1[c0+1]),0.f);
        sB[(i0+v)*L+c0]=eh0; sB[(i0+v)*L+c0+1]=eh1;
    }
    __syncwarp();
    float ae0[8],ae1[8];
    #pragma unroll
    for(int v=0;v<8;v++){ ae0[v]=sEb2[c0]; ae1[v]=sEb2[c0+1]; }
    for(int k=0;k<L;k++){
        float2 we = __ldg((const float2*)&eW2[k*L+c0]);
        #pragma unroll
        for(int v=0;v<8;v++){
            float ek = sB[(i0+v)*L+k];
            ae0[v]=fmaf(ek,we.x,ae0[v]); ae1[v]=fmaf(ek,we.y,ae1[v]);
        }
    }
    float encS = 0.f;
    #pragma unroll
    for(int v=0;v<8;v++){
        if(val[v]){
            float d0 = ae0[v]-sHn[(i0+v)*L+c0], d1 = ae1[v]-sHn[(i0+v)*L+c0+1];
            encS += d0*d0 + d1*d1;
        }
        sE[(i0+v)*L+c0]=ae0[v]; sE[(i0+v)*L+c0+1]=ae1[v];
    }
    __syncwarp();
    float ag0[8],ag1[8];
    #pragma unroll
    for(int v=0;v<8;v++){ ag0[v]=sdb1[c0]; ag1[v]=sdb1[c0+1]; }
    for(int k=0;k<L;k++){
        float2 wd = __ldg((const float2*)&dW1[k*L+c0]);
        #pragma unroll
        for(int v=0;v<8;v++){
            float ek = sE[(i0+v)*L+k];
            ag0[v]=fmaf(ek,wd.x,ag0[v]); ag1[v]=fmaf(ek,wd.y,ag1[v]);
        }
    }
    float autoS = 0.f;
    #pragma unroll
    for(int v=0;v<8;v++){
        float pa = fmaxf(ag0[v],0.f)*sdW2[c0] + fmaxf(ag1[v],0.f)*sdW2[c0+1];
        for(int o=16;o;o>>=1) pa += __shfl_xor_sync(0xffffffffu, pa, o);
        float aout = pa + db2v;
        if(val[v] && lane==0){ float d = aout - Uv[v]; autoS += d*d; }
    }
    float tot = encS;
    for(int o=16;o;o>>=1) tot += __shfl_xor_sync(0xffffffffu, tot, o);
    float at = autoS;
    for(int o=16;o;o>>=1) at += __shfl_xor_sync(0xffffffffu, at, o);
    if(lane==0) red[w] = (double)lossW * ((double)tot/((double)NN*64.0) + (double)at/(double)NN);
    __syncthreads();
    if(tid==0){
        double s = 0.0;
        for(int i=0;i<8;i++) s += red[i];
        atomicAdd(&g_loss, s);
    }
}

// ---------------- residual loss (rowJ/rowA: 8B/edge) ----------------
__global__ __launch_bounds__(256) void k_res(const float* __restrict__ y, float wgt){
    __shared__ double red[8];
    int lane = threadIdx.x&31, w = threadIdx.x>>5;
    int wid = blockIdx.x*8 + w;
    int nwarps = gridDim.x*8;
    float ls = 0.f;
    for(int n = wid; n < NN; n += nwarps){
        int s = g_rowptr[n], e = g_rowptr[n+1];
        float part = 0.f;
        for(int p = s+lane; p < e; p += 32){
            part += g_rowA[p] * g_U[g_rowJ[p]];
        }
        for(int o=16;o;o>>=1) part += __shfl_xor_sync(0xffffffffu, part, o);
        if(lane==0){ float d = part - y[n]; ls += d*d; }
    }
    for(int o=16;o;o>>=1) ls += __shfl_xor_sync(0xffffffffu, ls, o);
    if(lane==0) red[w] = (double)ls;
    __syncthreads();
    if(threadIdx.x==0){
        double s=0.0; for(int i=0;i<8;i++) s+=red[i];
        atomicAdd(&g_loss, s * (double)wgt / (double)NN);
    }
}

// ---------------- finalize + reset state for next replay ----------------
__global__ void k_fin(float* __restrict__ out, int out_size){
    int i = blockIdx.x*blockDim.x + threadIdx.x;
    if(i < NN && i < out_size) out[i] = g_U[i];
    if(i == NN){
        if(i < out_size) out[NN] = (float)g_loss;
        g_loss = 0.0;
    }
    if(i < NN){ g_cntr[i]=0; g_cntc[i]=0; }
}

extern "C" void kernel_launch(void* const* d_in, const int* in_sizes, int n_in,
                              void* d_out, int out_size){
    const float* x    = (const float*)d_in[0];
    const float* y    = (const float*)d_in[2];
    const int*   tags = (const int*)  d_in[3];
    const int*   ei   = (const int*)  d_in[4];
    const float* ea   = (const float*)d_in[5];
    const float* aij  = (const float*)d_in[6];
    const float* prb  = (const float*)d_in[7];
    const float* ptW1 = (const float*)d_in[8];
    const float* ptb1 = (const float*)d_in[9];
    const float* ptW2 = (const float*)d_in[10];
    const float* ptb2 = (const float*)d_in[11];
    const float* pfW1 = (const float*)d_in[12];
    const float* pfb1 = (const float*)d_in[13];
    const float* pfW2 = (const float*)d_in[14];
    const float* pfb2 = (const float*)d_in[15];
    const float* zkW  = (const float*)d_in[16];
    const float* zkb  = (const float*)d_in[17];
    const float* rkW  = (const float*)d_in[18];
    const float* rkb  = (const float*)d_in[19];
    const float* cW   = (const float*)d_in[20];
    const float* cb   = (const float*)d_in[21];
    const float* eW1  = (const float*)d_in[22];
    const float* eb1  = (const float*)d_in[23];
    const float* eW2  = (const float*)d_in[24];
    const float* eb2  = (const float*)d_in[25];
    const float* dW1  = (const float*)d_in[26];
    const float* db1  = (const float*)d_in[27];
    const float* dW2  = (const float*)d_in[28];
    const float* db2  = (const float*)d_in[29];

    cudaFuncSetAttribute(k_prep,   cudaFuncAttributeMaxDynamicSharedMemorySize, PREP_SMEM);
    cudaFuncSetAttribute(k_gate,   cudaFuncAttributeMaxDynamicSharedMemorySize, GATE_SMEM);
    cudaFuncSetAttribute(k_decode, cudaFuncAttributeMaxDynamicSharedMemorySize, DEC_SMEM);

    int *rowptr, *colptr;
    float4 *rowE4, *colE4;
    float *Pt, *Pf, *mt, *mf;
    __half2 *Qt16, *Qf16;
    cudaGetSymbolAddress((void**)&rowptr, g_rowptr);
    cudaGetSymbolAddress((void**)&colptr, g_colptr);
    cudaGetSymbolAddress((void**)&rowE4,  g_rowE4);
    cudaGetSymbolAddress((void**)&colE4,  g_colE4);
    cudaGetSymbolAddress((void**)&Pt, g_Pt);
    cudaGetSymbolAddress((void**)&Pf, g_Pf);
    cudaGetSymbolAddress((void**)&Qt16, g_Qt16);
    cudaGetSymbolAddress((void**)&Qf16, g_Qf16);
    cudaGetSymbolAddress((void**)&mt, g_mt);
    cudaGetSymbolAddress((void**)&mf, g_mf);

    // side stream + events (lazy-init on first/eager call; reused during capture)
    static cudaStream_t s1 = 0;
    static cudaEvent_t evA=0, evB=0, evP=0;
    if(!s1){
        cudaStreamCreateWithFlags(&s1, cudaStreamNonBlocking);
        cudaEventCreateWithFlags(&evA, cudaEventDisableTiming);
        cudaEventCreateWithFlags(&evB, cudaEventDisableTiming);
        cudaEventCreateWithFlags(&evP, cudaEventDisableTiming);
    }

    // fork: s1 = fma-bound setup (enc0 -> prep_full -> decode_dr)
    cudaEventRecord(evA, 0);
    cudaStreamWaitEvent(s1, evA, 0);
    k_enc0<<<NB32, 256, 0, s1>>>(x, eW1, eb1, eW2, eb2);
    k_prep<<<NB64, 256, PREP_SMEM, s1>>>(ptW1, ptb1, pfW1, pfb1, 0);

    // s0 = memory-bound setup (hist -> scans -> scatter)
    k_hist<<<(NE+255)/256, 256>>>(ei);
    k_scanA<<<SBLK, 256>>>(tags);
    k_scanB<<<1, 256>>>();
    k_scanC<<<SBLK, 256>>>(tags);
    cudaEventRecord(evB, 0);                 // nd/dr lists + CSR ptrs ready
    k_scatter<<<(NE+255)/256, 256>>>(ei, ea, aij);

    // s1: Dirichlet decode (needs enc0 H + dr list); overlaps scatter
    cudaStreamWaitEvent(s1, evB, 0);
    k_decode<<<NB64, 256, DEC_SMEM, s1>>>(0, 2.0f, dW1, db1, dW2, db2, eW1, eb1, eW2, eb2);
    cudaEventRecord(evP, s1);

    // join before loop
    cudaStreamWaitEvent(0, evP, 0);

    const float gammaw[2] = {0.9f, 1.0f};
    for(int step=0; step<2; step++){
        k_aggr<<<2*NB32, 256>>>(colptr, colE4, rowptr, rowE4,
                                Pt, Qt16, Pf, Qf16,
                                ptW1, ptb2, ptW2, pfW1, pfb2, pfW2, mt, mf);
        k_gate<<<NBG, 256, GATE_SMEM>>>(prb, zkW, zkb, rkW, rkb, cW, cb);
        k_decode<<<NB64, 256, DEC_SMEM>>>(1, 1.0f, dW1, db1, dW2, db2, eW1, eb1, eW2, eb2);
        k_res<<<NB32, 256>>>(y, gammaw[step]);
        if(step == 0)
            k_prep<<<NB64, 256, PREP_SMEM>>>(ptW1, ptb1, pfW1, pfb1, 1);
    }
    k_fin<<<(NN+256)/256, 256>>>((float*)d_out, out_size);
}